// round 5
// baseline (speedup 1.0000x reference)
#include <cuda_runtime.h>
#include <math.h>

#define D_MODEL   1024
#define NUM_HEADS 16
#define DKH       64
#define BATCH     2
#define SEQ       2048
#define MROWS     (BATCH * SEQ)   // 4096

// ---------------- scratch (device globals; no allocation allowed) ----------
__device__ float g_Q[MROWS * D_MODEL];
__device__ float g_K[MROWS * D_MODEL];
__device__ float g_V[MROWS * D_MODEL];
__device__ float g_O[MROWS * D_MODEL];

// ============================================================================
// GEMM: C[M,N] = A[M,K] @ W[N,K]^T + bias[N]   (both operands K-major)
// 128x128 block tile, BK=8, 256 threads, 8x8 per thread.
// ============================================================================
#define GBM 128
#define GBN 128
#define GBK 8

__global__ __launch_bounds__(256) void gemm_nt_bias(
    const float* __restrict__ A, const float* __restrict__ W,
    const float* __restrict__ bias, float* __restrict__ C,
    int M, int N, int K)
{
    __shared__ float As[GBK][GBM];
    __shared__ float Ws[GBK][GBN];

    const int tid = threadIdx.x;
    const int ty  = tid >> 4;          // 0..15
    const int tx  = tid & 15;          // 0..15
    const int rowBase = blockIdx.y * GBM;
    const int colBase = blockIdx.x * GBN;

    const int lr = tid >> 1;           // 0..127 (load row within tile)
    const int lk = (tid & 1) * 4;      // 0 or 4

    const float* Ap = A + (size_t)(rowBase + lr) * K + lk;
    const float* Wp = W + (size_t)(colBase + lr) * K + lk;

    float acc[8][8];
#pragma unroll
    for (int i = 0; i < 8; i++)
#pragma unroll
        for (int j = 0; j < 8; j++) acc[i][j] = 0.0f;

    for (int kt = 0; kt < K; kt += GBK) {
        float4 av = *reinterpret_cast<const float4*>(Ap + kt);
        float4 wv = *reinterpret_cast<const float4*>(Wp + kt);
        As[lk + 0][lr] = av.x; As[lk + 1][lr] = av.y;
        As[lk + 2][lr] = av.z; As[lk + 3][lr] = av.w;
        Ws[lk + 0][lr] = wv.x; Ws[lk + 1][lr] = wv.y;
        Ws[lk + 2][lr] = wv.z; Ws[lk + 3][lr] = wv.w;
        __syncthreads();

#pragma unroll
        for (int kk = 0; kk < GBK; kk++) {
            float4 a0 = *reinterpret_cast<const float4*>(&As[kk][ty * 8]);
            float4 a1 = *reinterpret_cast<const float4*>(&As[kk][ty * 8 + 4]);
            float4 b0 = *reinterpret_cast<const float4*>(&Ws[kk][tx * 8]);
            float4 b1 = *reinterpret_cast<const float4*>(&Ws[kk][tx * 8 + 4]);
            float a[8] = {a0.x, a0.y, a0.z, a0.w, a1.x, a1.y, a1.z, a1.w};
            float b[8] = {b0.x, b0.y, b0.z, b0.w, b1.x, b1.y, b1.z, b1.w};
#pragma unroll
            for (int i = 0; i < 8; i++)
#pragma unroll
                for (int j = 0; j < 8; j++)
                    acc[i][j] = fmaf(a[i], b[j], acc[i][j]);
        }
        __syncthreads();
    }

    const int row = rowBase + ty * 8;
    const int col = colBase + tx * 8;
    float bb[8];
#pragma unroll
    for (int j = 0; j < 8; j++) bb[j] = bias[col + j];

#pragma unroll
    for (int i = 0; i < 8; i++) {
        float* crow = C + (size_t)(row + i) * N + col;
        float4 r0, r1;
        r0.x = acc[i][0] + bb[0]; r0.y = acc[i][1] + bb[1];
        r0.z = acc[i][2] + bb[2]; r0.w = acc[i][3] + bb[3];
        r1.x = acc[i][4] + bb[4]; r1.y = acc[i][5] + bb[5];
        r1.z = acc[i][6] + bb[6]; r1.w = acc[i][7] + bb[7];
        *reinterpret_cast<float4*>(crow)     = r0;
        *reinterpret_cast<float4*>(crow + 4) = r1;
    }
}

// ============================================================================
// RoPE (interleaved pairs), in-place on Q and K.
// out[2i]   = x[2i]*cos - x[2i+1]*sin
// out[2i+1] = x[2i+1]*cos + x[2i]*sin,   angle_i = pos / 10000^(2i/64)
// ============================================================================
__global__ void rope_kernel(float* __restrict__ Q, float* __restrict__ K)
{
    int idx = blockIdx.x * blockDim.x + threadIdx.x;   // [0, B*S*H*32)
    int p  = idx & 31;             // pair index within head
    int h  = (idx >> 5) & 15;      // head
    int bs = idx >> 9;             // b*SEQ + s, 0..4095
    int s  = bs & (SEQ - 1);

    size_t base = (size_t)bs * D_MODEL + h * DKH + 2 * p;
    float angle = (float)s * powf(10000.0f, -(float)p * (1.0f / 32.0f));
    float sn, cs;
    sincosf(angle, &sn, &cs);

    float q0 = Q[base], q1 = Q[base + 1];
    Q[base]     = q0 * cs - q1 * sn;
    Q[base + 1] = q1 * cs + q0 * sn;
    float k0 = K[base], k1 = K[base + 1];
    K[base]     = k0 * cs - k1 * sn;
    K[base + 1] = k1 * cs + k0 * sn;
}

// ============================================================================
// Flash attention (fp32, online softmax).
// Block = (q-tile of 128, one (b,h)). 256 threads: ty=tid/8 -> 4 rows,
// tx=tid%8 -> 8 cols (stage1 keys / stage2 dims).
// Smem: Qs[128][65], Ks[64][65], Vs[64][68], Ps[128][65]  (~98 KB)
// ============================================================================
#define QS_STRIDE 65
#define KS_STRIDE 65
#define VS_STRIDE 68
#define PS_STRIDE 65
#define ATT_SMEM_BYTES ((128 * QS_STRIDE + 64 * KS_STRIDE + 64 * VS_STRIDE + 128 * PS_STRIDE) * 4)

__global__ __launch_bounds__(256, 2) void attention_kernel(
    const float* __restrict__ Q, const float* __restrict__ K,
    const float* __restrict__ V, float* __restrict__ O)
{
    extern __shared__ float sm[];
    float* Qs = sm;                           // [128][65]
    float* Ks = Qs + 128 * QS_STRIDE;         // [64][65]
    float* Vs = Ks + 64 * KS_STRIDE;          // [64][68]
    float* Ps = Vs + 64 * VS_STRIDE;          // [128][65]

    const int bh = blockIdx.y;
    const int b  = bh >> 4;
    const int h  = bh & 15;
    const int q0 = blockIdx.x * 128;
    const int tid = threadIdx.x;
    const int ty = tid >> 3;   // 0..31 -> rows ty*4..ty*4+3
    const int tx = tid & 7;    // 0..7

    const size_t headoff = (size_t)h * DKH;
    const float* Qb = Q + ((size_t)b * SEQ) * D_MODEL + headoff;
    const float* Kb = K + ((size_t)b * SEQ) * D_MODEL + headoff;
    const float* Vb = V + ((size_t)b * SEQ) * D_MODEL + headoff;

    // Load Q tile, folding in the 1/sqrt(dk)=0.125 score scale.
    for (int idx = tid; idx < 128 * 64; idx += 256) {
        int r = idx >> 6, d = idx & 63;
        Qs[r * QS_STRIDE + d] = Qb[(size_t)(q0 + r) * D_MODEL + d] * 0.125f;
    }

    float m[4], l[4], o[4][8];
#pragma unroll
    for (int i = 0; i < 4; i++) {
        m[i] = -INFINITY; l[i] = 0.0f;
#pragma unroll
        for (int j = 0; j < 8; j++) o[i][j] = 0.0f;
    }

    for (int kv0 = 0; kv0 < SEQ; kv0 += 64) {
        for (int idx = tid; idx < 64 * 64; idx += 256) {
            int r = idx >> 6, d = idx & 63;
            float kval = Kb[(size_t)(kv0 + r) * D_MODEL + d];
            float vval = Vb[(size_t)(kv0 + r) * D_MODEL + d];
            Ks[r * KS_STRIDE + d] = kval;
            Vs[r * VS_STRIDE + d] = vval;
        }
        __syncthreads();   // also covers the Q-tile load on iteration 0

        // ---- S = Qs @ Ks^T  (4x8 per thread) ----
        float s[4][8];
#pragma unroll
        for (int i = 0; i < 4; i++)
#pragma unroll
            for (int j = 0; j < 8; j++) s[i][j] = 0.0f;

#pragma unroll 8
        for (int d = 0; d < 64; d++) {
            float qv[4], kv[8];
#pragma unroll
            for (int i = 0; i < 4; i++) qv[i] = Qs[(ty * 4 + i) * QS_STRIDE + d];
#pragma unroll
            for (int j = 0; j < 8; j++) kv[j] = Ks[(tx * 8 + j) * KS_STRIDE + d];
#pragma unroll
            for (int i = 0; i < 4; i++)
#pragma unroll
                for (int j = 0; j < 8; j++)
                    s[i][j] = fmaf(qv[i], kv[j], s[i][j]);
        }

        // ---- online softmax (row reductions across the 8-lane tx group) ----
#pragma unroll
        for (int i = 0; i < 4; i++) {
            float mloc = s[i][0];
#pragma unroll
            for (int j = 1; j < 8; j++) mloc = fmaxf(mloc, s[i][j]);
#pragma unroll
            for (int off = 1; off < 8; off <<= 1)
                mloc = fmaxf(mloc, __shfl_xor_sync(0xffffffffu, mloc, off));
            float mnew  = fmaxf(m[i], mloc);
            float alpha = __expf(m[i] - mnew);
            float lloc  = 0.0f;
#pragma unroll
            for (int j = 0; j < 8; j++) {
                s[i][j] = __expf(s[i][j] - mnew);
                lloc += s[i][j];
            }
#pragma unroll
            for (int off = 1; off < 8; off <<= 1)
                lloc += __shfl_xor_sync(0xffffffffu, lloc, off);
            l[i] = l[i] * alpha + lloc;
            m[i] = mnew;
#pragma unroll
            for (int j = 0; j < 8; j++) o[i][j] *= alpha;
#pragma unroll
            for (int j = 0; j < 8; j++)
                Ps[(ty * 4 + i) * PS_STRIDE + tx * 8 + j] = s[i][j];
        }
        __syncthreads();

        // ---- O += P @ V  (thread owns rows ty*4..+3, dims tx*8..+7) ----
#pragma unroll 4
        for (int c = 0; c < 64; c++) {
            float pv[4];
#pragma unroll
            for (int i = 0; i < 4; i++) pv[i] = Ps[(ty * 4 + i) * PS_STRIDE + c];
            float4 v0 = *reinterpret_cast<const float4*>(&Vs[c * VS_STRIDE + tx * 8]);
            float4 v1 = *reinterpret_cast<const float4*>(&Vs[c * VS_STRIDE + tx * 8 + 4]);
            float vv[8] = {v0.x, v0.y, v0.z, v0.w, v1.x, v1.y, v1.z, v1.w};
#pragma unroll
            for (int i = 0; i < 4; i++)
#pragma unroll
                for (int j = 0; j < 8; j++)
                    o[i][j] = fmaf(pv[i], vv[j], o[i][j]);
        }
        __syncthreads();
    }

    float* Ob = O + ((size_t)b * SEQ) * D_MODEL + headoff;
#pragma unroll
    for (int i = 0; i < 4; i++) {
        float inv = 1.0f / l[i];
#pragma unroll
        for (int j = 0; j < 8; j++)
            Ob[(size_t)(q0 + ty * 4 + i) * D_MODEL + tx * 8 + j] = o[i][j] * inv;
    }
}

// ============================================================================
// Launch
// ============================================================================
extern "C" void kernel_launch(void* const* d_in, const int* in_sizes, int n_in,
                              void* d_out, int out_size)
{
    (void)in_sizes; (void)n_in; (void)out_size;
    const float* x  = (const float*)d_in[0];
    const float* wq = (const float*)d_in[1];
    const float* bq = (const float*)d_in[2];
    const float* wk = (const float*)d_in[3];
    const float* bk = (const float*)d_in[4];
    const float* wv = (const float*)d_in[5];
    const float* bv = (const float*)d_in[6];
    const float* wo = (const float*)d_in[7];
    const float* bo = (const float*)d_in[8];
    float* out = (float*)d_out;

    float *Qp, *Kp, *Vp, *Op;
    cudaGetSymbolAddress((void**)&Qp, g_Q);
    cudaGetSymbolAddress((void**)&Kp, g_K);
    cudaGetSymbolAddress((void**)&Vp, g_V);
    cudaGetSymbolAddress((void**)&Op, g_O);

    cudaFuncSetAttribute(attention_kernel,
                         cudaFuncAttributeMaxDynamicSharedMemorySize,
                         ATT_SMEM_BYTES);

    dim3 ggrid(D_MODEL / GBN, MROWS / GBM);   // (8, 32)

    gemm_nt_bias<<<ggrid, 256>>>(x, wq, bq, Qp, MROWS, D_MODEL, D_MODEL);
    gemm_nt_bias<<<ggrid, 256>>>(x, wk, bk, Kp, MROWS, D_MODEL, D_MODEL);
    gemm_nt_bias<<<ggrid, 256>>>(x, wv, bv, Vp, MROWS, D_MODEL, D_MODEL);

    int rope_threads = BATCH * SEQ * NUM_HEADS * (DKH / 2);   // 2,097,152
    rope_kernel<<<rope_threads / 256, 256>>>(Qp, Kp);

    dim3 agrid(SEQ / 128, BATCH * NUM_HEADS);                 // (16, 32)
    attention_kernel<<<agrid, 256, ATT_SMEM_BYTES>>>(Qp, Kp, Vp, Op);

    gemm_nt_bias<<<ggrid, 256>>>(Op, wo, bo, out, MROWS, D_MODEL, D_MODEL);
}

// round 6
// speedup vs baseline: 1.2648x; 1.2648x over previous
#include <cuda_runtime.h>
#include <cuda_bf16.h>
#include <math.h>
#include <stdint.h>

#define D_MODEL   1024
#define NUM_HEADS 16
#define DKH       64
#define BATCH     2
#define SEQ       2048
#define MROWS     (BATCH * SEQ)   // 4096

// ---------------- scratch (device globals; no allocation allowed) ----------
__device__ float g_Q[MROWS * D_MODEL];
__device__ float g_K[MROWS * D_MODEL];
__device__ float g_V[MROWS * D_MODEL];
__device__ float g_O[MROWS * D_MODEL];

__device__ __nv_bfloat16 g_Xh[MROWS * D_MODEL];
__device__ __nv_bfloat16 g_Xl[MROWS * D_MODEL];
__device__ __nv_bfloat16 g_Oh[MROWS * D_MODEL];
__device__ __nv_bfloat16 g_Ol[MROWS * D_MODEL];
__device__ __nv_bfloat16 g_Wh[4 * D_MODEL * D_MODEL];
__device__ __nv_bfloat16 g_Wl[4 * D_MODEL * D_MODEL];

// ============================================================================
// Split fp32 -> bf16 hi + bf16 lo (error-compensated). Processes 4 floats/thr.
// ============================================================================
__global__ void convert_split4(const float4* __restrict__ src,
                               uint2* __restrict__ hi, uint2* __restrict__ lo,
                               int n4)
{
    int i = blockIdx.x * blockDim.x + threadIdx.x;
    if (i >= n4) return;
    float4 v = src[i];
    __nv_bfloat162 h01 = __float22bfloat162_rn(make_float2(v.x, v.y));
    __nv_bfloat162 h23 = __float22bfloat162_rn(make_float2(v.z, v.w));
    float2 f01 = __bfloat1622float2(h01);
    float2 f23 = __bfloat1622float2(h23);
    __nv_bfloat162 l01 = __float22bfloat162_rn(make_float2(v.x - f01.x, v.y - f01.y));
    __nv_bfloat162 l23 = __float22bfloat162_rn(make_float2(v.z - f23.x, v.w - f23.y));
    uint2 ho, loo;
    ho.x  = *reinterpret_cast<uint32_t*>(&h01);
    ho.y  = *reinterpret_cast<uint32_t*>(&h23);
    loo.x = *reinterpret_cast<uint32_t*>(&l01);
    loo.y = *reinterpret_cast<uint32_t*>(&l23);
    hi[i] = ho;
    lo[i] = loo;
}

// ============================================================================
// Tensor-core GEMM: C[M,N] = A[M,K] @ W[N,K]^T + bias[N]
// A,W given as bf16 (hi,lo) splits; C = Ah@Wh + Ah@Wl + Al@Wh  (fp32 accum).
// 128x128 block tile, BK=32, 256 threads = 8 warps, warp tile 64x32,
// mma.sync.aligned.m16n8k16.row.col.f32.bf16.bf16.f32.
// ============================================================================
#define MMA_BF16(c, a, b)                                                     \
    asm("mma.sync.aligned.m16n8k16.row.col.f32.bf16.bf16.f32 "                \
        "{%0,%1,%2,%3}, {%4,%5,%6,%7}, {%8,%9}, {%0,%1,%2,%3};"               \
        : "+f"((c)[0]), "+f"((c)[1]), "+f"((c)[2]), "+f"((c)[3])              \
        : "r"((a)[0]), "r"((a)[1]), "r"((a)[2]), "r"((a)[3]),                 \
          "r"((b)[0]), "r"((b)[1]))

// smem row stride: 32 bf16 data + 8 pad = 40 bf16 = 20 words = 5 uint4.
#define SROW_W 20

__global__ __launch_bounds__(256, 1) void gemm_bf16_split(
    const __nv_bfloat16* __restrict__ Ah, const __nv_bfloat16* __restrict__ Al,
    const __nv_bfloat16* __restrict__ Wh, const __nv_bfloat16* __restrict__ Wl,
    const float* __restrict__ bias, float* __restrict__ C,
    int M, int N, int K)
{
    __shared__ __align__(16) uint32_t sAh[128 * SROW_W];
    __shared__ __align__(16) uint32_t sAl[128 * SROW_W];
    __shared__ __align__(16) uint32_t sWh[128 * SROW_W];
    __shared__ __align__(16) uint32_t sWl[128 * SROW_W];

    const int tid  = threadIdx.x;
    const int lane = tid & 31;
    const int wrp  = tid >> 5;
    const int g    = lane >> 2;      // 0..7
    const int t    = lane & 3;       // 0..3
    const int wm   = (wrp & 1) * 64; // warp M offset in tile
    const int wn   = (wrp >> 1) * 32;// warp N offset in tile
    const int rowBase = blockIdx.y * 128;
    const int colBase = blockIdx.x * 128;

    float c[4][4][4];
#pragma unroll
    for (int i = 0; i < 4; i++)
#pragma unroll
        for (int j = 0; j < 4; j++)
#pragma unroll
            for (int e = 0; e < 4; e++) c[i][j][e] = 0.0f;

    for (int kt = 0; kt < K; kt += 32) {
        // ---- stage 4 tiles (128 rows x 32 bf16) into smem ----
#pragma unroll
        for (int p = 0; p < 2; p++) {
            int id = tid + p * 256;       // 0..511
            int r  = id >> 2;             // 0..127
            int q  = id & 3;              // uint4 chunk within row
            const uint4* ga  = (const uint4*)(Ah + (size_t)(rowBase + r) * K + kt) + q;
            const uint4* gal = (const uint4*)(Al + (size_t)(rowBase + r) * K + kt) + q;
            const uint4* gw  = (const uint4*)(Wh + (size_t)(colBase + r) * K + kt) + q;
            const uint4* gwl = (const uint4*)(Wl + (size_t)(colBase + r) * K + kt) + q;
            ((uint4*)sAh)[r * 5 + q] = *ga;
            ((uint4*)sAl)[r * 5 + q] = *gal;
            ((uint4*)sWh)[r * 5 + q] = *gw;
            ((uint4*)sWl)[r * 5 + q] = *gwl;
        }
        __syncthreads();

#pragma unroll
        for (int kk = 0; kk < 2; kk++) {           // two k16 chunks
            uint32_t ah[4][4], al[4][4], bh[4][2], bl[4][2];
#pragma unroll
            for (int i = 0; i < 4; i++) {
                int r0 = wm + i * 16 + g;
                int b0 = r0 * SROW_W + kk * 8 + t;
                int b8 = (r0 + 8) * SROW_W + kk * 8 + t;
                ah[i][0] = sAh[b0];     ah[i][1] = sAh[b8];
                ah[i][2] = sAh[b0 + 4]; ah[i][3] = sAh[b8 + 4];
                al[i][0] = sAl[b0];     al[i][1] = sAl[b8];
                al[i][2] = sAl[b0 + 4]; al[i][3] = sAl[b8 + 4];
            }
#pragma unroll
            for (int j = 0; j < 4; j++) {
                int rn = wn + j * 8 + g;
                int b0 = rn * SROW_W + kk * 8 + t;
                bh[j][0] = sWh[b0]; bh[j][1] = sWh[b0 + 4];
                bl[j][0] = sWl[b0]; bl[j][1] = sWl[b0 + 4];
            }
#pragma unroll
            for (int i = 0; i < 4; i++)
#pragma unroll
                for (int j = 0; j < 4; j++) {
                    MMA_BF16(c[i][j], ah[i], bh[j]);
                    MMA_BF16(c[i][j], ah[i], bl[j]);
                    MMA_BF16(c[i][j], al[i], bh[j]);
                }
        }
        __syncthreads();
    }

    // ---- epilogue: C = acc + bias ----
#pragma unroll
    for (int i = 0; i < 4; i++) {
        int row = rowBase + wm + i * 16 + g;
#pragma unroll
        for (int j = 0; j < 4; j++) {
            int col = colBase + wn + j * 8 + 2 * t;
            float b0 = bias[col], b1 = bias[col + 1];
            float2 v0 = make_float2(c[i][j][0] + b0, c[i][j][1] + b1);
            float2 v1 = make_float2(c[i][j][2] + b0, c[i][j][3] + b1);
            *reinterpret_cast<float2*>(&C[(size_t)row * N + col])       = v0;
            *reinterpret_cast<float2*>(&C[(size_t)(row + 8) * N + col]) = v1;
        }
    }
}

// ============================================================================
// RoPE (interleaved pairs), in-place on Q and K.
// ============================================================================
__global__ void rope_kernel(float* __restrict__ Q, float* __restrict__ K)
{
    int idx = blockIdx.x * blockDim.x + threadIdx.x;   // [0, B*S*H*32)
    int p  = idx & 31;             // pair index within head
    int h  = (idx >> 5) & 15;      // head
    int bs = idx >> 9;             // b*SEQ + s
    int s  = bs & (SEQ - 1);

    size_t base = (size_t)bs * D_MODEL + h * DKH + 2 * p;
    float angle = (float)s * powf(10000.0f, -(float)p * (1.0f / 32.0f));
    float sn, cs;
    sincosf(angle, &sn, &cs);

    float q0 = Q[base], q1 = Q[base + 1];
    Q[base]     = q0 * cs - q1 * sn;
    Q[base + 1] = q1 * cs + q0 * sn;
    float k0 = K[base], k1 = K[base + 1];
    K[base]     = k0 * cs - k1 * sn;
    K[base + 1] = k1 * cs + k0 * sn;
}

// ============================================================================
// Flash attention (fp32, online softmax) — unchanged from passing baseline.
// ============================================================================
#define QS_STRIDE 65
#define KS_STRIDE 65
#define VS_STRIDE 68
#define PS_STRIDE 65
#define ATT_SMEM_BYTES ((128 * QS_STRIDE + 64 * KS_STRIDE + 64 * VS_STRIDE + 128 * PS_STRIDE) * 4)

__global__ __launch_bounds__(256, 2) void attention_kernel(
    const float* __restrict__ Q, const float* __restrict__ K,
    const float* __restrict__ V, float* __restrict__ O)
{
    extern __shared__ float sm[];
    float* Qs = sm;
    float* Ks = Qs + 128 * QS_STRIDE;
    float* Vs = Ks + 64 * KS_STRIDE;
    float* Ps = Vs + 64 * VS_STRIDE;

    const int bh = blockIdx.y;
    const int b  = bh >> 4;
    const int h  = bh & 15;
    const int q0 = blockIdx.x * 128;
    const int tid = threadIdx.x;
    const int ty = tid >> 3;
    const int tx = tid & 7;

    const size_t headoff = (size_t)h * DKH;
    const float* Qb = Q + ((size_t)b * SEQ) * D_MODEL + headoff;
    const float* Kb = K + ((size_t)b * SEQ) * D_MODEL + headoff;
    const float* Vb = V + ((size_t)b * SEQ) * D_MODEL + headoff;

    for (int idx = tid; idx < 128 * 64; idx += 256) {
        int r = idx >> 6, d = idx & 63;
        Qs[r * QS_STRIDE + d] = Qb[(size_t)(q0 + r) * D_MODEL + d] * 0.125f;
    }

    float m[4], l[4], o[4][8];
#pragma unroll
    for (int i = 0; i < 4; i++) {
        m[i] = -INFINITY; l[i] = 0.0f;
#pragma unroll
        for (int j = 0; j < 8; j++) o[i][j] = 0.0f;
    }

    for (int kv0 = 0; kv0 < SEQ; kv0 += 64) {
        for (int idx = tid; idx < 64 * 64; idx += 256) {
            int r = idx >> 6, d = idx & 63;
            Ks[r * KS_STRIDE + d] = Kb[(size_t)(kv0 + r) * D_MODEL + d];
            Vs[r * VS_STRIDE + d] = Vb[(size_t)(kv0 + r) * D_MODEL + d];
        }
        __syncthreads();

        float s[4][8];
#pragma unroll
        for (int i = 0; i < 4; i++)
#pragma unroll
            for (int j = 0; j < 8; j++) s[i][j] = 0.0f;

#pragma unroll 8
        for (int d = 0; d < 64; d++) {
            float qv[4], kv[8];
#pragma unroll
            for (int i = 0; i < 4; i++) qv[i] = Qs[(ty * 4 + i) * QS_STRIDE + d];
#pragma unroll
            for (int j = 0; j < 8; j++) kv[j] = Ks[(tx * 8 + j) * KS_STRIDE + d];
#pragma unroll
            for (int i = 0; i < 4; i++)
#pragma unroll
                for (int j = 0; j < 8; j++)
                    s[i][j] = fmaf(qv[i], kv[j], s[i][j]);
        }

#pragma unroll
        for (int i = 0; i < 4; i++) {
            float mloc = s[i][0];
#pragma unroll
            for (int j = 1; j < 8; j++) mloc = fmaxf(mloc, s[i][j]);
#pragma unroll
            for (int off = 1; off < 8; off <<= 1)
                mloc = fmaxf(mloc, __shfl_xor_sync(0xffffffffu, mloc, off));
            float mnew  = fmaxf(m[i], mloc);
            float alpha = __expf(m[i] - mnew);
            float lloc  = 0.0f;
#pragma unroll
            for (int j = 0; j < 8; j++) {
                s[i][j] = __expf(s[i][j] - mnew);
                lloc += s[i][j];
            }
#pragma unroll
            for (int off = 1; off < 8; off <<= 1)
                lloc += __shfl_xor_sync(0xffffffffu, lloc, off);
            l[i] = l[i] * alpha + lloc;
            m[i] = mnew;
#pragma unroll
            for (int j = 0; j < 8; j++) o[i][j] *= alpha;
#pragma unroll
            for (int j = 0; j < 8; j++)
                Ps[(ty * 4 + i) * PS_STRIDE + tx * 8 + j] = s[i][j];
        }
        __syncthreads();

#pragma unroll 4
        for (int cc = 0; cc < 64; cc++) {
            float pv[4];
#pragma unroll
            for (int i = 0; i < 4; i++) pv[i] = Ps[(ty * 4 + i) * PS_STRIDE + cc];
            float4 v0 = *reinterpret_cast<const float4*>(&Vs[cc * VS_STRIDE + tx * 8]);
            float4 v1 = *reinterpret_cast<const float4*>(&Vs[cc * VS_STRIDE + tx * 8 + 4]);
            float vv[8] = {v0.x, v0.y, v0.z, v0.w, v1.x, v1.y, v1.z, v1.w};
#pragma unroll
            for (int i = 0; i < 4; i++)
#pragma unroll
                for (int j = 0; j < 8; j++)
                    o[i][j] = fmaf(pv[i], vv[j], o[i][j]);
        }
        __syncthreads();
    }

    float* Ob = O + ((size_t)b * SEQ) * D_MODEL + headoff;
#pragma unroll
    for (int i = 0; i < 4; i++) {
        float inv = 1.0f / l[i];
#pragma unroll
        for (int j = 0; j < 8; j++)
            Ob[(size_t)(q0 + ty * 4 + i) * D_MODEL + tx * 8 + j] = o[i][j] * inv;
    }
}

// ============================================================================
// Launch
// ============================================================================
extern "C" void kernel_launch(void* const* d_in, const int* in_sizes, int n_in,
                              void* d_out, int out_size)
{
    (void)in_sizes; (void)n_in; (void)out_size;
    const float* x  = (const float*)d_in[0];
    const float* wq = (const float*)d_in[1];
    const float* bq = (const float*)d_in[2];
    const float* wk = (const float*)d_in[3];
    const float* bk = (const float*)d_in[4];
    const float* wv = (const float*)d_in[5];
    const float* bv = (const float*)d_in[6];
    const float* wo = (const float*)d_in[7];
    const float* bo = (const float*)d_in[8];
    float* out = (float*)d_out;

    float *Qp, *Kp, *Vp, *Op;
    __nv_bfloat16 *Xh, *Xl, *Oh, *Ol, *Wh, *Wl;
    cudaGetSymbolAddress((void**)&Qp, g_Q);
    cudaGetSymbolAddress((void**)&Kp, g_K);
    cudaGetSymbolAddress((void**)&Vp, g_V);
    cudaGetSymbolAddress((void**)&Op, g_O);
    cudaGetSymbolAddress((void**)&Xh, g_Xh);
    cudaGetSymbolAddress((void**)&Xl, g_Xl);
    cudaGetSymbolAddress((void**)&Oh, g_Oh);
    cudaGetSymbolAddress((void**)&Ol, g_Ol);
    cudaGetSymbolAddress((void**)&Wh, g_Wh);
    cudaGetSymbolAddress((void**)&Wl, g_Wl);

    cudaFuncSetAttribute(attention_kernel,
                         cudaFuncAttributeMaxDynamicSharedMemorySize,
                         ATT_SMEM_BYTES);

    const int WSZ = D_MODEL * D_MODEL;   // 1M elems per weight

    // --- split conversions (x and the 4 weights) ---
    int n4x = (MROWS * D_MODEL) / 4;     // 1M float4
    int n4w = WSZ / 4;                   // 256K float4
    convert_split4<<<(n4x + 255) / 256, 256>>>((const float4*)x,  (uint2*)Xh,          (uint2*)Xl,          n4x);
    convert_split4<<<(n4w + 255) / 256, 256>>>((const float4*)wq, (uint2*)(Wh + 0*WSZ), (uint2*)(Wl + 0*WSZ), n4w);
    convert_split4<<<(n4w + 255) / 256, 256>>>((const float4*)wk, (uint2*)(Wh + 1*WSZ), (uint2*)(Wl + 1*WSZ), n4w);
    convert_split4<<<(n4w + 255) / 256, 256>>>((const float4*)wv, (uint2*)(Wh + 2*WSZ), (uint2*)(Wl + 2*WSZ), n4w);
    convert_split4<<<(n4w + 255) / 256, 256>>>((const float4*)wo, (uint2*)(Wh + 3*WSZ), (uint2*)(Wl + 3*WSZ), n4w);

    // --- QKV projections on tensor cores ---
    dim3 ggrid(D_MODEL / 128, MROWS / 128);   // (8, 32)
    gemm_bf16_split<<<ggrid, 256>>>(Xh, Xl, Wh + 0*WSZ, Wl + 0*WSZ, bq, Qp, MROWS, D_MODEL, D_MODEL);
    gemm_bf16_split<<<ggrid, 256>>>(Xh, Xl, Wh + 1*WSZ, Wl + 1*WSZ, bk, Kp, MROWS, D_MODEL, D_MODEL);
    gemm_bf16_split<<<ggrid, 256>>>(Xh, Xl, Wh + 2*WSZ, Wl + 2*WSZ, bv, Vp, MROWS, D_MODEL, D_MODEL);

    // --- RoPE ---
    int rope_threads = BATCH * SEQ * NUM_HEADS * (DKH / 2);
    rope_kernel<<<rope_threads / 256, 256>>>(Qp, Kp);

    // --- attention ---
    dim3 agrid(SEQ / 128, BATCH * NUM_HEADS);
    attention_kernel<<<agrid, 256, ATT_SMEM_BYTES>>>(Qp, Kp, Vp, Op);

    // --- output projection ---
    convert_split4<<<(n4x + 255) / 256, 256>>>((const float4*)Op, (uint2*)Oh, (uint2*)Ol, n4x);
    gemm_bf16_split<<<ggrid, 256>>>(Oh, Ol, Wh + 3*WSZ, Wl + 3*WSZ, bo, out, MROWS, D_MODEL, D_MODEL);
}

// round 7
// speedup vs baseline: 2.5956x; 2.0522x over previous
#include <cuda_runtime.h>
#include <cuda_bf16.h>
#include <math.h>
#include <stdint.h>

#define D_MODEL   1024
#define NUM_HEADS 16
#define DKH       64
#define BATCH     2
#define SEQ       2048
#define MROWS     (BATCH * SEQ)   // 4096

// ---------------- scratch (device globals; no allocation allowed) ----------
__device__ float g_Q[MROWS * D_MODEL];
__device__ float g_K[MROWS * D_MODEL];
__device__ float g_V[MROWS * D_MODEL];

__device__ __nv_bfloat16 g_Xh[MROWS * D_MODEL];
__device__ __nv_bfloat16 g_Xl[MROWS * D_MODEL];
__device__ __nv_bfloat16 g_Oh[MROWS * D_MODEL];
__device__ __nv_bfloat16 g_Ol[MROWS * D_MODEL];
__device__ __nv_bfloat16 g_Wh[4 * D_MODEL * D_MODEL];
__device__ __nv_bfloat16 g_Wl[4 * D_MODEL * D_MODEL];

__device__ __nv_bfloat16 g_Qh[MROWS * D_MODEL];
__device__ __nv_bfloat16 g_Ql[MROWS * D_MODEL];
__device__ __nv_bfloat16 g_Kh[MROWS * D_MODEL];
__device__ __nv_bfloat16 g_Kl[MROWS * D_MODEL];
__device__ __nv_bfloat16 g_Vh[MROWS * D_MODEL];
__device__ __nv_bfloat16 g_Vl[MROWS * D_MODEL];

// ---------------- helpers ---------------------------------------------------
__device__ __forceinline__ uint32_t s_u32(const void* p) {
    return (uint32_t)__cvta_generic_to_shared(p);
}

#define LDSM4(r0, r1, r2, r3, a)                                              \
    asm volatile("ldmatrix.sync.aligned.m8n8.x4.shared.b16 {%0,%1,%2,%3},[%4];"\
        : "=r"(r0), "=r"(r1), "=r"(r2), "=r"(r3) : "r"(a))

#define LDSM4T(r0, r1, r2, r3, a)                                             \
    asm volatile("ldmatrix.sync.aligned.m8n8.x4.trans.shared.b16 {%0,%1,%2,%3},[%4];"\
        : "=r"(r0), "=r"(r1), "=r"(r2), "=r"(r3) : "r"(a))

#define MMA_BF16(c, a, b)                                                     \
    asm("mma.sync.aligned.m16n8k16.row.col.f32.bf16.bf16.f32 "                \
        "{%0,%1,%2,%3}, {%4,%5,%6,%7}, {%8,%9}, {%0,%1,%2,%3};"               \
        : "+f"((c)[0]), "+f"((c)[1]), "+f"((c)[2]), "+f"((c)[3])              \
        : "r"((a)[0]), "r"((a)[1]), "r"((a)[2]), "r"((a)[3]),                 \
          "r"((b)[0]), "r"((b)[1]))

// split two floats into packed bf16x2 hi + bf16x2 lo
__device__ __forceinline__ void split2(float a, float b, uint32_t& hi, uint32_t& lo) {
    __nv_bfloat162 h, l;
    h.x = __float2bfloat16_rn(a);
    h.y = __float2bfloat16_rn(b);
    l.x = __float2bfloat16_rn(a - __bfloat162float(h.x));
    l.y = __float2bfloat16_rn(b - __bfloat162float(h.y));
    hi = *reinterpret_cast<uint32_t*>(&h);
    lo = *reinterpret_cast<uint32_t*>(&l);
}

// ============================================================================
// Split fp32 -> bf16 hi + bf16 lo. 4 floats/thread.
// ============================================================================
__global__ void convert_split4(const float4* __restrict__ src,
                               uint2* __restrict__ hi, uint2* __restrict__ lo,
                               int n4)
{
    int i = blockIdx.x * blockDim.x + threadIdx.x;
    if (i >= n4) return;
    float4 v = src[i];
    uint2 ho, loo;
    split2(v.x, v.y, ho.x, loo.x);
    split2(v.z, v.w, ho.y, loo.y);
    hi[i] = ho;
    lo[i] = loo;
}

// ============================================================================
// Tensor-core GEMM: C[M,N] = A[M,K] @ W[N,K]^T + bias[N]
// bf16 split operands, ldmatrix fragment loads, fp32 accum.
// 128x128 tile, BK=32, 8 warps, warp tile 64x32.
// ============================================================================
#define GSTR 40   // smem row stride in bf16 (32 data + 8 pad)

__global__ __launch_bounds__(256, 1) void gemm_bf16_split(
    const __nv_bfloat16* __restrict__ Ah, const __nv_bfloat16* __restrict__ Al,
    const __nv_bfloat16* __restrict__ Wh, const __nv_bfloat16* __restrict__ Wl,
    const float* __restrict__ bias, float* __restrict__ C,
    int M, int N, int K)
{
    __shared__ __align__(16) __nv_bfloat16 sAh[128 * GSTR];
    __shared__ __align__(16) __nv_bfloat16 sAl[128 * GSTR];
    __shared__ __align__(16) __nv_bfloat16 sWh[128 * GSTR];
    __shared__ __align__(16) __nv_bfloat16 sWl[128 * GSTR];

    const int tid  = threadIdx.x;
    const int lane = tid & 31;
    const int wrp  = tid >> 5;
    const int g    = lane >> 2;
    const int t    = lane & 3;
    const int wm   = (wrp & 1) * 64;
    const int wn   = (wrp >> 1) * 32;
    const int rowBase = blockIdx.y * 128;
    const int colBase = blockIdx.x * 128;

    const int arow = (lane & 15);
    const int akoA = ((lane >> 4) << 3);
    const int brow = ((lane >> 4) << 3) + (lane & 7);
    const int bkoB = ((lane >> 3) & 1) * 8;

    float c[4][4][4];
#pragma unroll
    for (int i = 0; i < 4; i++)
#pragma unroll
        for (int j = 0; j < 4; j++)
#pragma unroll
            for (int e = 0; e < 4; e++) c[i][j][e] = 0.0f;

    for (int kt = 0; kt < K; kt += 32) {
#pragma unroll
        for (int p = 0; p < 2; p++) {
            int id = tid + p * 256;       // 0..511
            int r  = id >> 2;
            int q  = (id & 3) * 8;        // bf16 offset of uint4 chunk
            *(uint4*)&sAh[r * GSTR + q] = *(const uint4*)&Ah[(size_t)(rowBase + r) * K + kt + q];
            *(uint4*)&sAl[r * GSTR + q] = *(const uint4*)&Al[(size_t)(rowBase + r) * K + kt + q];
            *(uint4*)&sWh[r * GSTR + q] = *(const uint4*)&Wh[(size_t)(colBase + r) * K + kt + q];
            *(uint4*)&sWl[r * GSTR + q] = *(const uint4*)&Wl[(size_t)(colBase + r) * K + kt + q];
        }
        __syncthreads();

#pragma unroll
        for (int kk = 0; kk < 2; kk++) {
            uint32_t ah[4][4], al[4][4], bh[4][2], bl[4][2];
#pragma unroll
            for (int i = 0; i < 4; i++) {
                uint32_t a = s_u32(&sAh[(wm + 16 * i + arow) * GSTR + kk * 16 + akoA]);
                LDSM4(ah[i][0], ah[i][1], ah[i][2], ah[i][3], a);
                a = s_u32(&sAl[(wm + 16 * i + arow) * GSTR + kk * 16 + akoA]);
                LDSM4(al[i][0], al[i][1], al[i][2], al[i][3], a);
            }
#pragma unroll
            for (int jj = 0; jj < 2; jj++) {
                uint32_t a = s_u32(&sWh[(wn + 16 * jj + brow) * GSTR + kk * 16 + bkoB]);
                LDSM4(bh[2*jj][0], bh[2*jj][1], bh[2*jj+1][0], bh[2*jj+1][1], a);
                a = s_u32(&sWl[(wn + 16 * jj + brow) * GSTR + kk * 16 + bkoB]);
                LDSM4(bl[2*jj][0], bl[2*jj][1], bl[2*jj+1][0], bl[2*jj+1][1], a);
            }
#pragma unroll
            for (int i = 0; i < 4; i++)
#pragma unroll
                for (int j = 0; j < 4; j++) {
                    MMA_BF16(c[i][j], ah[i], bh[j]);
                    MMA_BF16(c[i][j], ah[i], bl[j]);
                    MMA_BF16(c[i][j], al[i], bh[j]);
                }
        }
        __syncthreads();
    }

#pragma unroll
    for (int i = 0; i < 4; i++) {
        int row = rowBase + wm + i * 16 + g;
#pragma unroll
        for (int j = 0; j < 4; j++) {
            int col = colBase + wn + j * 8 + 2 * t;
            float b0 = bias[col], b1 = bias[col + 1];
            float2 v0 = make_float2(c[i][j][0] + b0, c[i][j][1] + b1);
            float2 v1 = make_float2(c[i][j][2] + b0, c[i][j][3] + b1);
            *reinterpret_cast<float2*>(&C[(size_t)row * N + col])       = v0;
            *reinterpret_cast<float2*>(&C[(size_t)(row + 8) * N + col]) = v1;
        }
    }
}

// ============================================================================
// Fused RoPE + 0.125 Q-scale + bf16 hi/lo split for Q and K.
// ============================================================================
__global__ void rope_split(const float* __restrict__ Q, const float* __restrict__ K,
                           __nv_bfloat16* __restrict__ Qh, __nv_bfloat16* __restrict__ Ql,
                           __nv_bfloat16* __restrict__ Kh, __nv_bfloat16* __restrict__ Kl)
{
    int idx = blockIdx.x * blockDim.x + threadIdx.x;
    int p  = idx & 31;
    int h  = (idx >> 5) & 15;
    int bs = idx >> 9;
    int s  = bs & (SEQ - 1);

    size_t base = (size_t)bs * D_MODEL + h * DKH + 2 * p;
    float angle = (float)s * powf(10000.0f, -(float)p * (1.0f / 32.0f));
    float sn, cs;
    sincosf(angle, &sn, &cs);

    float q0 = Q[base], q1 = Q[base + 1];
    float k0 = K[base], k1 = K[base + 1];
    float qa = (q0 * cs - q1 * sn) * 0.125f;
    float qb = (q1 * cs + q0 * sn) * 0.125f;
    float ka = k0 * cs - k1 * sn;
    float kb = k1 * cs + k0 * sn;

    uint32_t hi, lo;
    split2(qa, qb, hi, lo);
    *(uint32_t*)&Qh[base] = hi;
    *(uint32_t*)&Ql[base] = lo;
    split2(ka, kb, hi, lo);
    *(uint32_t*)&Kh[base] = hi;
    *(uint32_t*)&Kl[base] = lo;
}

// ============================================================================
// Tensor-core flash attention.
// Block: 128 q-rows x one (b,h). 8 warps; warp owns 16 q-rows.
// S = Qh@Kh + Qh@Kl + Ql@Kh (fp32 acc) ; fp32 online softmax on fragments;
// O += Ph@Vh + Ph@Vl + Pl@Vh with P built in-register from the S C-fragment.
// ============================================================================
#define ATS 72   // smem row stride in bf16 (64 data + 8 pad)
#define ATT_SMEM ((2 * 128 + 4 * 64) * ATS * 2)   // 73728 bytes

__global__ __launch_bounds__(256, 1) void attention_mma(
    const __nv_bfloat16* __restrict__ Qh, const __nv_bfloat16* __restrict__ Ql,
    const __nv_bfloat16* __restrict__ Kh, const __nv_bfloat16* __restrict__ Kl,
    const __nv_bfloat16* __restrict__ Vh, const __nv_bfloat16* __restrict__ Vl,
    __nv_bfloat16* __restrict__ Oh, __nv_bfloat16* __restrict__ Ol)
{
    extern __shared__ __nv_bfloat16 smb[];
    __nv_bfloat16* sQh = smb;
    __nv_bfloat16* sQl = sQh + 128 * ATS;
    __nv_bfloat16* sKh = sQl + 128 * ATS;
    __nv_bfloat16* sKl = sKh + 64 * ATS;
    __nv_bfloat16* sVh = sKl + 64 * ATS;
    __nv_bfloat16* sVl = sVh + 64 * ATS;

    const int bh = blockIdx.y;
    const int b  = bh >> 4;
    const int h  = bh & 15;
    const int q0 = blockIdx.x * 128;
    const int tid  = threadIdx.x;
    const int lane = tid & 31;
    const int wrp  = tid >> 5;
    const int g    = lane >> 2;
    const int t    = lane & 3;

    const size_t gbase = (size_t)b * SEQ * D_MODEL + (size_t)h * DKH;

    // ---- load Q tiles (128 x 64 bf16, hi+lo) ----
    for (int idx = tid; idx < 128 * 8; idx += 256) {
        int r  = idx >> 3;
        int cq = (idx & 7) * 8;
        size_t gq = gbase + (size_t)(q0 + r) * D_MODEL + cq;
        *(uint4*)&sQh[r * ATS + cq] = *(const uint4*)&Qh[gq];
        *(uint4*)&sQl[r * ATS + cq] = *(const uint4*)&Ql[gq];
    }
    __syncthreads();

    // ---- preload Q fragments into registers (reused for all KV tiles) ----
    uint32_t qfh[4][4], qfl[4][4];
    {
        int arow = 16 * wrp + (lane & 15);
        int ako  = ((lane >> 4) << 3);
#pragma unroll
        for (int kc = 0; kc < 4; kc++) {
            uint32_t a = s_u32(&sQh[arow * ATS + kc * 16 + ako]);
            LDSM4(qfh[kc][0], qfh[kc][1], qfh[kc][2], qfh[kc][3], a);
            a = s_u32(&sQl[arow * ATS + kc * 16 + ako]);
            LDSM4(qfl[kc][0], qfl[kc][1], qfl[kc][2], qfl[kc][3], a);
        }
    }

    float m[2] = {-INFINITY, -INFINITY};
    float l[2] = {0.0f, 0.0f};
    float o[8][4];
#pragma unroll
    for (int j = 0; j < 8; j++)
#pragma unroll
        for (int e = 0; e < 4; e++) o[j][e] = 0.0f;

    const int brow  = ((lane >> 4) << 3) + (lane & 7);     // K n-row within pair
    const int bko   = ((lane >> 3) & 1) * 8;               // K k-offset
    const int vrow  = (lane & 7) + ((lane >> 3) & 1) * 8;  // V k-row within chunk
    const int vcol  = ((lane >> 4) << 3);                  // V n-offset within pair

    for (int kv0 = 0; kv0 < SEQ; kv0 += 64) {
        __syncthreads();
        for (int idx = tid; idx < 64 * 8; idx += 256) {
            int r  = idx >> 3;
            int cq = (idx & 7) * 8;
            size_t gk = gbase + (size_t)(kv0 + r) * D_MODEL + cq;
            *(uint4*)&sKh[r * ATS + cq] = *(const uint4*)&Kh[gk];
            *(uint4*)&sKl[r * ATS + cq] = *(const uint4*)&Kl[gk];
            *(uint4*)&sVh[r * ATS + cq] = *(const uint4*)&Vh[gk];
            *(uint4*)&sVl[r * ATS + cq] = *(const uint4*)&Vl[gk];
        }
        __syncthreads();

        // ---- S = Q @ K^T (split, fp32 acc) ----
        float s[8][4];
#pragma unroll
        for (int j = 0; j < 8; j++)
#pragma unroll
            for (int e = 0; e < 4; e++) s[j][e] = 0.0f;

#pragma unroll
        for (int kc = 0; kc < 4; kc++) {
            uint32_t kbh[8][2], kbl[8][2];
#pragma unroll
            for (int jj = 0; jj < 4; jj++) {
                uint32_t a = s_u32(&sKh[(16 * jj + brow) * ATS + kc * 16 + bko]);
                LDSM4(kbh[2*jj][0], kbh[2*jj][1], kbh[2*jj+1][0], kbh[2*jj+1][1], a);
                a = s_u32(&sKl[(16 * jj + brow) * ATS + kc * 16 + bko]);
                LDSM4(kbl[2*jj][0], kbl[2*jj][1], kbl[2*jj+1][0], kbl[2*jj+1][1], a);
            }
#pragma unroll
            for (int j = 0; j < 8; j++) {
                MMA_BF16(s[j], qfh[kc], kbh[j]);
                MMA_BF16(s[j], qfh[kc], kbl[j]);
                MMA_BF16(s[j], qfl[kc], kbh[j]);
            }
        }

        // ---- online softmax (rows g and g+8; quad-lane reduction) ----
        float alpha[2];
#pragma unroll
        for (int e = 0; e < 2; e++) {
            float mloc = s[0][2 * e];
#pragma unroll
            for (int j = 0; j < 8; j++) {
                mloc = fmaxf(mloc, s[j][2 * e]);
                mloc = fmaxf(mloc, s[j][2 * e + 1]);
            }
            mloc = fmaxf(mloc, __shfl_xor_sync(0xffffffffu, mloc, 1));
            mloc = fmaxf(mloc, __shfl_xor_sync(0xffffffffu, mloc, 2));
            float mnew = fmaxf(m[e], mloc);
            alpha[e] = __expf(m[e] - mnew);
            float ls = 0.0f;
#pragma unroll
            for (int j = 0; j < 8; j++) {
                float p0 = __expf(s[j][2 * e]     - mnew);
                float p1 = __expf(s[j][2 * e + 1] - mnew);
                s[j][2 * e]     = p0;
                s[j][2 * e + 1] = p1;
                ls += p0 + p1;
            }
            ls += __shfl_xor_sync(0xffffffffu, ls, 1);
            ls += __shfl_xor_sync(0xffffffffu, ls, 2);
            l[e] = l[e] * alpha[e] + ls;
            m[e] = mnew;
        }
#pragma unroll
        for (int j = 0; j < 8; j++) {
            o[j][0] *= alpha[0]; o[j][1] *= alpha[0];
            o[j][2] *= alpha[1]; o[j][3] *= alpha[1];
        }

        // ---- build P fragments (hi/lo) directly from S C-fragments ----
        uint32_t pah[4][4], pal[4][4];
#pragma unroll
        for (int kc = 0; kc < 4; kc++) {
            split2(s[2*kc][0],   s[2*kc][1],   pah[kc][0], pal[kc][0]);
            split2(s[2*kc][2],   s[2*kc][3],   pah[kc][1], pal[kc][1]);
            split2(s[2*kc+1][0], s[2*kc+1][1], pah[kc][2], pal[kc][2]);
            split2(s[2*kc+1][2], s[2*kc+1][3], pah[kc][3], pal[kc][3]);
        }

        // ---- O += P @ V (split) ----
#pragma unroll
        for (int kc = 0; kc < 4; kc++) {
            uint32_t vbh[8][2], vbl[8][2];
#pragma unroll
            for (int jj = 0; jj < 4; jj++) {
                uint32_t a = s_u32(&sVh[(kc * 16 + vrow) * ATS + 16 * jj + vcol]);
                LDSM4T(vbh[2*jj][0], vbh[2*jj][1], vbh[2*jj+1][0], vbh[2*jj+1][1], a);
                a = s_u32(&sVl[(kc * 16 + vrow) * ATS + 16 * jj + vcol]);
                LDSM4T(vbl[2*jj][0], vbl[2*jj][1], vbl[2*jj+1][0], vbl[2*jj+1][1], a);
            }
#pragma unroll
            for (int j = 0; j < 8; j++) {
                MMA_BF16(o[j], pah[kc], vbh[j]);
                MMA_BF16(o[j], pah[kc], vbl[j]);
                MMA_BF16(o[j], pal[kc], vbh[j]);
            }
        }
    }

    // ---- epilogue: normalize and write split bf16 O ----
    const int r0 = q0 + 16 * wrp + g;
    const float inv0 = 1.0f / l[0];
    const float inv1 = 1.0f / l[1];
#pragma unroll
    for (int j = 0; j < 8; j++) {
        int col = h * DKH + 8 * j + 2 * t;
        size_t i0 = (size_t)b * SEQ * D_MODEL + (size_t)r0 * D_MODEL + col;
        size_t i1 = i0 + (size_t)8 * D_MODEL;
        uint32_t hi, lo;
        split2(o[j][0] * inv0, o[j][1] * inv0, hi, lo);
        *(uint32_t*)&Oh[i0] = hi;
        *(uint32_t*)&Ol[i0] = lo;
        split2(o[j][2] * inv1, o[j][3] * inv1, hi, lo);
        *(uint32_t*)&Oh[i1] = hi;
        *(uint32_t*)&Ol[i1] = lo;
    }
}

// ============================================================================
// Launch
// ============================================================================
extern "C" void kernel_launch(void* const* d_in, const int* in_sizes, int n_in,
                              void* d_out, int out_size)
{
    (void)in_sizes; (void)n_in; (void)out_size;
    const float* x  = (const float*)d_in[0];
    const float* wq = (const float*)d_in[1];
    const float* bq = (const float*)d_in[2];
    const float* wk = (const float*)d_in[3];
    const float* bk = (const float*)d_in[4];
    const float* wv = (const float*)d_in[5];
    const float* bv = (const float*)d_in[6];
    const float* wo = (const float*)d_in[7];
    const float* bo = (const float*)d_in[8];
    float* out = (float*)d_out;

    float *Qp, *Kp, *Vp;
    __nv_bfloat16 *Xh, *Xl, *Ohp, *Olp, *Wh, *Wl;
    __nv_bfloat16 *Qhp, *Qlp, *Khp, *Klp, *Vhp, *Vlp;
    cudaGetSymbolAddress((void**)&Qp, g_Q);
    cudaGetSymbolAddress((void**)&Kp, g_K);
    cudaGetSymbolAddress((void**)&Vp, g_V);
    cudaGetSymbolAddress((void**)&Xh, g_Xh);
    cudaGetSymbolAddress((void**)&Xl, g_Xl);
    cudaGetSymbolAddress((void**)&Ohp, g_Oh);
    cudaGetSymbolAddress((void**)&Olp, g_Ol);
    cudaGetSymbolAddress((void**)&Wh, g_Wh);
    cudaGetSymbolAddress((void**)&Wl, g_Wl);
    cudaGetSymbolAddress((void**)&Qhp, g_Qh);
    cudaGetSymbolAddress((void**)&Qlp, g_Ql);
    cudaGetSymbolAddress((void**)&Khp, g_Kh);
    cudaGetSymbolAddress((void**)&Klp, g_Kl);
    cudaGetSymbolAddress((void**)&Vhp, g_Vh);
    cudaGetSymbolAddress((void**)&Vlp, g_Vl);

    cudaFuncSetAttribute(attention_mma,
                         cudaFuncAttributeMaxDynamicSharedMemorySize,
                         ATT_SMEM);

    const int WSZ = D_MODEL * D_MODEL;

    // --- split conversions (x and the 4 weights) ---
    int n4x = (MROWS * D_MODEL) / 4;
    int n4w = WSZ / 4;
    convert_split4<<<(n4x + 255) / 256, 256>>>((const float4*)x,  (uint2*)Xh,           (uint2*)Xl,           n4x);
    convert_split4<<<(n4w + 255) / 256, 256>>>((const float4*)wq, (uint2*)(Wh + 0*WSZ), (uint2*)(Wl + 0*WSZ), n4w);
    convert_split4<<<(n4w + 255) / 256, 256>>>((const float4*)wk, (uint2*)(Wh + 1*WSZ), (uint2*)(Wl + 1*WSZ), n4w);
    convert_split4<<<(n4w + 255) / 256, 256>>>((const float4*)wv, (uint2*)(Wh + 2*WSZ), (uint2*)(Wl + 2*WSZ), n4w);
    convert_split4<<<(n4w + 255) / 256, 256>>>((const float4*)wo, (uint2*)(Wh + 3*WSZ), (uint2*)(Wl + 3*WSZ), n4w);

    // --- QKV projections on tensor cores ---
    dim3 ggrid(D_MODEL / 128, MROWS / 128);   // (8, 32)
    gemm_bf16_split<<<ggrid, 256>>>(Xh, Xl, Wh + 0*WSZ, Wl + 0*WSZ, bq, Qp, MROWS, D_MODEL, D_MODEL);
    gemm_bf16_split<<<ggrid, 256>>>(Xh, Xl, Wh + 1*WSZ, Wl + 1*WSZ, bk, Kp, MROWS, D_MODEL, D_MODEL);
    gemm_bf16_split<<<ggrid, 256>>>(Xh, Xl, Wh + 2*WSZ, Wl + 2*WSZ, bv, Vp, MROWS, D_MODEL, D_MODEL);

    // --- fused RoPE + split (Q,K), split V ---
    int rope_threads = BATCH * SEQ * NUM_HEADS * (DKH / 2);   // 2,097,152
    rope_split<<<rope_threads / 256, 256>>>(Qp, Kp, Qhp, Qlp, Khp, Klp);
    convert_split4<<<(n4x + 255) / 256, 256>>>((const float4*)Vp, (uint2*)Vhp, (uint2*)Vlp, n4x);

    // --- tensor-core flash attention ---
    dim3 agrid(SEQ / 128, BATCH * NUM_HEADS);                 // (16, 32)
    attention_mma<<<agrid, 256, ATT_SMEM>>>(Qhp, Qlp, Khp, Klp, Vhp, Vlp, Ohp, Olp);

    // --- output projection ---
    gemm_bf16_split<<<ggrid, 256>>>(Ohp, Olp, Wh + 3*WSZ, Wl + 3*WSZ, bo, out, MROWS, D_MODEL, D_MODEL);
}

// round 8
// speedup vs baseline: 3.2402x; 1.2484x over previous
#include <cuda_runtime.h>
#include <cuda_bf16.h>
#include <math.h>
#include <stdint.h>

#define D_MODEL   1024
#define NUM_HEADS 16
#define DKH       64
#define BATCH     2
#define SEQ       2048
#define MROWS     (BATCH * SEQ)   // 4096

// ---------------- scratch (device globals; no allocation allowed) ----------
__device__ float g_Q[MROWS * D_MODEL];
__device__ float g_K[MROWS * D_MODEL];
__device__ float g_V[MROWS * D_MODEL];

__device__ __nv_bfloat16 g_Xh[MROWS * D_MODEL];
__device__ __nv_bfloat16 g_Xl[MROWS * D_MODEL];
__device__ __nv_bfloat16 g_Oh[MROWS * D_MODEL];
__device__ __nv_bfloat16 g_Ol[MROWS * D_MODEL];
__device__ __nv_bfloat16 g_Wh[4 * D_MODEL * D_MODEL];
__device__ __nv_bfloat16 g_Wl[4 * D_MODEL * D_MODEL];

__device__ __nv_bfloat16 g_Qh[MROWS * D_MODEL];
__device__ __nv_bfloat16 g_Ql[MROWS * D_MODEL];
__device__ __nv_bfloat16 g_Kh[MROWS * D_MODEL];
__device__ __nv_bfloat16 g_Kl[MROWS * D_MODEL];
__device__ __nv_bfloat16 g_Vh[MROWS * D_MODEL];
__device__ __nv_bfloat16 g_Vl[MROWS * D_MODEL];

// ---------------- helpers ---------------------------------------------------
__device__ __forceinline__ uint32_t s_u32(const void* p) {
    return (uint32_t)__cvta_generic_to_shared(p);
}

#define LDSM4(r0, r1, r2, r3, a)                                              \
    asm volatile("ldmatrix.sync.aligned.m8n8.x4.shared.b16 {%0,%1,%2,%3},[%4];"\
        : "=r"(r0), "=r"(r1), "=r"(r2), "=r"(r3) : "r"(a))

#define LDSM4T(r0, r1, r2, r3, a)                                             \
    asm volatile("ldmatrix.sync.aligned.m8n8.x4.trans.shared.b16 {%0,%1,%2,%3},[%4];"\
        : "=r"(r0), "=r"(r1), "=r"(r2), "=r"(r3) : "r"(a))

#define MMA_BF16(c, a, b)                                                     \
    asm("mma.sync.aligned.m16n8k16.row.col.f32.bf16.bf16.f32 "                \
        "{%0,%1,%2,%3}, {%4,%5,%6,%7}, {%8,%9}, {%0,%1,%2,%3};"               \
        : "+f"((c)[0]), "+f"((c)[1]), "+f"((c)[2]), "+f"((c)[3])              \
        : "r"((a)[0]), "r"((a)[1]), "r"((a)[2]), "r"((a)[3]),                 \
          "r"((b)[0]), "r"((b)[1]))

#define CP_ASYNC16(dst, src)                                                  \
    asm volatile("cp.async.cg.shared.global [%0], [%1], 16;"                  \
        :: "r"(dst), "l"(src))
#define CP_COMMIT   asm volatile("cp.async.commit_group;")
#define CP_WAIT1    asm volatile("cp.async.wait_group 1;")
#define CP_WAIT0    asm volatile("cp.async.wait_group 0;")

__device__ __forceinline__ void split2(float a, float b, uint32_t& hi, uint32_t& lo) {
    __nv_bfloat162 h, l;
    h.x = __float2bfloat16_rn(a);
    h.y = __float2bfloat16_rn(b);
    l.x = __float2bfloat16_rn(a - __bfloat162float(h.x));
    l.y = __float2bfloat16_rn(b - __bfloat162float(h.y));
    hi = *reinterpret_cast<uint32_t*>(&h);
    lo = *reinterpret_cast<uint32_t*>(&l);
}

// ============================================================================
// fp32 -> bf16 hi/lo split converters
// ============================================================================
__global__ void convert_split4(const float4* __restrict__ src,
                               uint2* __restrict__ hi, uint2* __restrict__ lo,
                               int n4)
{
    int i = blockIdx.x * blockDim.x + threadIdx.x;
    if (i >= n4) return;
    float4 v = src[i];
    uint2 ho, loo;
    split2(v.x, v.y, ho.x, loo.x);
    split2(v.z, v.w, ho.y, loo.y);
    hi[i] = ho;
    lo[i] = loo;
}

// all four weights in one launch (grid.y = 4)
__global__ void convert_weights4(const float4* __restrict__ w0,
                                 const float4* __restrict__ w1,
                                 const float4* __restrict__ w2,
                                 const float4* __restrict__ w3,
                                 uint2* __restrict__ Wh, uint2* __restrict__ Wl,
                                 int n4)
{
    int i = blockIdx.x * blockDim.x + threadIdx.x;
    if (i >= n4) return;
    int z = blockIdx.y;
    const float4* src = (z == 0) ? w0 : (z == 1) ? w1 : (z == 2) ? w2 : w3;
    float4 v = src[i];
    uint2 ho, loo;
    split2(v.x, v.y, ho.x, loo.x);
    split2(v.z, v.w, ho.y, loo.y);
    Wh[(size_t)z * n4 + i] = ho;
    Wl[(size_t)z * n4 + i] = loo;
}

// ============================================================================
// Tensor-core GEMM (4096x1024x1024, NT, +bias), bf16 3-term split,
// cp.async 2-stage double buffer. 128x128 tile, BK=32, 8 warps.
// ============================================================================
#define GSTR    40                 // smem row stride (bf16): 32 data + 8 pad
#define G_ARR   (128 * GSTR)       // bf16 per operand tile
#define G_STAGE (4 * G_ARR)        // bf16 per stage
#define GEMM_SMEM (2 * G_STAGE * 2)  // 81920 bytes

__device__ __forceinline__ void gemm_prefetch(
    __nv_bfloat16* st,
    const __nv_bfloat16* __restrict__ Ah, const __nv_bfloat16* __restrict__ Al,
    const __nv_bfloat16* __restrict__ Wh, const __nv_bfloat16* __restrict__ Wl,
    int rowBase, int colBase, int kt, int tid)
{
#pragma unroll
    for (int p = 0; p < 2; p++) {
        int id = tid + p * 256;           // 0..511
        int r  = id >> 2;
        int q  = (id & 3) * 8;
        int so = r * GSTR + q;
        size_t ga = (size_t)(rowBase + r) * D_MODEL + kt + q;
        size_t gw = (size_t)(colBase + r) * D_MODEL + kt + q;
        CP_ASYNC16(s_u32(st + so),             Ah + ga);
        CP_ASYNC16(s_u32(st + G_ARR + so),     Al + ga);
        CP_ASYNC16(s_u32(st + 2 * G_ARR + so), Wh + gw);
        CP_ASYNC16(s_u32(st + 3 * G_ARR + so), Wl + gw);
    }
}

__device__ __forceinline__ void gemm_body(
    const __nv_bfloat16* __restrict__ Ah, const __nv_bfloat16* __restrict__ Al,
    const __nv_bfloat16* __restrict__ Wh, const __nv_bfloat16* __restrict__ Wl,
    const float* __restrict__ bias, float* __restrict__ C,
    __nv_bfloat16* sm)
{
    const int tid  = threadIdx.x;
    const int lane = tid & 31;
    const int wrp  = tid >> 5;
    const int g    = lane >> 2;
    const int t    = lane & 3;
    const int wm   = (wrp & 1) * 64;
    const int wn   = (wrp >> 1) * 32;
    const int rowBase = blockIdx.y * 128;
    const int colBase = blockIdx.x * 128;

    const int arow = (lane & 15);
    const int akoA = ((lane >> 4) << 3);
    const int brow = ((lane >> 4) << 3) + (lane & 7);
    const int bkoB = ((lane >> 3) & 1) * 8;

    float c[4][4][4];
#pragma unroll
    for (int i = 0; i < 4; i++)
#pragma unroll
        for (int j = 0; j < 4; j++)
#pragma unroll
            for (int e = 0; e < 4; e++) c[i][j][e] = 0.0f;

    gemm_prefetch(sm, Ah, Al, Wh, Wl, rowBase, colBase, 0, tid);
    CP_COMMIT;

    const int NK = D_MODEL / 32;   // 32
    for (int it = 0; it < NK; it++) {
        __syncthreads();   // all warps done reading the stage we overwrite next
        if (it + 1 < NK) {
            gemm_prefetch(sm + ((it + 1) & 1) * G_STAGE, Ah, Al, Wh, Wl,
                          rowBase, colBase, (it + 1) * 32, tid);
            CP_COMMIT;
            CP_WAIT1;
        } else {
            CP_WAIT0;
        }
        __syncthreads();

        __nv_bfloat16* st  = sm + (it & 1) * G_STAGE;
        __nv_bfloat16* sAh = st;
        __nv_bfloat16* sAl = st + G_ARR;
        __nv_bfloat16* sWh = st + 2 * G_ARR;
        __nv_bfloat16* sWl = st + 3 * G_ARR;

#pragma unroll
        for (int kk = 0; kk < 2; kk++) {
            uint32_t ah[4][4], al[4][4], bh[4][2], bl[4][2];
#pragma unroll
            for (int i = 0; i < 4; i++) {
                uint32_t a = s_u32(&sAh[(wm + 16 * i + arow) * GSTR + kk * 16 + akoA]);
                LDSM4(ah[i][0], ah[i][1], ah[i][2], ah[i][3], a);
                a = s_u32(&sAl[(wm + 16 * i + arow) * GSTR + kk * 16 + akoA]);
                LDSM4(al[i][0], al[i][1], al[i][2], al[i][3], a);
            }
#pragma unroll
            for (int jj = 0; jj < 2; jj++) {
                uint32_t a = s_u32(&sWh[(wn + 16 * jj + brow) * GSTR + kk * 16 + bkoB]);
                LDSM4(bh[2*jj][0], bh[2*jj][1], bh[2*jj+1][0], bh[2*jj+1][1], a);
                a = s_u32(&sWl[(wn + 16 * jj + brow) * GSTR + kk * 16 + bkoB]);
                LDSM4(bl[2*jj][0], bl[2*jj][1], bl[2*jj+1][0], bl[2*jj+1][1], a);
            }
#pragma unroll
            for (int i = 0; i < 4; i++)
#pragma unroll
                for (int j = 0; j < 4; j++) {
                    MMA_BF16(c[i][j], ah[i], bh[j]);
                    MMA_BF16(c[i][j], ah[i], bl[j]);
                    MMA_BF16(c[i][j], al[i], bh[j]);
                }
        }
    }

#pragma unroll
    for (int i = 0; i < 4; i++) {
        int row = rowBase + wm + i * 16 + g;
#pragma unroll
        for (int j = 0; j < 4; j++) {
            int col = colBase + wn + j * 8 + 2 * t;
            float b0 = bias[col], b1 = bias[col + 1];
            float2 v0 = make_float2(c[i][j][0] + b0, c[i][j][1] + b1);
            float2 v1 = make_float2(c[i][j][2] + b0, c[i][j][3] + b1);
            *reinterpret_cast<float2*>(&C[(size_t)row * D_MODEL + col])       = v0;
            *reinterpret_cast<float2*>(&C[(size_t)(row + 8) * D_MODEL + col]) = v1;
        }
    }
}

// QKV fused: blockIdx.z selects the weight / bias / output
__global__ __launch_bounds__(256, 1) void gemm_qkv(
    const __nv_bfloat16* __restrict__ Ah, const __nv_bfloat16* __restrict__ Al,
    const __nv_bfloat16* __restrict__ WhB, const __nv_bfloat16* __restrict__ WlB,
    const float* __restrict__ b0, const float* __restrict__ b1, const float* __restrict__ b2,
    float* __restrict__ C0, float* __restrict__ C1, float* __restrict__ C2)
{
    extern __shared__ __nv_bfloat16 smg[];
    const int z = blockIdx.z;
    const size_t WSZ = (size_t)D_MODEL * D_MODEL;
    const float* bias = (z == 0) ? b0 : (z == 1) ? b1 : b2;
    float*       C    = (z == 0) ? C0 : (z == 1) ? C1 : C2;
    gemm_body(Ah, Al, WhB + z * WSZ, WlB + z * WSZ, bias, C, smg);
}

__global__ __launch_bounds__(256, 1) void gemm_one(
    const __nv_bfloat16* __restrict__ Ah, const __nv_bfloat16* __restrict__ Al,
    const __nv_bfloat16* __restrict__ Wh, const __nv_bfloat16* __restrict__ Wl,
    const float* __restrict__ bias, float* __restrict__ C)
{
    extern __shared__ __nv_bfloat16 smg[];
    gemm_body(Ah, Al, Wh, Wl, bias, C, smg);
}

// ============================================================================
// Fused RoPE + 0.125 Q-scale + bf16 hi/lo split for Q and K.
// ============================================================================
__global__ void rope_split(const float* __restrict__ Q, const float* __restrict__ K,
                           __nv_bfloat16* __restrict__ Qh, __nv_bfloat16* __restrict__ Ql,
                           __nv_bfloat16* __restrict__ Kh, __nv_bfloat16* __restrict__ Kl)
{
    int idx = blockIdx.x * blockDim.x + threadIdx.x;
    int p  = idx & 31;
    int h  = (idx >> 5) & 15;
    int bs = idx >> 9;
    int s  = bs & (SEQ - 1);

    size_t base = (size_t)bs * D_MODEL + h * DKH + 2 * p;
    float angle = (float)s * powf(10000.0f, -(float)p * (1.0f / 32.0f));
    float sn, cs;
    sincosf(angle, &sn, &cs);

    float q0 = Q[base], q1 = Q[base + 1];
    float k0 = K[base], k1 = K[base + 1];
    float qa = (q0 * cs - q1 * sn) * 0.125f;
    float qb = (q1 * cs + q0 * sn) * 0.125f;
    float ka = k0 * cs - k1 * sn;
    float kb = k1 * cs + k0 * sn;

    uint32_t hi, lo;
    split2(qa, qb, hi, lo);
    *(uint32_t*)&Qh[base] = hi;
    *(uint32_t*)&Ql[base] = lo;
    split2(ka, kb, hi, lo);
    *(uint32_t*)&Kh[base] = hi;
    *(uint32_t*)&Kl[base] = lo;
}

// ============================================================================
// Tensor-core flash attention with cp.async double-buffered KV tiles.
// ============================================================================
#define ATS     72                 // smem row stride (bf16): 64 data + 8 pad
#define A_ARR   (64 * ATS)
#define A_STAGE (4 * A_ARR)
#define ATT_SMEM ((2 * 128 * ATS + 2 * A_STAGE) * 2)   // 110592 bytes

__device__ __forceinline__ void att_prefetch(
    __nv_bfloat16* st,
    const __nv_bfloat16* __restrict__ Kh, const __nv_bfloat16* __restrict__ Kl,
    const __nv_bfloat16* __restrict__ Vh, const __nv_bfloat16* __restrict__ Vl,
    size_t gbase, int kv0, int tid)
{
#pragma unroll
    for (int p = 0; p < 2; p++) {
        int idx = tid + p * 256;          // 0..511
        int r   = idx >> 3;
        int cq  = (idx & 7) * 8;
        int so  = r * ATS + cq;
        size_t gk = gbase + (size_t)(kv0 + r) * D_MODEL + cq;
        CP_ASYNC16(s_u32(st + so),             Kh + gk);
        CP_ASYNC16(s_u32(st + A_ARR + so),     Kl + gk);
        CP_ASYNC16(s_u32(st + 2 * A_ARR + so), Vh + gk);
        CP_ASYNC16(s_u32(st + 3 * A_ARR + so), Vl + gk);
    }
}

__global__ __launch_bounds__(256, 1) void attention_mma(
    const __nv_bfloat16* __restrict__ Qh, const __nv_bfloat16* __restrict__ Ql,
    const __nv_bfloat16* __restrict__ Kh, const __nv_bfloat16* __restrict__ Kl,
    const __nv_bfloat16* __restrict__ Vh, const __nv_bfloat16* __restrict__ Vl,
    __nv_bfloat16* __restrict__ Oh, __nv_bfloat16* __restrict__ Ol)
{
    extern __shared__ __nv_bfloat16 smb[];
    __nv_bfloat16* sQh = smb;
    __nv_bfloat16* sQl = sQh + 128 * ATS;
    __nv_bfloat16* sKV = sQl + 128 * ATS;    // 2 stages of {Kh,Kl,Vh,Vl}

    const int bh = blockIdx.y;
    const int b  = bh >> 4;
    const int h  = bh & 15;
    const int q0 = blockIdx.x * 128;
    const int tid  = threadIdx.x;
    const int lane = tid & 31;
    const int wrp  = tid >> 5;
    const int g    = lane >> 2;
    const int t    = lane & 3;

    const size_t gbase = (size_t)b * SEQ * D_MODEL + (size_t)h * DKH;

    // prefetch KV tile 0 while we set up Q
    att_prefetch(sKV, Kh, Kl, Vh, Vl, gbase, 0, tid);
    CP_COMMIT;

    // ---- load Q tiles (128 x 64 bf16, hi+lo) ----
    for (int idx = tid; idx < 128 * 8; idx += 256) {
        int r  = idx >> 3;
        int cq = (idx & 7) * 8;
        size_t gq = gbase + (size_t)(q0 + r) * D_MODEL + cq;
        *(uint4*)&sQh[r * ATS + cq] = *(const uint4*)&Qh[gq];
        *(uint4*)&sQl[r * ATS + cq] = *(const uint4*)&Ql[gq];
    }
    __syncthreads();

    // ---- preload Q fragments (reused across all KV tiles) ----
    uint32_t qfh[4][4], qfl[4][4];
    {
        int arow = 16 * wrp + (lane & 15);
        int ako  = ((lane >> 4) << 3);
#pragma unroll
        for (int kc = 0; kc < 4; kc++) {
            uint32_t a = s_u32(&sQh[arow * ATS + kc * 16 + ako]);
            LDSM4(qfh[kc][0], qfh[kc][1], qfh[kc][2], qfh[kc][3], a);
            a = s_u32(&sQl[arow * ATS + kc * 16 + ako]);
            LDSM4(qfl[kc][0], qfl[kc][1], qfl[kc][2], qfl[kc][3], a);
        }
    }

    float m[2] = {-INFINITY, -INFINITY};
    float l[2] = {0.0f, 0.0f};
    float o[8][4];
#pragma unroll
    for (int j = 0; j < 8; j++)
#pragma unroll
        for (int e = 0; e < 4; e++) o[j][e] = 0.0f;

    const int brow  = ((lane >> 4) << 3) + (lane & 7);
    const int bko   = ((lane >> 3) & 1) * 8;
    const int vrow  = (lane & 7) + ((lane >> 3) & 1) * 8;
    const int vcol  = ((lane >> 4) << 3);

    const int NT = SEQ / 64;   // 32
    for (int it = 0; it < NT; it++) {
        __syncthreads();   // everyone done reading the stage we overwrite next
        if (it + 1 < NT) {
            att_prefetch(sKV + ((it + 1) & 1) * A_STAGE, Kh, Kl, Vh, Vl,
                         gbase, (it + 1) * 64, tid);
            CP_COMMIT;
            CP_WAIT1;
        } else {
            CP_WAIT0;
        }
        __syncthreads();

        __nv_bfloat16* st  = sKV + (it & 1) * A_STAGE;
        __nv_bfloat16* sKh = st;
        __nv_bfloat16* sKl = st + A_ARR;
        __nv_bfloat16* sVh = st + 2 * A_ARR;
        __nv_bfloat16* sVl = st + 3 * A_ARR;

        // ---- S = Q @ K^T (3-term split, fp32 acc) ----
        float s[8][4];
#pragma unroll
        for (int j = 0; j < 8; j++)
#pragma unroll
            for (int e = 0; e < 4; e++) s[j][e] = 0.0f;

#pragma unroll
        for (int kc = 0; kc < 4; kc++) {
            uint32_t kbh[8][2], kbl[8][2];
#pragma unroll
            for (int jj = 0; jj < 4; jj++) {
                uint32_t a = s_u32(&sKh[(16 * jj + brow) * ATS + kc * 16 + bko]);
                LDSM4(kbh[2*jj][0], kbh[2*jj][1], kbh[2*jj+1][0], kbh[2*jj+1][1], a);
                a = s_u32(&sKl[(16 * jj + brow) * ATS + kc * 16 + bko]);
                LDSM4(kbl[2*jj][0], kbl[2*jj][1], kbl[2*jj+1][0], kbl[2*jj+1][1], a);
            }
#pragma unroll
            for (int j = 0; j < 8; j++) {
                MMA_BF16(s[j], qfh[kc], kbh[j]);
                MMA_BF16(s[j], qfh[kc], kbl[j]);
                MMA_BF16(s[j], qfl[kc], kbh[j]);
            }
        }

        // ---- online softmax ----
        float alpha[2];
#pragma unroll
        for (int e = 0; e < 2; e++) {
            float mloc = s[0][2 * e];
#pragma unroll
            for (int j = 0; j < 8; j++) {
                mloc = fmaxf(mloc, s[j][2 * e]);
                mloc = fmaxf(mloc, s[j][2 * e + 1]);
            }
            mloc = fmaxf(mloc, __shfl_xor_sync(0xffffffffu, mloc, 1));
            mloc = fmaxf(mloc, __shfl_xor_sync(0xffffffffu, mloc, 2));
            float mnew = fmaxf(m[e], mloc);
            alpha[e] = __expf(m[e] - mnew);
            float ls = 0.0f;
#pragma unroll
            for (int j = 0; j < 8; j++) {
                float p0 = __expf(s[j][2 * e]     - mnew);
                float p1 = __expf(s[j][2 * e + 1] - mnew);
                s[j][2 * e]     = p0;
                s[j][2 * e + 1] = p1;
                ls += p0 + p1;
            }
            ls += __shfl_xor_sync(0xffffffffu, ls, 1);
            ls += __shfl_xor_sync(0xffffffffu, ls, 2);
            l[e] = l[e] * alpha[e] + ls;
            m[e] = mnew;
        }
#pragma unroll
        for (int j = 0; j < 8; j++) {
            o[j][0] *= alpha[0]; o[j][1] *= alpha[0];
            o[j][2] *= alpha[1]; o[j][3] *= alpha[1];
        }

        // ---- P fragments (hi/lo) from S C-fragments ----
        uint32_t pah[4][4], pal[4][4];
#pragma unroll
        for (int kc = 0; kc < 4; kc++) {
            split2(s[2*kc][0],   s[2*kc][1],   pah[kc][0], pal[kc][0]);
            split2(s[2*kc][2],   s[2*kc][3],   pah[kc][1], pal[kc][1]);
            split2(s[2*kc+1][0], s[2*kc+1][1], pah[kc][2], pal[kc][2]);
            split2(s[2*kc+1][2], s[2*kc+1][3], pah[kc][3], pal[kc][3]);
        }

        // ---- O += P @ V (3-term split) ----
#pragma unroll
        for (int kc = 0; kc < 4; kc++) {
            uint32_t vbh[8][2], vbl[8][2];
#pragma unroll
            for (int jj = 0; jj < 4; jj++) {
                uint32_t a = s_u32(&sVh[(kc * 16 + vrow) * ATS + 16 * jj + vcol]);
                LDSM4T(vbh[2*jj][0], vbh[2*jj][1], vbh[2*jj+1][0], vbh[2*jj+1][1], a);
                a = s_u32(&sVl[(kc * 16 + vrow) * ATS + 16 * jj + vcol]);
                LDSM4T(vbl[2*jj][0], vbl[2*jj][1], vbl[2*jj+1][0], vbl[2*jj+1][1], a);
            }
#pragma unroll
            for (int j = 0; j < 8; j++) {
                MMA_BF16(o[j], pah[kc], vbh[j]);
                MMA_BF16(o[j], pah[kc], vbl[j]);
                MMA_BF16(o[j], pal[kc], vbh[j]);
            }
        }
    }

    // ---- epilogue: normalize and write split bf16 O ----
    const int r0 = q0 + 16 * wrp + g;
    const float inv0 = 1.0f / l[0];
    const float inv1 = 1.0f / l[1];
#pragma unroll
    for (int j = 0; j < 8; j++) {
        int col = h * DKH + 8 * j + 2 * t;
        size_t i0 = (size_t)b * SEQ * D_MODEL + (size_t)r0 * D_MODEL + col;
        size_t i1 = i0 + (size_t)8 * D_MODEL;
        uint32_t hi, lo;
        split2(o[j][0] * inv0, o[j][1] * inv0, hi, lo);
        *(uint32_t*)&Oh[i0] = hi;
        *(uint32_t*)&Ol[i0] = lo;
        split2(o[j][2] * inv1, o[j][3] * inv1, hi, lo);
        *(uint32_t*)&Oh[i1] = hi;
        *(uint32_t*)&Ol[i1] = lo;
    }
}

// ============================================================================
// Launch
// ============================================================================
extern "C" void kernel_launch(void* const* d_in, const int* in_sizes, int n_in,
                              void* d_out, int out_size)
{
    (void)in_sizes; (void)n_in; (void)out_size;
    const float* x  = (const float*)d_in[0];
    const float* wq = (const float*)d_in[1];
    const float* bq = (const float*)d_in[2];
    const float* wk = (const float*)d_in[3];
    const float* bk = (const float*)d_in[4];
    const float* wv = (const float*)d_in[5];
    const float* bv = (const float*)d_in[6];
    const float* wo = (const float*)d_in[7];
    const float* bo = (const float*)d_in[8];
    float* out = (float*)d_out;

    float *Qp, *Kp, *Vp;
    __nv_bfloat16 *Xh, *Xl, *Ohp, *Olp, *Wh, *Wl;
    __nv_bfloat16 *Qhp, *Qlp, *Khp, *Klp, *Vhp, *Vlp;
    cudaGetSymbolAddress((void**)&Qp, g_Q);
    cudaGetSymbolAddress((void**)&Kp, g_K);
    cudaGetSymbolAddress((void**)&Vp, g_V);
    cudaGetSymbolAddress((void**)&Xh, g_Xh);
    cudaGetSymbolAddress((void**)&Xl, g_Xl);
    cudaGetSymbolAddress((void**)&Ohp, g_Oh);
    cudaGetSymbolAddress((void**)&Olp, g_Ol);
    cudaGetSymbolAddress((void**)&Wh, g_Wh);
    cudaGetSymbolAddress((void**)&Wl, g_Wl);
    cudaGetSymbolAddress((void**)&Qhp, g_Qh);
    cudaGetSymbolAddress((void**)&Qlp, g_Ql);
    cudaGetSymbolAddress((void**)&Khp, g_Kh);
    cudaGetSymbolAddress((void**)&Klp, g_Kl);
    cudaGetSymbolAddress((void**)&Vhp, g_Vh);
    cudaGetSymbolAddress((void**)&Vlp, g_Vl);

    cudaFuncSetAttribute(attention_mma,
                         cudaFuncAttributeMaxDynamicSharedMemorySize, ATT_SMEM);
    cudaFuncSetAttribute(gemm_qkv,
                         cudaFuncAttributeMaxDynamicSharedMemorySize, GEMM_SMEM);
    cudaFuncSetAttribute(gemm_one,
                         cudaFuncAttributeMaxDynamicSharedMemorySize, GEMM_SMEM);

    const size_t WSZ = (size_t)D_MODEL * D_MODEL;

    // --- split conversions ---
    int n4x = (MROWS * D_MODEL) / 4;
    int n4w = (int)(WSZ / 4);
    convert_split4<<<(n4x + 255) / 256, 256>>>((const float4*)x, (uint2*)Xh, (uint2*)Xl, n4x);
    dim3 wgrid((n4w + 255) / 256, 4);
    convert_weights4<<<wgrid, 256>>>((const float4*)wq, (const float4*)wk,
                                     (const float4*)wv, (const float4*)wo,
                                     (uint2*)Wh, (uint2*)Wl, n4w);

    // --- fused QKV projections ---
    dim3 qkvgrid(D_MODEL / 128, MROWS / 128, 3);   // (8, 32, 3)
    gemm_qkv<<<qkvgrid, 256, GEMM_SMEM>>>(Xh, Xl, Wh, Wl, bq, bk, bv, Qp, Kp, Vp);

    // --- fused RoPE + split (Q,K); split V ---
    int rope_threads = BATCH * SEQ * NUM_HEADS * (DKH / 2);
    rope_split<<<rope_threads / 256, 256>>>(Qp, Kp, Qhp, Qlp, Khp, Klp);
    convert_split4<<<(n4x + 255) / 256, 256>>>((const float4*)Vp, (uint2*)Vhp, (uint2*)Vlp, n4x);

    // --- tensor-core flash attention ---
    dim3 agrid(SEQ / 128, BATCH * NUM_HEADS);      // (16, 32)
    attention_mma<<<agrid, 256, ATT_SMEM>>>(Qhp, Qlp, Khp, Klp, Vhp, Vlp, Ohp, Olp);

    // --- output projection ---
    dim3 ogrid(D_MODEL / 128, MROWS / 128);        // (8, 32)
    gemm_one<<<ogrid, 256, GEMM_SMEM>>>(Ohp, Olp, Wh + 3 * WSZ, Wl + 3 * WSZ, bo, out);
}

// round 10
// speedup vs baseline: 3.5555x; 1.0973x over previous
#include <cuda_runtime.h>
#include <cuda_bf16.h>
#include <math.h>
#include <stdint.h>

#define D_MODEL   1024
#define NUM_HEADS 16
#define DKH       64
#define BATCH     2
#define SEQ       2048
#define MROWS     (BATCH * SEQ)   // 4096

// ---------------- scratch (device globals; no allocation allowed) ----------
__device__ __nv_bfloat16 g_Xh[MROWS * D_MODEL];
__device__ __nv_bfloat16 g_Xl[MROWS * D_MODEL];
__device__ __nv_bfloat16 g_Oh[MROWS * D_MODEL];
__device__ __nv_bfloat16 g_Ol[MROWS * D_MODEL];
__device__ __nv_bfloat16 g_Wh[4 * D_MODEL * D_MODEL];
__device__ __nv_bfloat16 g_Wl[4 * D_MODEL * D_MODEL];

__device__ __nv_bfloat16 g_Qh[MROWS * D_MODEL];
__device__ __nv_bfloat16 g_Ql[MROWS * D_MODEL];
__device__ __nv_bfloat16 g_Kh[MROWS * D_MODEL];
__device__ __nv_bfloat16 g_Kl[MROWS * D_MODEL];
__device__ __nv_bfloat16 g_Vh[MROWS * D_MODEL];
__device__ __nv_bfloat16 g_Vl[MROWS * D_MODEL];

// ---------------- helpers ---------------------------------------------------
__device__ __forceinline__ uint32_t s_u32(const void* p) {
    return (uint32_t)__cvta_generic_to_shared(p);
}

#define LDSM4(r0, r1, r2, r3, a)                                              \
    asm volatile("ldmatrix.sync.aligned.m8n8.x4.shared.b16 {%0,%1,%2,%3},[%4];"\
        : "=r"(r0), "=r"(r1), "=r"(r2), "=r"(r3) : "r"(a))

#define LDSM4T(r0, r1, r2, r3, a)                                             \
    asm volatile("ldmatrix.sync.aligned.m8n8.x4.trans.shared.b16 {%0,%1,%2,%3},[%4];"\
        : "=r"(r0), "=r"(r1), "=r"(r2), "=r"(r3) : "r"(a))

#define MMA_BF16(c, a, b)                                                     \
    asm("mma.sync.aligned.m16n8k16.row.col.f32.bf16.bf16.f32 "                \
        "{%0,%1,%2,%3}, {%4,%5,%6,%7}, {%8,%9}, {%0,%1,%2,%3};"               \
        : "+f"((c)[0]), "+f"((c)[1]), "+f"((c)[2]), "+f"((c)[3])              \
        : "r"((a)[0]), "r"((a)[1]), "r"((a)[2]), "r"((a)[3]),                 \
          "r"((b)[0]), "r"((b)[1]))

#define CP_ASYNC16(dst, src)                                                  \
    asm volatile("cp.async.cg.shared.global [%0], [%1], 16;"                  \
        :: "r"(dst), "l"(src))
#define CP_COMMIT   asm volatile("cp.async.commit_group;")
#define CP_WAIT1    asm volatile("cp.async.wait_group 1;")
#define CP_WAIT0    asm volatile("cp.async.wait_group 0;")

__device__ __forceinline__ void split2(float a, float b, uint32_t& hi, uint32_t& lo) {
    __nv_bfloat162 h, l;
    h.x = __float2bfloat16_rn(a);
    h.y = __float2bfloat16_rn(b);
    l.x = __float2bfloat16_rn(a - __bfloat162float(h.x));
    l.y = __float2bfloat16_rn(b - __bfloat162float(h.y));
    hi = *reinterpret_cast<uint32_t*>(&h);
    lo = *reinterpret_cast<uint32_t*>(&l);
}

// ============================================================================
// fp32 -> bf16 hi/lo split converters
// ============================================================================
__global__ void convert_split4(const float4* __restrict__ src,
                               uint2* __restrict__ hi, uint2* __restrict__ lo,
                               int n4)
{
    int i = blockIdx.x * blockDim.x + threadIdx.x;
    if (i >= n4) return;
    float4 v = src[i];
    uint2 ho, loo;
    split2(v.x, v.y, ho.x, loo.x);
    split2(v.z, v.w, ho.y, loo.y);
    hi[i] = ho;
    lo[i] = loo;
}

__global__ void convert_weights4(const float4* __restrict__ w0,
                                 const float4* __restrict__ w1,
                                 const float4* __restrict__ w2,
                                 const float4* __restrict__ w3,
                                 uint2* __restrict__ Wh, uint2* __restrict__ Wl,
                                 int n4)
{
    int i = blockIdx.x * blockDim.x + threadIdx.x;
    if (i >= n4) return;
    int z = blockIdx.y;
    const float4* src = (z == 0) ? w0 : (z == 1) ? w1 : (z == 2) ? w2 : w3;
    float4 v = src[i];
    uint2 ho, loo;
    split2(v.x, v.y, ho.x, loo.x);
    split2(v.z, v.w, ho.y, loo.y);
    Wh[(size_t)z * n4 + i] = ho;
    Wl[(size_t)z * n4 + i] = loo;
}

// ============================================================================
// mma.sync GEMM: 128x128 tile, BK=32, 8 warps, cp.async double buffer.
// mode 0: C = acc + bias (fp32 out)
// mode 1: RoPE(acc+bias)*0.125 -> split bf16 (Q)
// mode 2: RoPE(acc+bias)       -> split bf16 (K)
// mode 3: (acc+bias)           -> split bf16 (V)
// ============================================================================
#define GSTR    40                 // smem row stride (bf16): 32 data + 8 pad
#define G_ARR   (128 * GSTR)
#define G_STAGE (4 * G_ARR)
#define GEMM_SMEM (2 * G_STAGE * 2)  // 81920 bytes

__device__ __forceinline__ void gemm_prefetch(
    __nv_bfloat16* st,
    const __nv_bfloat16* __restrict__ Ah, const __nv_bfloat16* __restrict__ Al,
    const __nv_bfloat16* __restrict__ Wh, const __nv_bfloat16* __restrict__ Wl,
    int rowBase, int colBase, int kt, int tid)
{
#pragma unroll
    for (int p = 0; p < 2; p++) {
        int id = tid + p * 256;
        int r  = id >> 2;
        int q  = (id & 3) * 8;
        int so = r * GSTR + q;
        size_t ga = (size_t)(rowBase + r) * D_MODEL + kt + q;
        size_t gw = (size_t)(colBase + r) * D_MODEL + kt + q;
        CP_ASYNC16(s_u32(st + so),             Ah + ga);
        CP_ASYNC16(s_u32(st + G_ARR + so),     Al + ga);
        CP_ASYNC16(s_u32(st + 2 * G_ARR + so), Wh + gw);
        CP_ASYNC16(s_u32(st + 3 * G_ARR + so), Wl + gw);
    }
}

__device__ __forceinline__ void gemm_body(
    const __nv_bfloat16* __restrict__ Ah, const __nv_bfloat16* __restrict__ Al,
    const __nv_bfloat16* __restrict__ Wh, const __nv_bfloat16* __restrict__ Wl,
    const float* __restrict__ bias, float* __restrict__ C,
    __nv_bfloat16* __restrict__ Dh, __nv_bfloat16* __restrict__ Dl,
    int mode, __nv_bfloat16* sm)
{
    const int tid  = threadIdx.x;
    const int lane = tid & 31;
    const int wrp  = tid >> 5;
    const int g    = lane >> 2;
    const int t    = lane & 3;
    const int wm   = (wrp & 1) * 64;
    const int wn   = (wrp >> 1) * 32;
    const int rowBase = blockIdx.y * 128;
    const int colBase = blockIdx.x * 128;

    const int arow = (lane & 15);
    const int akoA = ((lane >> 4) << 3);
    const int brow = ((lane >> 4) << 3) + (lane & 7);
    const int bkoB = ((lane >> 3) & 1) * 8;

    float c[4][4][4];
#pragma unroll
    for (int i = 0; i < 4; i++)
#pragma unroll
        for (int j = 0; j < 4; j++)
#pragma unroll
            for (int e = 0; e < 4; e++) c[i][j][e] = 0.0f;

    gemm_prefetch(sm, Ah, Al, Wh, Wl, rowBase, colBase, 0, tid);
    CP_COMMIT;

    const int NK = D_MODEL / 32;   // 32
    for (int it = 0; it < NK; it++) {
        __syncthreads();
        if (it + 1 < NK) {
            gemm_prefetch(sm + ((it + 1) & 1) * G_STAGE, Ah, Al, Wh, Wl,
                          rowBase, colBase, (it + 1) * 32, tid);
            CP_COMMIT;
            CP_WAIT1;
        } else {
            CP_WAIT0;
        }
        __syncthreads();

        __nv_bfloat16* st  = sm + (it & 1) * G_STAGE;
        __nv_bfloat16* sAh = st;
        __nv_bfloat16* sAl = st + G_ARR;
        __nv_bfloat16* sWh = st + 2 * G_ARR;
        __nv_bfloat16* sWl = st + 3 * G_ARR;

#pragma unroll
        for (int kk = 0; kk < 2; kk++) {
            uint32_t ah[4][4], al[4][4], bb[4][2];
#pragma unroll
            for (int i = 0; i < 4; i++) {
                uint32_t a = s_u32(&sAh[(wm + 16 * i + arow) * GSTR + kk * 16 + akoA]);
                LDSM4(ah[i][0], ah[i][1], ah[i][2], ah[i][3], a);
                a = s_u32(&sAl[(wm + 16 * i + arow) * GSTR + kk * 16 + akoA]);
                LDSM4(al[i][0], al[i][1], al[i][2], al[i][3], a);
            }
            // hi B fragments
#pragma unroll
            for (int jj = 0; jj < 2; jj++) {
                uint32_t a = s_u32(&sWh[(wn + 16 * jj + brow) * GSTR + kk * 16 + bkoB]);
                LDSM4(bb[2*jj][0], bb[2*jj][1], bb[2*jj+1][0], bb[2*jj+1][1], a);
            }
#pragma unroll
            for (int i = 0; i < 4; i++)          // Ah @ Wh  (16 indep accs)
#pragma unroll
                for (int j = 0; j < 4; j++) MMA_BF16(c[i][j], ah[i], bb[j]);
#pragma unroll
            for (int i = 0; i < 4; i++)          // Al @ Wh
#pragma unroll
                for (int j = 0; j < 4; j++) MMA_BF16(c[i][j], al[i], bb[j]);
            // lo B fragments (reuse regs)
#pragma unroll
            for (int jj = 0; jj < 2; jj++) {
                uint32_t a = s_u32(&sWl[(wn + 16 * jj + brow) * GSTR + kk * 16 + bkoB]);
                LDSM4(bb[2*jj][0], bb[2*jj][1], bb[2*jj+1][0], bb[2*jj+1][1], a);
            }
#pragma unroll
            for (int i = 0; i < 4; i++)          // Ah @ Wl
#pragma unroll
                for (int j = 0; j < 4; j++) MMA_BF16(c[i][j], ah[i], bb[j]);
        }
    }

    // ---- fused epilogue ----
#pragma unroll
    for (int i = 0; i < 4; i++) {
        int row = rowBase + wm + i * 16 + g;
        int s0  = row & (SEQ - 1);
        int s1  = (row + 8) & (SEQ - 1);
#pragma unroll
        for (int j = 0; j < 4; j++) {
            int col = colBase + wn + j * 8 + 2 * t;
            float b0 = bias[col], b1 = bias[col + 1];
            float x0 = c[i][j][0] + b0, x1 = c[i][j][1] + b1;   // row
            float y0 = c[i][j][2] + b0, y1 = c[i][j][3] + b1;   // row+8
            if (mode == 0) {
                *reinterpret_cast<float2*>(&C[(size_t)row * D_MODEL + col]) =
                    make_float2(x0, x1);
                *reinterpret_cast<float2*>(&C[(size_t)(row + 8) * D_MODEL + col]) =
                    make_float2(y0, y1);
            } else {
                if (mode <= 2) {
                    int p = (col & 63) >> 1;
                    float freq = powf(10000.0f, -(float)p * (1.0f / 32.0f));
                    float sn0, cs0, sn1, cs1;
                    sincosf((float)s0 * freq, &sn0, &cs0);
                    sincosf((float)s1 * freq, &sn1, &cs1);
                    float r0a = x0 * cs0 - x1 * sn0;
                    float r0b = x1 * cs0 + x0 * sn0;
                    float r1a = y0 * cs1 - y1 * sn1;
                    float r1b = y1 * cs1 + y0 * sn1;
                    if (mode == 1) {
                        r0a *= 0.125f; r0b *= 0.125f;
                        r1a *= 0.125f; r1b *= 0.125f;
                    }
                    x0 = r0a; x1 = r0b; y0 = r1a; y1 = r1b;
                }
                size_t i0 = (size_t)row * D_MODEL + col;
                size_t i1 = i0 + (size_t)8 * D_MODEL;
                uint32_t hi, lo;
                split2(x0, x1, hi, lo);
                *(uint32_t*)&Dh[i0] = hi;
                *(uint32_t*)&Dl[i0] = lo;
                split2(y0, y1, hi, lo);
                *(uint32_t*)&Dh[i1] = hi;
                *(uint32_t*)&Dl[i1] = lo;
            }
        }
    }
}

// QKV fused: z=0 -> Q (rope+scale+split), z=1 -> K (rope+split), z=2 -> V (split)
__global__ __launch_bounds__(256, 2) void gemm_qkv(
    const __nv_bfloat16* __restrict__ Ah, const __nv_bfloat16* __restrict__ Al,
    const __nv_bfloat16* __restrict__ WhB, const __nv_bfloat16* __restrict__ WlB,
    const float* __restrict__ b0, const float* __restrict__ b1, const float* __restrict__ b2,
    __nv_bfloat16* __restrict__ Qh, __nv_bfloat16* __restrict__ Ql,
    __nv_bfloat16* __restrict__ Kh, __nv_bfloat16* __restrict__ Kl,
    __nv_bfloat16* __restrict__ Vh, __nv_bfloat16* __restrict__ Vl)
{
    extern __shared__ __nv_bfloat16 smg[];
    const int z = blockIdx.z;
    const size_t WSZ = (size_t)D_MODEL * D_MODEL;
    const float* bias = (z == 0) ? b0 : (z == 1) ? b1 : b2;
    __nv_bfloat16* Dh = (z == 0) ? Qh : (z == 1) ? Kh : Vh;
    __nv_bfloat16* Dl = (z == 0) ? Ql : (z == 1) ? Kl : Vl;
    gemm_body(Ah, Al, WhB + z * WSZ, WlB + z * WSZ, bias,
              (float*)0, Dh, Dl, z + 1, smg);
}

__global__ __launch_bounds__(256, 2) void gemm_out(
    const __nv_bfloat16* __restrict__ Ah, const __nv_bfloat16* __restrict__ Al,
    const __nv_bfloat16* __restrict__ Wh, const __nv_bfloat16* __restrict__ Wl,
    const float* __restrict__ bias, float* __restrict__ C)
{
    extern __shared__ __nv_bfloat16 smg[];
    gemm_body(Ah, Al, Wh, Wl, bias, C, (__nv_bfloat16*)0, (__nv_bfloat16*)0, 0, smg);
}

// ============================================================================
// Tensor-core flash attention; Q fragments from gmem, KV double-buffered,
// occupancy 2.
// ============================================================================
#define ATS     72
#define A_ARR   (64 * ATS)
#define A_STAGE (4 * A_ARR)
#define ATT_SMEM (2 * A_STAGE * 2)   // 73728 bytes

__device__ __forceinline__ void att_prefetch(
    __nv_bfloat16* st,
    const __nv_bfloat16* __restrict__ Kh, const __nv_bfloat16* __restrict__ Kl,
    const __nv_bfloat16* __restrict__ Vh, const __nv_bfloat16* __restrict__ Vl,
    size_t gbase, int kv0, int tid)
{
#pragma unroll
    for (int p = 0; p < 2; p++) {
        int idx = tid + p * 256;
        int r   = idx >> 3;
        int cq  = (idx & 7) * 8;
        int so  = r * ATS + cq;
        size_t gk = gbase + (size_t)(kv0 + r) * D_MODEL + cq;
        CP_ASYNC16(s_u32(st + so),             Kh + gk);
        CP_ASYNC16(s_u32(st + A_ARR + so),     Kl + gk);
        CP_ASYNC16(s_u32(st + 2 * A_ARR + so), Vh + gk);
        CP_ASYNC16(s_u32(st + 3 * A_ARR + so), Vl + gk);
    }
}

__global__ __launch_bounds__(256, 2) void attention_mma(
    const __nv_bfloat16* __restrict__ Qh, const __nv_bfloat16* __restrict__ Ql,
    const __nv_bfloat16* __restrict__ Kh, const __nv_bfloat16* __restrict__ Kl,
    const __nv_bfloat16* __restrict__ Vh, const __nv_bfloat16* __restrict__ Vl,
    __nv_bfloat16* __restrict__ Oh, __nv_bfloat16* __restrict__ Ol)
{
    extern __shared__ __nv_bfloat16 sKV[];   // 2 stages of {Kh,Kl,Vh,Vl}

    const int bh = blockIdx.y;
    const int b  = bh >> 4;
    const int h  = bh & 15;
    const int q0 = blockIdx.x * 128;
    const int tid  = threadIdx.x;
    const int lane = tid & 31;
    const int wrp  = tid >> 5;
    const int g    = lane >> 2;
    const int t    = lane & 3;

    const size_t gbase = (size_t)b * SEQ * D_MODEL + (size_t)h * DKH;

    att_prefetch(sKV, Kh, Kl, Vh, Vl, gbase, 0, tid);
    CP_COMMIT;

    // ---- Q fragments directly from gmem (A-frag layout) ----
    uint32_t qfh[4][4], qfl[4][4];
    {
        const int r0 = q0 + 16 * wrp + g;
        size_t ro0 = gbase + (size_t)r0 * D_MODEL;
        size_t ro8 = ro0 + (size_t)8 * D_MODEL;
#pragma unroll
        for (int kc = 0; kc < 4; kc++) {
            int cw = kc * 16 + 2 * t;
            qfh[kc][0] = *(const uint32_t*)&Qh[ro0 + cw];
            qfh[kc][1] = *(const uint32_t*)&Qh[ro8 + cw];
            qfh[kc][2] = *(const uint32_t*)&Qh[ro0 + cw + 8];
            qfh[kc][3] = *(const uint32_t*)&Qh[ro8 + cw + 8];
            qfl[kc][0] = *(const uint32_t*)&Ql[ro0 + cw];
            qfl[kc][1] = *(const uint32_t*)&Ql[ro8 + cw];
            qfl[kc][2] = *(const uint32_t*)&Ql[ro0 + cw + 8];
            qfl[kc][3] = *(const uint32_t*)&Ql[ro8 + cw + 8];
        }
    }

    float m[2] = {-INFINITY, -INFINITY};
    float l[2] = {0.0f, 0.0f};
    float o[8][4];
#pragma unroll
    for (int j = 0; j < 8; j++)
#pragma unroll
        for (int e = 0; e < 4; e++) o[j][e] = 0.0f;

    const int brow  = ((lane >> 4) << 3) + (lane & 7);
    const int bko   = ((lane >> 3) & 1) * 8;
    const int vrow  = (lane & 7) + ((lane >> 3) & 1) * 8;
    const int vcol  = ((lane >> 4) << 3);

    const int NT = SEQ / 64;
    for (int it = 0; it < NT; it++) {
        __syncthreads();
        if (it + 1 < NT) {
            att_prefetch(sKV + ((it + 1) & 1) * A_STAGE, Kh, Kl, Vh, Vl,
                         gbase, (it + 1) * 64, tid);
            CP_COMMIT;
            CP_WAIT1;
        } else {
            CP_WAIT0;
        }
        __syncthreads();

        __nv_bfloat16* st  = sKV + (it & 1) * A_STAGE;
        __nv_bfloat16* sKh = st;
        __nv_bfloat16* sKl = st + A_ARR;
        __nv_bfloat16* sVh = st + 2 * A_ARR;
        __nv_bfloat16* sVl = st + 3 * A_ARR;

        // ---- S = Q @ K^T (3-term split), term-major to break RAW chains ----
        float s[8][4];
#pragma unroll
        for (int j = 0; j < 8; j++)
#pragma unroll
            for (int e = 0; e < 4; e++) s[j][e] = 0.0f;

#pragma unroll
        for (int kc = 0; kc < 4; kc++) {
            uint32_t kb[8][2];
#pragma unroll
            for (int jj = 0; jj < 4; jj++) {
                uint32_t a = s_u32(&sKh[(16 * jj + brow) * ATS + kc * 16 + bko]);
                LDSM4(kb[2*jj][0], kb[2*jj][1], kb[2*jj+1][0], kb[2*jj+1][1], a);
            }
#pragma unroll
            for (int j = 0; j < 8; j++) MMA_BF16(s[j], qfh[kc], kb[j]);
#pragma unroll
            for (int j = 0; j < 8; j++) MMA_BF16(s[j], qfl[kc], kb[j]);
#pragma unroll
            for (int jj = 0; jj < 4; jj++) {
                uint32_t a = s_u32(&sKl[(16 * jj + brow) * ATS + kc * 16 + bko]);
                LDSM4(kb[2*jj][0], kb[2*jj][1], kb[2*jj+1][0], kb[2*jj+1][1], a);
            }
#pragma unroll
            for (int j = 0; j < 8; j++) MMA_BF16(s[j], qfh[kc], kb[j]);
        }

        // ---- online softmax ----
        float alpha[2];
#pragma unroll
        for (int e = 0; e < 2; e++) {
            float mloc = s[0][2 * e];
#pragma unroll
            for (int j = 0; j < 8; j++) {
                mloc = fmaxf(mloc, s[j][2 * e]);
                mloc = fmaxf(mloc, s[j][2 * e + 1]);
            }
            mloc = fmaxf(mloc, __shfl_xor_sync(0xffffffffu, mloc, 1));
            mloc = fmaxf(mloc, __shfl_xor_sync(0xffffffffu, mloc, 2));
            float mnew = fmaxf(m[e], mloc);
            alpha[e] = __expf(m[e] - mnew);
            float ls = 0.0f;
#pragma unroll
            for (int j = 0; j < 8; j++) {
                float p0 = __expf(s[j][2 * e]     - mnew);
                float p1 = __expf(s[j][2 * e + 1] - mnew);
                s[j][2 * e]     = p0;
                s[j][2 * e + 1] = p1;
                ls += p0 + p1;
            }
            ls += __shfl_xor_sync(0xffffffffu, ls, 1);
            ls += __shfl_xor_sync(0xffffffffu, ls, 2);
            l[e] = l[e] * alpha[e] + ls;
            m[e] = mnew;
        }
#pragma unroll
        for (int j = 0; j < 8; j++) {
            o[j][0] *= alpha[0]; o[j][1] *= alpha[0];
            o[j][2] *= alpha[1]; o[j][3] *= alpha[1];
        }

        // ---- P fragments (hi/lo) from S C-fragments ----
        uint32_t pah[4][4], pal[4][4];
#pragma unroll
        for (int kc = 0; kc < 4; kc++) {
            split2(s[2*kc][0],   s[2*kc][1],   pah[kc][0], pal[kc][0]);
            split2(s[2*kc][2],   s[2*kc][3],   pah[kc][1], pal[kc][1]);
            split2(s[2*kc+1][0], s[2*kc+1][1], pah[kc][2], pal[kc][2]);
            split2(s[2*kc+1][2], s[2*kc+1][3], pah[kc][3], pal[kc][3]);
        }

        // ---- O += P @ V (3-term split), term-major ----
#pragma unroll
        for (int kc = 0; kc < 4; kc++) {
            uint32_t vb[8][2];
#pragma unroll
            for (int jj = 0; jj < 4; jj++) {
                uint32_t a = s_u32(&sVh[(kc * 16 + vrow) * ATS + 16 * jj + vcol]);
                LDSM4T(vb[2*jj][0], vb[2*jj][1], vb[2*jj+1][0], vb[2*jj+1][1], a);
            }
#pragma unroll
            for (int j = 0; j < 8; j++) MMA_BF16(o[j], pah[kc], vb[j]);
#pragma unroll
            for (int j = 0; j < 8; j++) MMA_BF16(o[j], pal[kc], vb[j]);
#pragma unroll
            for (int jj = 0; jj < 4; jj++) {
                uint32_t a = s_u32(&sVl[(kc * 16 + vrow) * ATS + 16 * jj + vcol]);
                LDSM4T(vb[2*jj][0], vb[2*jj][1], vb[2*jj+1][0], vb[2*jj+1][1], a);
            }
#pragma unroll
            for (int j = 0; j < 8; j++) MMA_BF16(o[j], pah[kc], vb[j]);
        }
    }

    // ---- epilogue: normalize and write split bf16 O ----
    const int r0 = q0 + 16 * wrp + g;
    const float inv0 = 1.0f / l[0];
    const float inv1 = 1.0f / l[1];
#pragma unroll
    for (int j = 0; j < 8; j++) {
        int col = h * DKH + 8 * j + 2 * t;
        size_t i0 = (size_t)b * SEQ * D_MODEL + (size_t)r0 * D_MODEL + col;
        size_t i1 = i0 + (size_t)8 * D_MODEL;
        uint32_t hi, lo;
        split2(o[j][0] * inv0, o[j][1] * inv0, hi, lo);
        *(uint32_t*)&Oh[i0] = hi;
        *(uint32_t*)&Ol[i0] = lo;
        split2(o[j][2] * inv1, o[j][3] * inv1, hi, lo);
        *(uint32_t*)&Oh[i1] = hi;
        *(uint32_t*)&Ol[i1] = lo;
    }
}

// ============================================================================
// Launch
// ============================================================================
extern "C" void kernel_launch(void* const* d_in, const int* in_sizes, int n_in,
                              void* d_out, int out_size)
{
    (void)in_sizes; (void)n_in; (void)out_size;
    const float* x  = (const float*)d_in[0];
    const float* wq = (const float*)d_in[1];
    const float* bq = (const float*)d_in[2];
    const float* wk = (const float*)d_in[3];
    const float* bk = (const float*)d_in[4];
    const float* wv = (const float*)d_in[5];
    const float* bv = (const float*)d_in[6];
    const float* wo = (const float*)d_in[7];
    const float* bo = (const float*)d_in[8];
    float* out = (float*)d_out;

    __nv_bfloat16 *Xh, *Xl, *Ohp, *Olp, *Wh, *Wl;
    __nv_bfloat16 *Qhp, *Qlp, *Khp, *Klp, *Vhp, *Vlp;
    cudaGetSymbolAddress((void**)&Xh, g_Xh);
    cudaGetSymbolAddress((void**)&Xl, g_Xl);
    cudaGetSymbolAddress((void**)&Ohp, g_Oh);
    cudaGetSymbolAddress((void**)&Olp, g_Ol);
    cudaGetSymbolAddress((void**)&Wh, g_Wh);
    cudaGetSymbolAddress((void**)&Wl, g_Wl);
    cudaGetSymbolAddress((void**)&Qhp, g_Qh);
    cudaGetSymbolAddress((void**)&Qlp, g_Ql);
    cudaGetSymbolAddress((void**)&Khp, g_Kh);
    cudaGetSymbolAddress((void**)&Klp, g_Kl);
    cudaGetSymbolAddress((void**)&Vhp, g_Vh);
    cudaGetSymbolAddress((void**)&Vlp, g_Vl);

    cudaFuncSetAttribute(attention_mma,
                         cudaFuncAttributeMaxDynamicSharedMemorySize, ATT_SMEM);
    cudaFuncSetAttribute(gemm_qkv,
                         cudaFuncAttributeMaxDynamicSharedMemorySize, GEMM_SMEM);
    cudaFuncSetAttribute(gemm_out,
                         cudaFuncAttributeMaxDynamicSharedMemorySize, GEMM_SMEM);

    const size_t WSZ = (size_t)D_MODEL * D_MODEL;

    int n4x = (MROWS * D_MODEL) / 4;
    int n4w = (int)(WSZ / 4);
    convert_split4<<<(n4x + 255) / 256, 256>>>((const float4*)x, (uint2*)Xh, (uint2*)Xl, n4x);
    dim3 wgrid((n4w + 255) / 256, 4);
    convert_weights4<<<wgrid, 256>>>((const float4*)wq, (const float4*)wk,
                                     (const float4*)wv, (const float4*)wo,
                                     (uint2*)Wh, (uint2*)Wl, n4w);

    // fused QKV projections with RoPE/scale/split epilogue
    dim3 qkvgrid(D_MODEL / 128, MROWS / 128, 3);   // (8, 32, 3)
    gemm_qkv<<<qkvgrid, 256, GEMM_SMEM>>>(Xh, Xl, Wh, Wl, bq, bk, bv,
                                          Qhp, Qlp, Khp, Klp, Vhp, Vlp);

    // tensor-core flash attention
    dim3 agrid(SEQ / 128, BATCH * NUM_HEADS);      // (16, 32)
    attention_mma<<<agrid, 256, ATT_SMEM>>>(Qhp, Qlp, Khp, Klp, Vhp, Vlp, Ohp, Olp);

    // output projection
    dim3 ogrid(D_MODEL / 128, MROWS / 128);        // (8, 32)
    gemm_out<<<ogrid, 256, GEMM_SMEM>>>(Ohp, Olp, Wh + 3 * WSZ, Wl + 3 * WSZ, bo, out);
}

// round 11
// speedup vs baseline: 3.9026x; 1.0976x over previous
#include <cuda_runtime.h>
#include <cuda_bf16.h>
#include <cuda_fp16.h>
#include <math.h>
#include <stdint.h>

#define D_MODEL   1024
#define NUM_HEADS 16
#define DKH       64
#define BATCH     2
#define SEQ       2048
#define MROWS     (BATCH * SEQ)   // 4096

// Q pre-scale: 1/sqrt(dk) * log2(e)  (softmax runs in exp2 domain)
#define QSCALE (0.125f * 1.44269504f)

// ---------------- scratch (device globals; no allocation allowed) ----------
__device__ __nv_bfloat16 g_Xh[MROWS * D_MODEL];
__device__ __nv_bfloat16 g_Xl[MROWS * D_MODEL];
__device__ __nv_bfloat16 g_Oh[MROWS * D_MODEL];
__device__ __nv_bfloat16 g_Ol[MROWS * D_MODEL];
__device__ __nv_bfloat16 g_Wh[4 * D_MODEL * D_MODEL];
__device__ __nv_bfloat16 g_Wl[4 * D_MODEL * D_MODEL];

__device__ __nv_bfloat16 g_Qh[MROWS * D_MODEL];
__device__ __nv_bfloat16 g_Ql[MROWS * D_MODEL];
__device__ __nv_bfloat16 g_Kh[MROWS * D_MODEL];
__device__ __nv_bfloat16 g_Kl[MROWS * D_MODEL];
__device__ __nv_bfloat16 g_Vh[MROWS * D_MODEL];   // holds fp16 bits
__device__ __nv_bfloat16 g_Vl[MROWS * D_MODEL];   // holds fp16 bits

// ---------------- helpers ---------------------------------------------------
__device__ __forceinline__ uint32_t s_u32(const void* p) {
    return (uint32_t)__cvta_generic_to_shared(p);
}

#define LDSM4(r0, r1, r2, r3, a)                                              \
    asm volatile("ldmatrix.sync.aligned.m8n8.x4.shared.b16 {%0,%1,%2,%3},[%4];"\
        : "=r"(r0), "=r"(r1), "=r"(r2), "=r"(r3) : "r"(a))

#define LDSM4T(r0, r1, r2, r3, a)                                             \
    asm volatile("ldmatrix.sync.aligned.m8n8.x4.trans.shared.b16 {%0,%1,%2,%3},[%4];"\
        : "=r"(r0), "=r"(r1), "=r"(r2), "=r"(r3) : "r"(a))

#define MMA_BF16(c, a, b)                                                     \
    asm("mma.sync.aligned.m16n8k16.row.col.f32.bf16.bf16.f32 "                \
        "{%0,%1,%2,%3}, {%4,%5,%6,%7}, {%8,%9}, {%0,%1,%2,%3};"               \
        : "+f"((c)[0]), "+f"((c)[1]), "+f"((c)[2]), "+f"((c)[3])              \
        : "r"((a)[0]), "r"((a)[1]), "r"((a)[2]), "r"((a)[3]),                 \
          "r"((b)[0]), "r"((b)[1]))

#define MMA_FP16(c, a, b)                                                     \
    asm("mma.sync.aligned.m16n8k16.row.col.f32.f16.f16.f32 "                  \
        "{%0,%1,%2,%3}, {%4,%5,%6,%7}, {%8,%9}, {%0,%1,%2,%3};"               \
        : "+f"((c)[0]), "+f"((c)[1]), "+f"((c)[2]), "+f"((c)[3])              \
        : "r"((a)[0]), "r"((a)[1]), "r"((a)[2]), "r"((a)[3]),                 \
          "r"((b)[0]), "r"((b)[1]))

#define CP_ASYNC16(dst, src)                                                  \
    asm volatile("cp.async.cg.shared.global [%0], [%1], 16;"                  \
        :: "r"(dst), "l"(src))
#define CP_COMMIT   asm volatile("cp.async.commit_group;")
#define CP_WAIT1    asm volatile("cp.async.wait_group 1;")
#define CP_WAIT0    asm volatile("cp.async.wait_group 0;")

__device__ __forceinline__ float ex2f(float x) {
    float r;
    asm("ex2.approx.f32 %0, %1;" : "=f"(r) : "f"(x));
    return r;
}

__device__ __forceinline__ void split2(float a, float b, uint32_t& hi, uint32_t& lo) {
    __nv_bfloat162 h, l;
    h.x = __float2bfloat16_rn(a);
    h.y = __float2bfloat16_rn(b);
    l.x = __float2bfloat16_rn(a - __bfloat162float(h.x));
    l.y = __float2bfloat16_rn(b - __bfloat162float(h.y));
    hi = *reinterpret_cast<uint32_t*>(&h);
    lo = *reinterpret_cast<uint32_t*>(&l);
}

__device__ __forceinline__ void split2h(float a, float b, uint32_t& hi, uint32_t& lo) {
    __half2 h = __floats2half2_rn(a, b);
    float2 f = __half22float2(h);
    __half2 l2 = __floats2half2_rn(a - f.x, b - f.y);
    hi = *reinterpret_cast<uint32_t*>(&h);
    lo = *reinterpret_cast<uint32_t*>(&l2);
}

__device__ __forceinline__ uint32_t f2h2(float a, float b) {
    __half2 h = __floats2half2_rn(a, b);
    return *reinterpret_cast<uint32_t*>(&h);
}

// ============================================================================
// fp32 -> bf16 hi/lo split converters
// ============================================================================
__global__ void convert_split4(const float4* __restrict__ src,
                               uint2* __restrict__ hi, uint2* __restrict__ lo,
                               int n4)
{
    int i = blockIdx.x * blockDim.x + threadIdx.x;
    if (i >= n4) return;
    float4 v = src[i];
    uint2 ho, loo;
    split2(v.x, v.y, ho.x, loo.x);
    split2(v.z, v.w, ho.y, loo.y);
    hi[i] = ho;
    lo[i] = loo;
}

__global__ void convert_weights4(const float4* __restrict__ w0,
                                 const float4* __restrict__ w1,
                                 const float4* __restrict__ w2,
                                 const float4* __restrict__ w3,
                                 uint2* __restrict__ Wh, uint2* __restrict__ Wl,
                                 int n4)
{
    int i = blockIdx.x * blockDim.x + threadIdx.x;
    if (i >= n4) return;
    int z = blockIdx.y;
    const float4* src = (z == 0) ? w0 : (z == 1) ? w1 : (z == 2) ? w2 : w3;
    float4 v = src[i];
    uint2 ho, loo;
    split2(v.x, v.y, ho.x, loo.x);
    split2(v.z, v.w, ho.y, loo.y);
    Wh[(size_t)z * n4 + i] = ho;
    Wl[(size_t)z * n4 + i] = loo;
}

// ============================================================================
// mma.sync GEMM: 128x128 tile, BK=32, 8 warps, cp.async double buffer.
// mode 0: C = acc + bias (fp32 out)
// mode 1: RoPE(acc+bias)*QSCALE -> split bf16 (Q, exp2-domain scale)
// mode 2: RoPE(acc+bias)        -> split bf16 (K)
// mode 3: (acc+bias)            -> split fp16 (V)
// ============================================================================
#define GSTR    40
#define G_ARR   (128 * GSTR)
#define G_STAGE (4 * G_ARR)
#define GEMM_SMEM (2 * G_STAGE * 2)  // 81920 bytes

__device__ __forceinline__ void gemm_prefetch(
    __nv_bfloat16* st,
    const __nv_bfloat16* __restrict__ Ah, const __nv_bfloat16* __restrict__ Al,
    const __nv_bfloat16* __restrict__ Wh, const __nv_bfloat16* __restrict__ Wl,
    int rowBase, int colBase, int kt, int tid)
{
#pragma unroll
    for (int p = 0; p < 2; p++) {
        int id = tid + p * 256;
        int r  = id >> 2;
        int q  = (id & 3) * 8;
        int so = r * GSTR + q;
        size_t ga = (size_t)(rowBase + r) * D_MODEL + kt + q;
        size_t gw = (size_t)(colBase + r) * D_MODEL + kt + q;
        CP_ASYNC16(s_u32(st + so),             Ah + ga);
        CP_ASYNC16(s_u32(st + G_ARR + so),     Al + ga);
        CP_ASYNC16(s_u32(st + 2 * G_ARR + so), Wh + gw);
        CP_ASYNC16(s_u32(st + 3 * G_ARR + so), Wl + gw);
    }
}

__device__ __forceinline__ void gemm_body(
    const __nv_bfloat16* __restrict__ Ah, const __nv_bfloat16* __restrict__ Al,
    const __nv_bfloat16* __restrict__ Wh, const __nv_bfloat16* __restrict__ Wl,
    const float* __restrict__ bias, float* __restrict__ C,
    __nv_bfloat16* __restrict__ Dh, __nv_bfloat16* __restrict__ Dl,
    int mode, __nv_bfloat16* sm)
{
    const int tid  = threadIdx.x;
    const int lane = tid & 31;
    const int wrp  = tid >> 5;
    const int g    = lane >> 2;
    const int t    = lane & 3;
    const int wm   = (wrp & 1) * 64;
    const int wn   = (wrp >> 1) * 32;
    const int rowBase = blockIdx.y * 128;
    const int colBase = blockIdx.x * 128;

    const int arow = (lane & 15);
    const int akoA = ((lane >> 4) << 3);
    const int brow = ((lane >> 4) << 3) + (lane & 7);
    const int bkoB = ((lane >> 3) & 1) * 8;

    float c[4][4][4];
#pragma unroll
    for (int i = 0; i < 4; i++)
#pragma unroll
        for (int j = 0; j < 4; j++)
#pragma unroll
            for (int e = 0; e < 4; e++) c[i][j][e] = 0.0f;

    gemm_prefetch(sm, Ah, Al, Wh, Wl, rowBase, colBase, 0, tid);
    CP_COMMIT;

    const int NK = D_MODEL / 32;
    for (int it = 0; it < NK; it++) {
        __syncthreads();
        if (it + 1 < NK) {
            gemm_prefetch(sm + ((it + 1) & 1) * G_STAGE, Ah, Al, Wh, Wl,
                          rowBase, colBase, (it + 1) * 32, tid);
            CP_COMMIT;
            CP_WAIT1;
        } else {
            CP_WAIT0;
        }
        __syncthreads();

        __nv_bfloat16* st  = sm + (it & 1) * G_STAGE;
        __nv_bfloat16* sAh = st;
        __nv_bfloat16* sAl = st + G_ARR;
        __nv_bfloat16* sWh = st + 2 * G_ARR;
        __nv_bfloat16* sWl = st + 3 * G_ARR;

#pragma unroll
        for (int kk = 0; kk < 2; kk++) {
            uint32_t ah[4][4], al[4][4], bb[4][2];
#pragma unroll
            for (int i = 0; i < 4; i++) {
                uint32_t a = s_u32(&sAh[(wm + 16 * i + arow) * GSTR + kk * 16 + akoA]);
                LDSM4(ah[i][0], ah[i][1], ah[i][2], ah[i][3], a);
                a = s_u32(&sAl[(wm + 16 * i + arow) * GSTR + kk * 16 + akoA]);
                LDSM4(al[i][0], al[i][1], al[i][2], al[i][3], a);
            }
#pragma unroll
            for (int jj = 0; jj < 2; jj++) {
                uint32_t a = s_u32(&sWh[(wn + 16 * jj + brow) * GSTR + kk * 16 + bkoB]);
                LDSM4(bb[2*jj][0], bb[2*jj][1], bb[2*jj+1][0], bb[2*jj+1][1], a);
            }
#pragma unroll
            for (int i = 0; i < 4; i++)
#pragma unroll
                for (int j = 0; j < 4; j++) MMA_BF16(c[i][j], ah[i], bb[j]);
#pragma unroll
            for (int i = 0; i < 4; i++)
#pragma unroll
                for (int j = 0; j < 4; j++) MMA_BF16(c[i][j], al[i], bb[j]);
#pragma unroll
            for (int jj = 0; jj < 2; jj++) {
                uint32_t a = s_u32(&sWl[(wn + 16 * jj + brow) * GSTR + kk * 16 + bkoB]);
                LDSM4(bb[2*jj][0], bb[2*jj][1], bb[2*jj+1][0], bb[2*jj+1][1], a);
            }
#pragma unroll
            for (int i = 0; i < 4; i++)
#pragma unroll
                for (int j = 0; j < 4; j++) MMA_BF16(c[i][j], ah[i], bb[j]);
        }
    }

    // ---- fused epilogue ----
#pragma unroll
    for (int i = 0; i < 4; i++) {
        int row = rowBase + wm + i * 16 + g;
        int s0  = row & (SEQ - 1);
        int s1  = (row + 8) & (SEQ - 1);
#pragma unroll
        for (int j = 0; j < 4; j++) {
            int col = colBase + wn + j * 8 + 2 * t;
            float b0 = bias[col], b1 = bias[col + 1];
            float x0 = c[i][j][0] + b0, x1 = c[i][j][1] + b1;
            float y0 = c[i][j][2] + b0, y1 = c[i][j][3] + b1;
            if (mode == 0) {
                *reinterpret_cast<float2*>(&C[(size_t)row * D_MODEL + col]) =
                    make_float2(x0, x1);
                *reinterpret_cast<float2*>(&C[(size_t)(row + 8) * D_MODEL + col]) =
                    make_float2(y0, y1);
            } else {
                if (mode <= 2) {
                    int p = (col & 63) >> 1;
                    float freq = powf(10000.0f, -(float)p * (1.0f / 32.0f));
                    float sn0, cs0, sn1, cs1;
                    sincosf((float)s0 * freq, &sn0, &cs0);
                    sincosf((float)s1 * freq, &sn1, &cs1);
                    float r0a = x0 * cs0 - x1 * sn0;
                    float r0b = x1 * cs0 + x0 * sn0;
                    float r1a = y0 * cs1 - y1 * sn1;
                    float r1b = y1 * cs1 + y0 * sn1;
                    if (mode == 1) {
                        r0a *= QSCALE; r0b *= QSCALE;
                        r1a *= QSCALE; r1b *= QSCALE;
                    }
                    x0 = r0a; x1 = r0b; y0 = r1a; y1 = r1b;
                }
                size_t i0 = (size_t)row * D_MODEL + col;
                size_t i1 = i0 + (size_t)8 * D_MODEL;
                uint32_t hi, lo;
                if (mode == 3) {
                    split2h(x0, x1, hi, lo);
                    *(uint32_t*)&Dh[i0] = hi;
                    *(uint32_t*)&Dl[i0] = lo;
                    split2h(y0, y1, hi, lo);
                    *(uint32_t*)&Dh[i1] = hi;
                    *(uint32_t*)&Dl[i1] = lo;
                } else {
                    split2(x0, x1, hi, lo);
                    *(uint32_t*)&Dh[i0] = hi;
                    *(uint32_t*)&Dl[i0] = lo;
                    split2(y0, y1, hi, lo);
                    *(uint32_t*)&Dh[i1] = hi;
                    *(uint32_t*)&Dl[i1] = lo;
                }
            }
        }
    }
}

__global__ __launch_bounds__(256, 2) void gemm_qkv(
    const __nv_bfloat16* __restrict__ Ah, const __nv_bfloat16* __restrict__ Al,
    const __nv_bfloat16* __restrict__ WhB, const __nv_bfloat16* __restrict__ WlB,
    const float* __restrict__ b0, const float* __restrict__ b1, const float* __restrict__ b2,
    __nv_bfloat16* __restrict__ Qh, __nv_bfloat16* __restrict__ Ql,
    __nv_bfloat16* __restrict__ Kh, __nv_bfloat16* __restrict__ Kl,
    __nv_bfloat16* __restrict__ Vh, __nv_bfloat16* __restrict__ Vl)
{
    extern __shared__ __nv_bfloat16 smg[];
    const int z = blockIdx.z;
    const size_t WSZ = (size_t)D_MODEL * D_MODEL;
    const float* bias = (z == 0) ? b0 : (z == 1) ? b1 : b2;
    __nv_bfloat16* Dh = (z == 0) ? Qh : (z == 1) ? Kh : Vh;
    __nv_bfloat16* Dl = (z == 0) ? Ql : (z == 1) ? Kl : Vl;
    gemm_body(Ah, Al, WhB + z * WSZ, WlB + z * WSZ, bias,
              (float*)0, Dh, Dl, z + 1, smg);
}

__global__ __launch_bounds__(256, 2) void gemm_out(
    const __nv_bfloat16* __restrict__ Ah, const __nv_bfloat16* __restrict__ Al,
    const __nv_bfloat16* __restrict__ Wh, const __nv_bfloat16* __restrict__ Wl,
    const float* __restrict__ bias, float* __restrict__ C)
{
    extern __shared__ __nv_bfloat16 smg[];
    gemm_body(Ah, Al, Wh, Wl, bias, C, (__nv_bfloat16*)0, (__nv_bfloat16*)0, 0, smg);
}

// ============================================================================
// Tensor-core flash attention: S = 3-term bf16; softmax in exp2 domain;
// PV = fp16 P (single) @ fp16 V (hi/lo) — 2 terms. occupancy 2.
// ============================================================================
#define ATS     72
#define A_ARR   (64 * ATS)
#define A_STAGE (4 * A_ARR)
#define ATT_SMEM (2 * A_STAGE * 2)   // 73728 bytes

__device__ __forceinline__ void att_prefetch(
    __nv_bfloat16* st,
    const __nv_bfloat16* __restrict__ Kh, const __nv_bfloat16* __restrict__ Kl,
    const __nv_bfloat16* __restrict__ Vh, const __nv_bfloat16* __restrict__ Vl,
    size_t gbase, int kv0, int tid)
{
#pragma unroll
    for (int p = 0; p < 2; p++) {
        int idx = tid + p * 256;
        int r   = idx >> 3;
        int cq  = (idx & 7) * 8;
        int so  = r * ATS + cq;
        size_t gk = gbase + (size_t)(kv0 + r) * D_MODEL + cq;
        CP_ASYNC16(s_u32(st + so),             Kh + gk);
        CP_ASYNC16(s_u32(st + A_ARR + so),     Kl + gk);
        CP_ASYNC16(s_u32(st + 2 * A_ARR + so), Vh + gk);
        CP_ASYNC16(s_u32(st + 3 * A_ARR + so), Vl + gk);
    }
}

__global__ __launch_bounds__(256, 2) void attention_mma(
    const __nv_bfloat16* __restrict__ Qh, const __nv_bfloat16* __restrict__ Ql,
    const __nv_bfloat16* __restrict__ Kh, const __nv_bfloat16* __restrict__ Kl,
    const __nv_bfloat16* __restrict__ Vh, const __nv_bfloat16* __restrict__ Vl,
    __nv_bfloat16* __restrict__ Oh, __nv_bfloat16* __restrict__ Ol)
{
    extern __shared__ __nv_bfloat16 sKV[];

    const int bh = blockIdx.y;
    const int b  = bh >> 4;
    const int h  = bh & 15;
    const int q0 = blockIdx.x * 128;
    const int tid  = threadIdx.x;
    const int lane = tid & 31;
    const int wrp  = tid >> 5;
    const int g    = lane >> 2;
    const int t    = lane & 3;

    const size_t gbase = (size_t)b * SEQ * D_MODEL + (size_t)h * DKH;

    att_prefetch(sKV, Kh, Kl, Vh, Vl, gbase, 0, tid);
    CP_COMMIT;

    // ---- Q fragments directly from gmem (A-frag layout) ----
    uint32_t qfh[4][4], qfl[4][4];
    {
        const int r0 = q0 + 16 * wrp + g;
        size_t ro0 = gbase + (size_t)r0 * D_MODEL;
        size_t ro8 = ro0 + (size_t)8 * D_MODEL;
#pragma unroll
        for (int kc = 0; kc < 4; kc++) {
            int cw = kc * 16 + 2 * t;
            qfh[kc][0] = *(const uint32_t*)&Qh[ro0 + cw];
            qfh[kc][1] = *(const uint32_t*)&Qh[ro8 + cw];
            qfh[kc][2] = *(const uint32_t*)&Qh[ro0 + cw + 8];
            qfh[kc][3] = *(const uint32_t*)&Qh[ro8 + cw + 8];
            qfl[kc][0] = *(const uint32_t*)&Ql[ro0 + cw];
            qfl[kc][1] = *(const uint32_t*)&Ql[ro8 + cw];
            qfl[kc][2] = *(const uint32_t*)&Ql[ro0 + cw + 8];
            qfl[kc][3] = *(const uint32_t*)&Ql[ro8 + cw + 8];
        }
    }

    float m[2] = {-INFINITY, -INFINITY};
    float l[2] = {0.0f, 0.0f};     // per-thread partials; quad-reduced at end
    float o[8][4];
#pragma unroll
    for (int j = 0; j < 8; j++)
#pragma unroll
        for (int e = 0; e < 4; e++) o[j][e] = 0.0f;

    const int brow  = ((lane >> 4) << 3) + (lane & 7);
    const int bko   = ((lane >> 3) & 1) * 8;
    const int vrow  = (lane & 7) + ((lane >> 3) & 1) * 8;
    const int vcol  = ((lane >> 4) << 3);

    const int NT = SEQ / 64;
    for (int it = 0; it < NT; it++) {
        __syncthreads();
        if (it + 1 < NT) {
            att_prefetch(sKV + ((it + 1) & 1) * A_STAGE, Kh, Kl, Vh, Vl,
                         gbase, (it + 1) * 64, tid);
            CP_COMMIT;
            CP_WAIT1;
        } else {
            CP_WAIT0;
        }
        __syncthreads();

        __nv_bfloat16* st  = sKV + (it & 1) * A_STAGE;
        __nv_bfloat16* sKh = st;
        __nv_bfloat16* sKl = st + A_ARR;
        __nv_bfloat16* sVh = st + 2 * A_ARR;
        __nv_bfloat16* sVl = st + 3 * A_ARR;

        // ---- S = Q @ K^T (3-term split, term-major) ----
        float s[8][4];
#pragma unroll
        for (int j = 0; j < 8; j++)
#pragma unroll
            for (int e = 0; e < 4; e++) s[j][e] = 0.0f;

#pragma unroll
        for (int kc = 0; kc < 4; kc++) {
            uint32_t kb[8][2];
#pragma unroll
            for (int jj = 0; jj < 4; jj++) {
                uint32_t a = s_u32(&sKh[(16 * jj + brow) * ATS + kc * 16 + bko]);
                LDSM4(kb[2*jj][0], kb[2*jj][1], kb[2*jj+1][0], kb[2*jj+1][1], a);
            }
#pragma unroll
            for (int j = 0; j < 8; j++) MMA_BF16(s[j], qfh[kc], kb[j]);
#pragma unroll
            for (int j = 0; j < 8; j++) MMA_BF16(s[j], qfl[kc], kb[j]);
#pragma unroll
            for (int jj = 0; jj < 4; jj++) {
                uint32_t a = s_u32(&sKl[(16 * jj + brow) * ATS + kc * 16 + bko]);
                LDSM4(kb[2*jj][0], kb[2*jj][1], kb[2*jj+1][0], kb[2*jj+1][1], a);
            }
#pragma unroll
            for (int j = 0; j < 8; j++) MMA_BF16(s[j], qfh[kc], kb[j]);
        }

        // ---- online softmax (exp2 domain, tree reductions, deferred l) ----
        float alpha[2];
#pragma unroll
        for (int e = 0; e < 2; e++) {
            float a0 = fmaxf(s[0][2*e], s[0][2*e+1]);
            float a1 = fmaxf(s[1][2*e], s[1][2*e+1]);
            float a2 = fmaxf(s[2][2*e], s[2][2*e+1]);
            float a3 = fmaxf(s[3][2*e], s[3][2*e+1]);
            float a4 = fmaxf(s[4][2*e], s[4][2*e+1]);
            float a5 = fmaxf(s[5][2*e], s[5][2*e+1]);
            float a6 = fmaxf(s[6][2*e], s[6][2*e+1]);
            float a7 = fmaxf(s[7][2*e], s[7][2*e+1]);
            a0 = fmaxf(a0, a1); a2 = fmaxf(a2, a3);
            a4 = fmaxf(a4, a5); a6 = fmaxf(a6, a7);
            float mloc = fmaxf(fmaxf(a0, a2), fmaxf(a4, a6));
            mloc = fmaxf(mloc, __shfl_xor_sync(0xffffffffu, mloc, 1));
            mloc = fmaxf(mloc, __shfl_xor_sync(0xffffffffu, mloc, 2));
            float mnew = fmaxf(m[e], mloc);
            alpha[e] = ex2f(m[e] - mnew);
            float ls0 = 0.0f, ls1 = 0.0f, ls2 = 0.0f, ls3 = 0.0f;
#pragma unroll
            for (int j = 0; j < 8; j += 2) {
                float p0 = ex2f(s[j][2*e]       - mnew);
                float p1 = ex2f(s[j][2*e+1]     - mnew);
                float p2 = ex2f(s[j+1][2*e]     - mnew);
                float p3 = ex2f(s[j+1][2*e+1]   - mnew);
                s[j][2*e]     = p0; s[j][2*e+1]     = p1;
                s[j+1][2*e]   = p2; s[j+1][2*e+1]   = p3;
                ls0 += p0; ls1 += p1; ls2 += p2; ls3 += p3;
            }
            l[e] = l[e] * alpha[e] + ((ls0 + ls1) + (ls2 + ls3));
            m[e] = mnew;
        }
#pragma unroll
        for (int j = 0; j < 8; j++) {
            o[j][0] *= alpha[0]; o[j][1] *= alpha[0];
            o[j][2] *= alpha[1]; o[j][3] *= alpha[1];
        }

        // ---- P fragments: single fp16 (A-frag layout) ----
        uint32_t pa[4][4];
#pragma unroll
        for (int kc = 0; kc < 4; kc++) {
            pa[kc][0] = f2h2(s[2*kc][0],   s[2*kc][1]);
            pa[kc][1] = f2h2(s[2*kc][2],   s[2*kc][3]);
            pa[kc][2] = f2h2(s[2*kc+1][0], s[2*kc+1][1]);
            pa[kc][3] = f2h2(s[2*kc+1][2], s[2*kc+1][3]);
        }

        // ---- O += P @ (Vh + Vl)  (2 fp16 terms) ----
#pragma unroll
        for (int kc = 0; kc < 4; kc++) {
            uint32_t vb[8][2];
#pragma unroll
            for (int jj = 0; jj < 4; jj++) {
                uint32_t a = s_u32(&sVh[(kc * 16 + vrow) * ATS + 16 * jj + vcol]);
                LDSM4T(vb[2*jj][0], vb[2*jj][1], vb[2*jj+1][0], vb[2*jj+1][1], a);
            }
#pragma unroll
            for (int j = 0; j < 8; j++) MMA_FP16(o[j], pa[kc], vb[j]);
#pragma unroll
            for (int jj = 0; jj < 4; jj++) {
                uint32_t a = s_u32(&sVl[(kc * 16 + vrow) * ATS + 16 * jj + vcol]);
                LDSM4T(vb[2*jj][0], vb[2*jj][1], vb[2*jj+1][0], vb[2*jj+1][1], a);
            }
#pragma unroll
            for (int j = 0; j < 8; j++) MMA_FP16(o[j], pa[kc], vb[j]);
        }
    }

    // ---- epilogue: quad-reduce l, normalize, write split bf16 O ----
    l[0] += __shfl_xor_sync(0xffffffffu, l[0], 1);
    l[0] += __shfl_xor_sync(0xffffffffu, l[0], 2);
    l[1] += __shfl_xor_sync(0xffffffffu, l[1], 1);
    l[1] += __shfl_xor_sync(0xffffffffu, l[1], 2);

    const int r0 = q0 + 16 * wrp + g;
    const float inv0 = 1.0f / l[0];
    const float inv1 = 1.0f / l[1];
#pragma unroll
    for (int j = 0; j < 8; j++) {
        int col = h * DKH + 8 * j + 2 * t;
        size_t i0 = (size_t)b * SEQ * D_MODEL + (size_t)r0 * D_MODEL + col;
        size_t i1 = i0 + (size_t)8 * D_MODEL;
        uint32_t hi, lo;
        split2(o[j][0] * inv0, o[j][1] * inv0, hi, lo);
        *(uint32_t*)&Oh[i0] = hi;
        *(uint32_t*)&Ol[i0] = lo;
        split2(o[j][2] * inv1, o[j][3] * inv1, hi, lo);
        *(uint32_t*)&Oh[i1] = hi;
        *(uint32_t*)&Ol[i1] = lo;
    }
}

// ============================================================================
// Launch
// ============================================================================
extern "C" void kernel_launch(void* const* d_in, const int* in_sizes, int n_in,
                              void* d_out, int out_size)
{
    (void)in_sizes; (void)n_in; (void)out_size;
    const float* x  = (const float*)d_in[0];
    const float* wq = (const float*)d_in[1];
    const float* bq = (const float*)d_in[2];
    const float* wk = (const float*)d_in[3];
    const float* bk = (const float*)d_in[4];
    const float* wv = (const float*)d_in[5];
    const float* bv = (const float*)d_in[6];
    const float* wo = (const float*)d_in[7];
    const float* bo = (const float*)d_in[8];
    float* out = (float*)d_out;

    __nv_bfloat16 *Xh, *Xl, *Ohp, *Olp, *Wh, *Wl;
    __nv_bfloat16 *Qhp, *Qlp, *Khp, *Klp, *Vhp, *Vlp;
    cudaGetSymbolAddress((void**)&Xh, g_Xh);
    cudaGetSymbolAddress((void**)&Xl, g_Xl);
    cudaGetSymbolAddress((void**)&Ohp, g_Oh);
    cudaGetSymbolAddress((void**)&Olp, g_Ol);
    cudaGetSymbolAddress((void**)&Wh, g_Wh);
    cudaGetSymbolAddress((void**)&Wl, g_Wl);
    cudaGetSymbolAddress((void**)&Qhp, g_Qh);
    cudaGetSymbolAddress((void**)&Qlp, g_Ql);
    cudaGetSymbolAddress((void**)&Khp, g_Kh);
    cudaGetSymbolAddress((void**)&Klp, g_Kl);
    cudaGetSymbolAddress((void**)&Vhp, g_Vh);
    cudaGetSymbolAddress((void**)&Vlp, g_Vl);

    cudaFuncSetAttribute(attention_mma,
                         cudaFuncAttributeMaxDynamicSharedMemorySize, ATT_SMEM);
    cudaFuncSetAttribute(gemm_qkv,
                         cudaFuncAttributeMaxDynamicSharedMemorySize, GEMM_SMEM);
    cudaFuncSetAttribute(gemm_out,
                         cudaFuncAttributeMaxDynamicSharedMemorySize, GEMM_SMEM);

    const size_t WSZ = (size_t)D_MODEL * D_MODEL;

    int n4x = (MROWS * D_MODEL) / 4;
    int n4w = (int)(WSZ / 4);
    convert_split4<<<(n4x + 255) / 256, 256>>>((const float4*)x, (uint2*)Xh, (uint2*)Xl, n4x);
    dim3 wgrid((n4w + 255) / 256, 4);
    convert_weights4<<<wgrid, 256>>>((const float4*)wq, (const float4*)wk,
                                     (const float4*)wv, (const float4*)wo,
                                     (uint2*)Wh, (uint2*)Wl, n4w);

    // fused QKV projections (Q: rope+exp2-scale, K: rope, V: fp16 split)
    dim3 qkvgrid(D_MODEL / 128, MROWS / 128, 3);
    gemm_qkv<<<qkvgrid, 256, GEMM_SMEM>>>(Xh, Xl, Wh, Wl, bq, bk, bv,
                                          Qhp, Qlp, Khp, Klp, Vhp, Vlp);

    // tensor-core flash attention
    dim3 agrid(SEQ / 128, BATCH * NUM_HEADS);
    attention_mma<<<agrid, 256, ATT_SMEM>>>(Qhp, Qlp, Khp, Klp, Vhp, Vlp, Ohp, Olp);

    // output projection
    dim3 ogrid(D_MODEL / 128, MROWS / 128);
    gemm_out<<<ogrid, 256, GEMM_SMEM>>>(Ohp, Olp, Wh + 3 * WSZ, Wl + 3 * WSZ, bo, out);
}

// round 12
// speedup vs baseline: 5.1833x; 1.3282x over previous
#include <cuda_runtime.h>
#include <cuda_bf16.h>
#include <cuda_fp16.h>
#include <math.h>
#include <stdint.h>

#define D_MODEL   1024
#define NUM_HEADS 16
#define DKH       64
#define BATCH     2
#define SEQ       2048
#define MROWS     (BATCH * SEQ)   // 4096

// Q pre-scale: 1/sqrt(dk) * log2(e)  (softmax runs in exp2 domain)
#define QSCALE (0.125f * 1.44269504f)

// ---------------- scratch (device globals; no allocation allowed) ----------
__device__ __half          g_X16[MROWS * D_MODEL];
__device__ __half          g_O16[MROWS * D_MODEL];
__device__ __half          g_V16[MROWS * D_MODEL];
__device__ __half          g_W16h[4 * D_MODEL * D_MODEL];
__device__ __half          g_W16l[4 * D_MODEL * D_MODEL];

__device__ __nv_bfloat16 g_Qh[MROWS * D_MODEL];
__device__ __nv_bfloat16 g_Ql[MROWS * D_MODEL];
__device__ __nv_bfloat16 g_Kh[MROWS * D_MODEL];
__device__ __nv_bfloat16 g_Kl[MROWS * D_MODEL];

// ---------------- helpers ---------------------------------------------------
__device__ __forceinline__ uint32_t s_u32(const void* p) {
    return (uint32_t)__cvta_generic_to_shared(p);
}

#define LDSM4(r0, r1, r2, r3, a)                                              \
    asm volatile("ldmatrix.sync.aligned.m8n8.x4.shared.b16 {%0,%1,%2,%3},[%4];"\
        : "=r"(r0), "=r"(r1), "=r"(r2), "=r"(r3) : "r"(a))

#define LDSM4T(r0, r1, r2, r3, a)                                             \
    asm volatile("ldmatrix.sync.aligned.m8n8.x4.trans.shared.b16 {%0,%1,%2,%3},[%4];"\
        : "=r"(r0), "=r"(r1), "=r"(r2), "=r"(r3) : "r"(a))

#define MMA_BF16(c, a, b)                                                     \
    asm("mma.sync.aligned.m16n8k16.row.col.f32.bf16.bf16.f32 "                \
        "{%0,%1,%2,%3}, {%4,%5,%6,%7}, {%8,%9}, {%0,%1,%2,%3};"               \
        : "+f"((c)[0]), "+f"((c)[1]), "+f"((c)[2]), "+f"((c)[3])              \
        : "r"((a)[0]), "r"((a)[1]), "r"((a)[2]), "r"((a)[3]),                 \
          "r"((b)[0]), "r"((b)[1]))

#define MMA_FP16(c, a, b)                                                     \
    asm("mma.sync.aligned.m16n8k16.row.col.f32.f16.f16.f32 "                  \
        "{%0,%1,%2,%3}, {%4,%5,%6,%7}, {%8,%9}, {%0,%1,%2,%3};"               \
        : "+f"((c)[0]), "+f"((c)[1]), "+f"((c)[2]), "+f"((c)[3])              \
        : "r"((a)[0]), "r"((a)[1]), "r"((a)[2]), "r"((a)[3]),                 \
          "r"((b)[0]), "r"((b)[1]))

#define CP_ASYNC16(dst, src)                                                  \
    asm volatile("cp.async.cg.shared.global [%0], [%1], 16;"                  \
        :: "r"(dst), "l"(src))
#define CP_COMMIT   asm volatile("cp.async.commit_group;")
#define CP_WAIT1    asm volatile("cp.async.wait_group 1;")
#define CP_WAIT0    asm volatile("cp.async.wait_group 0;")

__device__ __forceinline__ float ex2f(float x) {
    float r;
    asm("ex2.approx.f32 %0, %1;" : "=f"(r) : "f"(x));
    return r;
}

__device__ __forceinline__ void split2(float a, float b, uint32_t& hi, uint32_t& lo) {
    __nv_bfloat162 h, l;
    h.x = __float2bfloat16_rn(a);
    h.y = __float2bfloat16_rn(b);
    l.x = __float2bfloat16_rn(a - __bfloat162float(h.x));
    l.y = __float2bfloat16_rn(b - __bfloat162float(h.y));
    hi = *reinterpret_cast<uint32_t*>(&h);
    lo = *reinterpret_cast<uint32_t*>(&l);
}

__device__ __forceinline__ void split2h(float a, float b, uint32_t& hi, uint32_t& lo) {
    __half2 h = __floats2half2_rn(a, b);
    float2 f = __half22float2(h);
    __half2 l2 = __floats2half2_rn(a - f.x, b - f.y);
    hi = *reinterpret_cast<uint32_t*>(&h);
    lo = *reinterpret_cast<uint32_t*>(&l2);
}

__device__ __forceinline__ uint32_t f2h2(float a, float b) {
    __half2 h = __floats2half2_rn(a, b);
    return *reinterpret_cast<uint32_t*>(&h);
}

// ============================================================================
// converters
// ============================================================================
// fp32 -> single fp16 (x)
__global__ void convert_h4(const float4* __restrict__ src,
                           uint2* __restrict__ dst, int n4)
{
    int i = blockIdx.x * blockDim.x + threadIdx.x;
    if (i >= n4) return;
    float4 v = src[i];
    uint2 d;
    d.x = f2h2(v.x, v.y);
    d.y = f2h2(v.z, v.w);
    dst[i] = d;
}

// 4 weights -> fp16 hi/lo splits, one launch (grid.y = 4)
__global__ void convert_weights4(const float4* __restrict__ w0,
                                 const float4* __restrict__ w1,
                                 const float4* __restrict__ w2,
                                 const float4* __restrict__ w3,
                                 uint2* __restrict__ Wh, uint2* __restrict__ Wl,
                                 int n4)
{
    int i = blockIdx.x * blockDim.x + threadIdx.x;
    if (i >= n4) return;
    int z = blockIdx.y;
    const float4* src = (z == 0) ? w0 : (z == 1) ? w1 : (z == 2) ? w2 : w3;
    float4 v = src[i];
    uint2 ho, loo;
    split2h(v.x, v.y, ho.x, loo.x);
    split2h(v.z, v.w, ho.y, loo.y);
    Wh[(size_t)z * n4 + i] = ho;
    Wl[(size_t)z * n4 + i] = loo;
}

// ============================================================================
// fp16 2-term GEMM: C = A @ (Wh+Wl)^T + bias.  128x128 tile, BK=32, 8 warps,
// cp.async double buffer, fp32 accum.
// mode 0: fp32 out
// mode 1: RoPE(acc+bias)*QSCALE -> split bf16 (Q)
// mode 2: RoPE(acc+bias)        -> split bf16 (K)
// mode 3: (acc+bias)            -> single fp16 (V)
// ============================================================================
#define GSTR    40                 // smem row stride (halves): 32 data + 8 pad
#define G_ARR   (128 * GSTR)
#define G_STAGE (3 * G_ARR)
#define GEMM_SMEM (2 * G_STAGE * 2)   // 61440 bytes

__device__ __forceinline__ void gemm_prefetch(
    __half* st,
    const __half* __restrict__ A,
    const __half* __restrict__ Wh, const __half* __restrict__ Wl,
    int rowBase, int colBase, int kt, int tid)
{
#pragma unroll
    for (int p = 0; p < 2; p++) {
        int id = tid + p * 256;
        int r  = id >> 2;
        int q  = (id & 3) * 8;
        int so = r * GSTR + q;
        size_t ga = (size_t)(rowBase + r) * D_MODEL + kt + q;
        size_t gw = (size_t)(colBase + r) * D_MODEL + kt + q;
        CP_ASYNC16(s_u32(st + so),             A  + ga);
        CP_ASYNC16(s_u32(st + G_ARR + so),     Wh + gw);
        CP_ASYNC16(s_u32(st + 2 * G_ARR + so), Wl + gw);
    }
}

__device__ __forceinline__ void gemm_body(
    const __half* __restrict__ A,
    const __half* __restrict__ Wh, const __half* __restrict__ Wl,
    const float* __restrict__ bias, float* __restrict__ C,
    __nv_bfloat16* __restrict__ Dh, __nv_bfloat16* __restrict__ Dl,
    __half* __restrict__ Dv, int mode, __half* sm)
{
    const int tid  = threadIdx.x;
    const int lane = tid & 31;
    const int wrp  = tid >> 5;
    const int g    = lane >> 2;
    const int t    = lane & 3;
    const int wm   = (wrp & 1) * 64;
    const int wn   = (wrp >> 1) * 32;
    const int rowBase = blockIdx.y * 128;
    const int colBase = blockIdx.x * 128;

    const int arow = (lane & 15);
    const int akoA = ((lane >> 4) << 3);
    const int brow = ((lane >> 4) << 3) + (lane & 7);
    const int bkoB = ((lane >> 3) & 1) * 8;

    float c[4][4][4];
#pragma unroll
    for (int i = 0; i < 4; i++)
#pragma unroll
        for (int j = 0; j < 4; j++)
#pragma unroll
            for (int e = 0; e < 4; e++) c[i][j][e] = 0.0f;

    gemm_prefetch(sm, A, Wh, Wl, rowBase, colBase, 0, tid);
    CP_COMMIT;

    const int NK = D_MODEL / 32;
    for (int it = 0; it < NK; it++) {
        __syncthreads();
        if (it + 1 < NK) {
            gemm_prefetch(sm + ((it + 1) & 1) * G_STAGE, A, Wh, Wl,
                          rowBase, colBase, (it + 1) * 32, tid);
            CP_COMMIT;
            CP_WAIT1;
        } else {
            CP_WAIT0;
        }
        __syncthreads();

        __half* st  = sm + (it & 1) * G_STAGE;
        __half* sA  = st;
        __half* sWh = st + G_ARR;
        __half* sWl = st + 2 * G_ARR;

#pragma unroll
        for (int kk = 0; kk < 2; kk++) {
            uint32_t ar[4][4], bb[4][2];
#pragma unroll
            for (int i = 0; i < 4; i++) {
                uint32_t a = s_u32(&sA[(wm + 16 * i + arow) * GSTR + kk * 16 + akoA]);
                LDSM4(ar[i][0], ar[i][1], ar[i][2], ar[i][3], a);
            }
#pragma unroll
            for (int jj = 0; jj < 2; jj++) {
                uint32_t a = s_u32(&sWh[(wn + 16 * jj + brow) * GSTR + kk * 16 + bkoB]);
                LDSM4(bb[2*jj][0], bb[2*jj][1], bb[2*jj+1][0], bb[2*jj+1][1], a);
            }
#pragma unroll
            for (int i = 0; i < 4; i++)
#pragma unroll
                for (int j = 0; j < 4; j++) MMA_FP16(c[i][j], ar[i], bb[j]);
#pragma unroll
            for (int jj = 0; jj < 2; jj++) {
                uint32_t a = s_u32(&sWl[(wn + 16 * jj + brow) * GSTR + kk * 16 + bkoB]);
                LDSM4(bb[2*jj][0], bb[2*jj][1], bb[2*jj+1][0], bb[2*jj+1][1], a);
            }
#pragma unroll
            for (int i = 0; i < 4; i++)
#pragma unroll
                for (int j = 0; j < 4; j++) MMA_FP16(c[i][j], ar[i], bb[j]);
        }
    }

    // ---- fused epilogue ----
#pragma unroll
    for (int i = 0; i < 4; i++) {
        int row = rowBase + wm + i * 16 + g;
        int s0  = row & (SEQ - 1);
        int s1  = (row + 8) & (SEQ - 1);
#pragma unroll
        for (int j = 0; j < 4; j++) {
            int col = colBase + wn + j * 8 + 2 * t;
            float b0 = bias[col], b1 = bias[col + 1];
            float x0 = c[i][j][0] + b0, x1 = c[i][j][1] + b1;
            float y0 = c[i][j][2] + b0, y1 = c[i][j][3] + b1;
            size_t i0 = (size_t)row * D_MODEL + col;
            size_t i1 = i0 + (size_t)8 * D_MODEL;
            if (mode == 0) {
                *reinterpret_cast<float2*>(&C[i0]) = make_float2(x0, x1);
                *reinterpret_cast<float2*>(&C[i1]) = make_float2(y0, y1);
            } else if (mode == 3) {
                *(uint32_t*)&Dv[i0] = f2h2(x0, x1);
                *(uint32_t*)&Dv[i1] = f2h2(y0, y1);
            } else {
                int p = (col & 63) >> 1;
                float freq = powf(10000.0f, -(float)p * (1.0f / 32.0f));
                float sn0, cs0, sn1, cs1;
                sincosf((float)s0 * freq, &sn0, &cs0);
                sincosf((float)s1 * freq, &sn1, &cs1);
                float r0a = x0 * cs0 - x1 * sn0;
                float r0b = x1 * cs0 + x0 * sn0;
                float r1a = y0 * cs1 - y1 * sn1;
                float r1b = y1 * cs1 + y0 * sn1;
                if (mode == 1) {
                    r0a *= QSCALE; r0b *= QSCALE;
                    r1a *= QSCALE; r1b *= QSCALE;
                }
                uint32_t hi, lo;
                split2(r0a, r0b, hi, lo);
                *(uint32_t*)&Dh[i0] = hi;
                *(uint32_t*)&Dl[i0] = lo;
                split2(r1a, r1b, hi, lo);
                *(uint32_t*)&Dh[i1] = hi;
                *(uint32_t*)&Dl[i1] = lo;
            }
        }
    }
}

__global__ __launch_bounds__(256, 2) void gemm_qkv(
    const __half* __restrict__ A,
    const __half* __restrict__ WhB, const __half* __restrict__ WlB,
    const float* __restrict__ b0, const float* __restrict__ b1, const float* __restrict__ b2,
    __nv_bfloat16* __restrict__ Qh, __nv_bfloat16* __restrict__ Ql,
    __nv_bfloat16* __restrict__ Kh, __nv_bfloat16* __restrict__ Kl,
    __half* __restrict__ V16)
{
    extern __shared__ __half smg[];
    const int z = blockIdx.z;
    const size_t WSZ = (size_t)D_MODEL * D_MODEL;
    const float* bias = (z == 0) ? b0 : (z == 1) ? b1 : b2;
    __nv_bfloat16* Dh = (z == 0) ? Qh : Kh;
    __nv_bfloat16* Dl = (z == 0) ? Ql : Kl;
    gemm_body(A, WhB + z * WSZ, WlB + z * WSZ, bias,
              (float*)0, Dh, Dl, V16, z + 1, smg);
}

__global__ __launch_bounds__(256, 2) void gemm_out(
    const __half* __restrict__ A,
    const __half* __restrict__ Wh, const __half* __restrict__ Wl,
    const float* __restrict__ bias, float* __restrict__ C)
{
    extern __shared__ __half smg[];
    gemm_body(A, Wh, Wl, bias, C,
              (__nv_bfloat16*)0, (__nv_bfloat16*)0, (__half*)0, 0, smg);
}

// ============================================================================
// Tensor-core flash attention: S = 3-term bf16; softmax in exp2 domain;
// PV = fp16 P @ single fp16 V. occupancy 2.
// ============================================================================
#define ATS     72
#define A_ARR   (64 * ATS)
#define A_STAGE (3 * A_ARR)               // Kh, Kl (bf16 bits), V (fp16 bits)
#define ATT_SMEM (2 * A_STAGE * 2)        // 55296 bytes

__device__ __forceinline__ void att_prefetch(
    __nv_bfloat16* st,
    const __nv_bfloat16* __restrict__ Kh, const __nv_bfloat16* __restrict__ Kl,
    const __half* __restrict__ V16,
    size_t gbase, int kv0, int tid)
{
#pragma unroll
    for (int p = 0; p < 2; p++) {
        int idx = tid + p * 256;
        int r   = idx >> 3;
        int cq  = (idx & 7) * 8;
        int so  = r * ATS + cq;
        size_t gk = gbase + (size_t)(kv0 + r) * D_MODEL + cq;
        CP_ASYNC16(s_u32(st + so),             Kh  + gk);
        CP_ASYNC16(s_u32(st + A_ARR + so),     Kl  + gk);
        CP_ASYNC16(s_u32(st + 2 * A_ARR + so), V16 + gk);
    }
}

__global__ __launch_bounds__(256, 2) void attention_mma(
    const __nv_bfloat16* __restrict__ Qh, const __nv_bfloat16* __restrict__ Ql,
    const __nv_bfloat16* __restrict__ Kh, const __nv_bfloat16* __restrict__ Kl,
    const __half* __restrict__ V16,
    __half* __restrict__ O16)
{
    extern __shared__ __nv_bfloat16 sKV[];

    const int bh = blockIdx.y;
    const int b  = bh >> 4;
    const int h  = bh & 15;
    const int q0 = blockIdx.x * 128;
    const int tid  = threadIdx.x;
    const int lane = tid & 31;
    const int wrp  = tid >> 5;
    const int g    = lane >> 2;
    const int t    = lane & 3;

    const size_t gbase = (size_t)b * SEQ * D_MODEL + (size_t)h * DKH;

    att_prefetch(sKV, Kh, Kl, V16, gbase, 0, tid);
    CP_COMMIT;

    // ---- Q fragments directly from gmem (A-frag layout) ----
    uint32_t qfh[4][4], qfl[4][4];
    {
        const int r0 = q0 + 16 * wrp + g;
        size_t ro0 = gbase + (size_t)r0 * D_MODEL;
        size_t ro8 = ro0 + (size_t)8 * D_MODEL;
#pragma unroll
        for (int kc = 0; kc < 4; kc++) {
            int cw = kc * 16 + 2 * t;
            qfh[kc][0] = *(const uint32_t*)&Qh[ro0 + cw];
            qfh[kc][1] = *(const uint32_t*)&Qh[ro8 + cw];
            qfh[kc][2] = *(const uint32_t*)&Qh[ro0 + cw + 8];
            qfh[kc][3] = *(const uint32_t*)&Qh[ro8 + cw + 8];
            qfl[kc][0] = *(const uint32_t*)&Ql[ro0 + cw];
            qfl[kc][1] = *(const uint32_t*)&Ql[ro8 + cw];
            qfl[kc][2] = *(const uint32_t*)&Ql[ro0 + cw + 8];
            qfl[kc][3] = *(const uint32_t*)&Ql[ro8 + cw + 8];
        }
    }

    float m[2] = {-INFINITY, -INFINITY};
    float l[2] = {0.0f, 0.0f};
    float o[8][4];
#pragma unroll
    for (int j = 0; j < 8; j++)
#pragma unroll
        for (int e = 0; e < 4; e++) o[j][e] = 0.0f;

    const int brow  = ((lane >> 4) << 3) + (lane & 7);
    const int bko   = ((lane >> 3) & 1) * 8;
    const int vrow  = (lane & 7) + ((lane >> 3) & 1) * 8;
    const int vcol  = ((lane >> 4) << 3);

    const int NT = SEQ / 64;
    for (int it = 0; it < NT; it++) {
        __syncthreads();
        if (it + 1 < NT) {
            att_prefetch(sKV + ((it + 1) & 1) * A_STAGE, Kh, Kl, V16,
                         gbase, (it + 1) * 64, tid);
            CP_COMMIT;
            CP_WAIT1;
        } else {
            CP_WAIT0;
        }
        __syncthreads();

        __nv_bfloat16* st  = sKV + (it & 1) * A_STAGE;
        __nv_bfloat16* sKh = st;
        __nv_bfloat16* sKl = st + A_ARR;
        __nv_bfloat16* sV  = st + 2 * A_ARR;   // fp16 bits

        // ---- S = Q @ K^T (3-term bf16 split, term-major) ----
        float s[8][4];
#pragma unroll
        for (int j = 0; j < 8; j++)
#pragma unroll
            for (int e = 0; e < 4; e++) s[j][e] = 0.0f;

#pragma unroll
        for (int kc = 0; kc < 4; kc++) {
            uint32_t kb[8][2];
#pragma unroll
            for (int jj = 0; jj < 4; jj++) {
                uint32_t a = s_u32(&sKh[(16 * jj + brow) * ATS + kc * 16 + bko]);
                LDSM4(kb[2*jj][0], kb[2*jj][1], kb[2*jj+1][0], kb[2*jj+1][1], a);
            }
#pragma unroll
            for (int j = 0; j < 8; j++) MMA_BF16(s[j], qfh[kc], kb[j]);
#pragma unroll
            for (int j = 0; j < 8; j++) MMA_BF16(s[j], qfl[kc], kb[j]);
#pragma unroll
            for (int jj = 0; jj < 4; jj++) {
                uint32_t a = s_u32(&sKl[(16 * jj + brow) * ATS + kc * 16 + bko]);
                LDSM4(kb[2*jj][0], kb[2*jj][1], kb[2*jj+1][0], kb[2*jj+1][1], a);
            }
#pragma unroll
            for (int j = 0; j < 8; j++) MMA_BF16(s[j], qfh[kc], kb[j]);
        }

        // ---- online softmax (exp2 domain, tree max, deferred l) ----
        float alpha[2];
#pragma unroll
        for (int e = 0; e < 2; e++) {
            float a0 = fmaxf(s[0][2*e], s[0][2*e+1]);
            float a1 = fmaxf(s[1][2*e], s[1][2*e+1]);
            float a2 = fmaxf(s[2][2*e], s[2][2*e+1]);
            float a3 = fmaxf(s[3][2*e], s[3][2*e+1]);
            float a4 = fmaxf(s[4][2*e], s[4][2*e+1]);
            float a5 = fmaxf(s[5][2*e], s[5][2*e+1]);
            float a6 = fmaxf(s[6][2*e], s[6][2*e+1]);
            float a7 = fmaxf(s[7][2*e], s[7][2*e+1]);
            a0 = fmaxf(a0, a1); a2 = fmaxf(a2, a3);
            a4 = fmaxf(a4, a5); a6 = fmaxf(a6, a7);
            float mloc = fmaxf(fmaxf(a0, a2), fmaxf(a4, a6));
            mloc = fmaxf(mloc, __shfl_xor_sync(0xffffffffu, mloc, 1));
            mloc = fmaxf(mloc, __shfl_xor_sync(0xffffffffu, mloc, 2));
            float mnew = fmaxf(m[e], mloc);
            alpha[e] = ex2f(m[e] - mnew);
            float ls0 = 0.0f, ls1 = 0.0f, ls2 = 0.0f, ls3 = 0.0f;
#pragma unroll
            for (int j = 0; j < 8; j += 2) {
                float p0 = ex2f(s[j][2*e]     - mnew);
                float p1 = ex2f(s[j][2*e+1]   - mnew);
                float p2 = ex2f(s[j+1][2*e]   - mnew);
                float p3 = ex2f(s[j+1][2*e+1] - mnew);
                s[j][2*e]     = p0; s[j][2*e+1]   = p1;
                s[j+1][2*e]   = p2; s[j+1][2*e+1] = p3;
                ls0 += p0; ls1 += p1; ls2 += p2; ls3 += p3;
            }
            l[e] = l[e] * alpha[e] + ((ls0 + ls1) + (ls2 + ls3));
            m[e] = mnew;
        }
#pragma unroll
        for (int j = 0; j < 8; j++) {
            o[j][0] *= alpha[0]; o[j][1] *= alpha[0];
            o[j][2] *= alpha[1]; o[j][3] *= alpha[1];
        }

        // ---- P fragments: single fp16 (A-frag layout) ----
        uint32_t pa[4][4];
#pragma unroll
        for (int kc = 0; kc < 4; kc++) {
            pa[kc][0] = f2h2(s[2*kc][0],   s[2*kc][1]);
            pa[kc][1] = f2h2(s[2*kc][2],   s[2*kc][3]);
            pa[kc][2] = f2h2(s[2*kc+1][0], s[2*kc+1][1]);
            pa[kc][3] = f2h2(s[2*kc+1][2], s[2*kc+1][3]);
        }

        // ---- O += P @ V (single fp16 term) ----
#pragma unroll
        for (int kc = 0; kc < 4; kc++) {
            uint32_t vb[8][2];
#pragma unroll
            for (int jj = 0; jj < 4; jj++) {
                uint32_t a = s_u32(&sV[(kc * 16 + vrow) * ATS + 16 * jj + vcol]);
                LDSM4T(vb[2*jj][0], vb[2*jj][1], vb[2*jj+1][0], vb[2*jj+1][1], a);
            }
#pragma unroll
            for (int j = 0; j < 8; j++) MMA_FP16(o[j], pa[kc], vb[j]);
        }
    }

    // ---- epilogue: quad-reduce l, normalize, write single fp16 O ----
    l[0] += __shfl_xor_sync(0xffffffffu, l[0], 1);
    l[0] += __shfl_xor_sync(0xffffffffu, l[0], 2);
    l[1] += __shfl_xor_sync(0xffffffffu, l[1], 1);
    l[1] += __shfl_xor_sync(0xffffffffu, l[1], 2);

    const int r0 = q0 + 16 * wrp + g;
    const float inv0 = 1.0f / l[0];
    const float inv1 = 1.0f / l[1];
#pragma unroll
    for (int j = 0; j < 8; j++) {
        int col = h * DKH + 8 * j + 2 * t;
        size_t i0 = (size_t)b * SEQ * D_MODEL + (size_t)r0 * D_MODEL + col;
        size_t i1 = i0 + (size_t)8 * D_MODEL;
        *(uint32_t*)&O16[i0] = f2h2(o[j][0] * inv0, o[j][1] * inv0);
        *(uint32_t*)&O16[i1] = f2h2(o[j][2] * inv1, o[j][3] * inv1);
    }
}

// ============================================================================
// Launch
// ============================================================================
extern "C" void kernel_launch(void* const* d_in, const int* in_sizes, int n_in,
                              void* d_out, int out_size)
{
    (void)in_sizes; (void)n_in; (void)out_size;
    const float* x  = (const float*)d_in[0];
    const float* wq = (const float*)d_in[1];
    const float* bq = (const float*)d_in[2];
    const float* wk = (const float*)d_in[3];
    const float* bk = (const float*)d_in[4];
    const float* wv = (const float*)d_in[5];
    const float* bv = (const float*)d_in[6];
    const float* wo = (const float*)d_in[7];
    const float* bo = (const float*)d_in[8];
    float* out = (float*)d_out;

    __half *X16, *O16, *V16, *W16h, *W16l;
    __nv_bfloat16 *Qhp, *Qlp, *Khp, *Klp;
    cudaGetSymbolAddress((void**)&X16,  g_X16);
    cudaGetSymbolAddress((void**)&O16,  g_O16);
    cudaGetSymbolAddress((void**)&V16,  g_V16);
    cudaGetSymbolAddress((void**)&W16h, g_W16h);
    cudaGetSymbolAddress((void**)&W16l, g_W16l);
    cudaGetSymbolAddress((void**)&Qhp,  g_Qh);
    cudaGetSymbolAddress((void**)&Qlp,  g_Ql);
    cudaGetSymbolAddress((void**)&Khp,  g_Kh);
    cudaGetSymbolAddress((void**)&Klp,  g_Kl);

    cudaFuncSetAttribute(attention_mma,
                         cudaFuncAttributeMaxDynamicSharedMemorySize, ATT_SMEM);
    cudaFuncSetAttribute(gemm_qkv,
                         cudaFuncAttributeMaxDynamicSharedMemorySize, GEMM_SMEM);
    cudaFuncSetAttribute(gemm_out,
                         cudaFuncAttributeMaxDynamicSharedMemorySize, GEMM_SMEM);

    const size_t WSZ = (size_t)D_MODEL * D_MODEL;

    int n4x = (MROWS * D_MODEL) / 4;
    int n4w = (int)(WSZ / 4);
    convert_h4<<<(n4x + 255) / 256, 256>>>((const float4*)x, (uint2*)X16, n4x);
    dim3 wgrid((n4w + 255) / 256, 4);
    convert_weights4<<<wgrid, 256>>>((const float4*)wq, (const float4*)wk,
                                     (const float4*)wv, (const float4*)wo,
                                     (uint2*)W16h, (uint2*)W16l, n4w);

    // fused QKV projections (Q: rope+exp2-scale bf16 split, K: rope bf16 split,
    // V: single fp16)
    dim3 qkvgrid(D_MODEL / 128, MROWS / 128, 3);
    gemm_qkv<<<qkvgrid, 256, GEMM_SMEM>>>(X16, W16h, W16l, bq, bk, bv,
                                          Qhp, Qlp, Khp, Klp, V16);

    // tensor-core flash attention (writes single fp16 O)
    dim3 agrid(SEQ / 128, BATCH * NUM_HEADS);
    attention_mma<<<agrid, 256, ATT_SMEM>>>(Qhp, Qlp, Khp, Klp, V16, O16);

    // output projection
    dim3 ogrid(D_MODEL / 128, MROWS / 128);
    gemm_out<<<ogrid, 256, GEMM_SMEM>>>(O16, W16h + 3 * WSZ, W16l + 3 * WSZ,
                                        bo, out);
}

// round 13
// speedup vs baseline: 6.3873x; 1.2323x over previous
#include <cuda_runtime.h>
#include <cuda_bf16.h>
#include <cuda_fp16.h>
#include <math.h>
#include <stdint.h>

#define D_MODEL   1024
#define NUM_HEADS 16
#define DKH       64
#define BATCH     2
#define SEQ       2048
#define MROWS     (BATCH * SEQ)   // 4096

// Q pre-scale: 1/sqrt(dk) * log2(e)  (softmax runs in exp2 domain)
#define QSCALE (0.125f * 1.44269504f)

// ---------------- scratch (device globals; no allocation allowed) ----------
__device__ __half g_X16[MROWS * D_MODEL];
__device__ __half g_O16[MROWS * D_MODEL];
__device__ __half g_Q16[MROWS * D_MODEL];
__device__ __half g_K16h[MROWS * D_MODEL];
__device__ __half g_K16l[MROWS * D_MODEL];
__device__ __half g_V16[MROWS * D_MODEL];
__device__ __half g_W16h[4 * D_MODEL * D_MODEL];
__device__ __half g_W16l[4 * D_MODEL * D_MODEL];

// ---------------- helpers ---------------------------------------------------
__device__ __forceinline__ uint32_t s_u32(const void* p) {
    return (uint32_t)__cvta_generic_to_shared(p);
}

#define LDSM4(r0, r1, r2, r3, a)                                              \
    asm volatile("ldmatrix.sync.aligned.m8n8.x4.shared.b16 {%0,%1,%2,%3},[%4];"\
        : "=r"(r0), "=r"(r1), "=r"(r2), "=r"(r3) : "r"(a))

#define LDSM4T(r0, r1, r2, r3, a)                                             \
    asm volatile("ldmatrix.sync.aligned.m8n8.x4.trans.shared.b16 {%0,%1,%2,%3},[%4];"\
        : "=r"(r0), "=r"(r1), "=r"(r2), "=r"(r3) : "r"(a))

#define MMA_FP16(c, a, b)                                                     \
    asm("mma.sync.aligned.m16n8k16.row.col.f32.f16.f16.f32 "                  \
        "{%0,%1,%2,%3}, {%4,%5,%6,%7}, {%8,%9}, {%0,%1,%2,%3};"               \
        : "+f"((c)[0]), "+f"((c)[1]), "+f"((c)[2]), "+f"((c)[3])              \
        : "r"((a)[0]), "r"((a)[1]), "r"((a)[2]), "r"((a)[3]),                 \
          "r"((b)[0]), "r"((b)[1]))

#define CP_ASYNC16(dst, src)                                                  \
    asm volatile("cp.async.cg.shared.global [%0], [%1], 16;"                  \
        :: "r"(dst), "l"(src))
#define CP_COMMIT   asm volatile("cp.async.commit_group;")
#define CP_WAIT1    asm volatile("cp.async.wait_group 1;")
#define CP_WAIT0    asm volatile("cp.async.wait_group 0;")

__device__ __forceinline__ float ex2f(float x) {
    float r;
    asm("ex2.approx.f32 %0, %1;" : "=f"(r) : "f"(x));
    return r;
}

__device__ __forceinline__ void split2h(float a, float b, uint32_t& hi, uint32_t& lo) {
    __half2 h = __floats2half2_rn(a, b);
    float2 f = __half22float2(h);
    __half2 l2 = __floats2half2_rn(a - f.x, b - f.y);
    hi = *reinterpret_cast<uint32_t*>(&h);
    lo = *reinterpret_cast<uint32_t*>(&l2);
}

__device__ __forceinline__ uint32_t f2h2(float a, float b) {
    __half2 h = __floats2half2_rn(a, b);
    return *reinterpret_cast<uint32_t*>(&h);
}

// ============================================================================
// converters
// ============================================================================
__global__ void convert_h4(const float4* __restrict__ src,
                           uint2* __restrict__ dst, int n4)
{
    int i = blockIdx.x * blockDim.x + threadIdx.x;
    if (i >= n4) return;
    float4 v = src[i];
    uint2 d;
    d.x = f2h2(v.x, v.y);
    d.y = f2h2(v.z, v.w);
    dst[i] = d;
}

__global__ void convert_weights4(const float4* __restrict__ w0,
                                 const float4* __restrict__ w1,
                                 const float4* __restrict__ w2,
                                 const float4* __restrict__ w3,
                                 uint2* __restrict__ Wh, uint2* __restrict__ Wl,
                                 int n4)
{
    int i = blockIdx.x * blockDim.x + threadIdx.x;
    if (i >= n4) return;
    int z = blockIdx.y;
    const float4* src = (z == 0) ? w0 : (z == 1) ? w1 : (z == 2) ? w2 : w3;
    float4 v = src[i];
    uint2 ho, loo;
    split2h(v.x, v.y, ho.x, loo.x);
    split2h(v.z, v.w, ho.y, loo.y);
    Wh[(size_t)z * n4 + i] = ho;
    Wl[(size_t)z * n4 + i] = loo;
}

// ============================================================================
// fp16 GEMM: C = A @ W^T + bias (1 or 2 W terms). 128x128 tile, BK=32,
// 8 warps, cp.async double buffer, fp32 accum.
// mode 0: fp32 out (O-proj)
// mode 1: RoPE(acc+bias)*QSCALE -> single fp16 (Q)
// mode 2: RoPE(acc+bias)        -> fp16 hi/lo   (K)
// mode 3: (acc+bias)            -> single fp16  (V)
// ============================================================================
#define GSTR    40                 // smem row stride (halves): 32 data + 8 pad
#define G_ARR   (128 * GSTR)
#define G_STAGE (3 * G_ARR)
#define GEMM_SMEM (2 * G_STAGE * 2)   // 61440 bytes

__device__ __forceinline__ void gemm_prefetch(
    __half* st,
    const __half* __restrict__ A,
    const __half* __restrict__ Wh, const __half* __restrict__ Wl,
    int rowBase, int colBase, int kt, int tid, int nterms)
{
#pragma unroll
    for (int p = 0; p < 2; p++) {
        int id = tid + p * 256;
        int r  = id >> 2;
        int q  = (id & 3) * 8;
        int so = r * GSTR + q;
        size_t ga = (size_t)(rowBase + r) * D_MODEL + kt + q;
        size_t gw = (size_t)(colBase + r) * D_MODEL + kt + q;
        CP_ASYNC16(s_u32(st + so),         A  + ga);
        CP_ASYNC16(s_u32(st + G_ARR + so), Wh + gw);
        if (nterms == 2)
            CP_ASYNC16(s_u32(st + 2 * G_ARR + so), Wl + gw);
    }
}

__device__ __forceinline__ void gemm_body(
    const __half* __restrict__ A,
    const __half* __restrict__ Wh, const __half* __restrict__ Wl,
    const float* __restrict__ bias, float* __restrict__ C,
    __half* __restrict__ Dh, __half* __restrict__ Dl,
    int mode, int nterms, __half* sm)
{
    const int tid  = threadIdx.x;
    const int lane = tid & 31;
    const int wrp  = tid >> 5;
    const int g    = lane >> 2;
    const int t    = lane & 3;
    const int wm   = (wrp & 1) * 64;
    const int wn   = (wrp >> 1) * 32;
    const int rowBase = blockIdx.y * 128;
    const int colBase = blockIdx.x * 128;

    const int arow = (lane & 15);
    const int akoA = ((lane >> 4) << 3);
    const int brow = ((lane >> 4) << 3) + (lane & 7);
    const int bkoB = ((lane >> 3) & 1) * 8;

    float c[4][4][4];
#pragma unroll
    for (int i = 0; i < 4; i++)
#pragma unroll
        for (int j = 0; j < 4; j++)
#pragma unroll
            for (int e = 0; e < 4; e++) c[i][j][e] = 0.0f;

    gemm_prefetch(sm, A, Wh, Wl, rowBase, colBase, 0, tid, nterms);
    CP_COMMIT;

    const int NK = D_MODEL / 32;
    for (int it = 0; it < NK; it++) {
        __syncthreads();
        if (it + 1 < NK) {
            gemm_prefetch(sm + ((it + 1) & 1) * G_STAGE, A, Wh, Wl,
                          rowBase, colBase, (it + 1) * 32, tid, nterms);
            CP_COMMIT;
            CP_WAIT1;
        } else {
            CP_WAIT0;
        }
        __syncthreads();

        __half* st  = sm + (it & 1) * G_STAGE;
        __half* sA  = st;
        __half* sWh = st + G_ARR;
        __half* sWl = st + 2 * G_ARR;

#pragma unroll
        for (int kk = 0; kk < 2; kk++) {
            uint32_t ar[4][4], bb[4][2];
#pragma unroll
            for (int i = 0; i < 4; i++) {
                uint32_t a = s_u32(&sA[(wm + 16 * i + arow) * GSTR + kk * 16 + akoA]);
                LDSM4(ar[i][0], ar[i][1], ar[i][2], ar[i][3], a);
            }
#pragma unroll
            for (int jj = 0; jj < 2; jj++) {
                uint32_t a = s_u32(&sWh[(wn + 16 * jj + brow) * GSTR + kk * 16 + bkoB]);
                LDSM4(bb[2*jj][0], bb[2*jj][1], bb[2*jj+1][0], bb[2*jj+1][1], a);
            }
#pragma unroll
            for (int i = 0; i < 4; i++)
#pragma unroll
                for (int j = 0; j < 4; j++) MMA_FP16(c[i][j], ar[i], bb[j]);
            if (nterms == 2) {
#pragma unroll
                for (int jj = 0; jj < 2; jj++) {
                    uint32_t a = s_u32(&sWl[(wn + 16 * jj + brow) * GSTR + kk * 16 + bkoB]);
                    LDSM4(bb[2*jj][0], bb[2*jj][1], bb[2*jj+1][0], bb[2*jj+1][1], a);
                }
#pragma unroll
                for (int i = 0; i < 4; i++)
#pragma unroll
                    for (int j = 0; j < 4; j++) MMA_FP16(c[i][j], ar[i], bb[j]);
            }
        }
    }

    // ---- fused epilogue ----
#pragma unroll
    for (int i = 0; i < 4; i++) {
        int row = rowBase + wm + i * 16 + g;
        int s0  = row & (SEQ - 1);
        int s1  = (row + 8) & (SEQ - 1);
#pragma unroll
        for (int j = 0; j < 4; j++) {
            int col = colBase + wn + j * 8 + 2 * t;
            float b0 = bias[col], b1 = bias[col + 1];
            float x0 = c[i][j][0] + b0, x1 = c[i][j][1] + b1;
            float y0 = c[i][j][2] + b0, y1 = c[i][j][3] + b1;
            size_t i0 = (size_t)row * D_MODEL + col;
            size_t i1 = i0 + (size_t)8 * D_MODEL;
            if (mode == 0) {
                *reinterpret_cast<float2*>(&C[i0]) = make_float2(x0, x1);
                *reinterpret_cast<float2*>(&C[i1]) = make_float2(y0, y1);
            } else if (mode == 3) {
                *(uint32_t*)&Dh[i0] = f2h2(x0, x1);
                *(uint32_t*)&Dh[i1] = f2h2(y0, y1);
            } else {
                int p = (col & 63) >> 1;
                float freq = powf(10000.0f, -(float)p * (1.0f / 32.0f));
                float sn0, cs0, sn1, cs1;
                sincosf((float)s0 * freq, &sn0, &cs0);
                sincosf((float)s1 * freq, &sn1, &cs1);
                float r0a = x0 * cs0 - x1 * sn0;
                float r0b = x1 * cs0 + x0 * sn0;
                float r1a = y0 * cs1 - y1 * sn1;
                float r1b = y1 * cs1 + y0 * sn1;
                if (mode == 1) {
                    // Q: rope + exp2-domain scale -> single fp16
                    *(uint32_t*)&Dh[i0] = f2h2(r0a * QSCALE, r0b * QSCALE);
                    *(uint32_t*)&Dh[i1] = f2h2(r1a * QSCALE, r1b * QSCALE);
                } else {
                    // K: rope -> fp16 hi/lo split
                    uint32_t hi, lo;
                    split2h(r0a, r0b, hi, lo);
                    *(uint32_t*)&Dh[i0] = hi;
                    *(uint32_t*)&Dl[i0] = lo;
                    split2h(r1a, r1b, hi, lo);
                    *(uint32_t*)&Dh[i1] = hi;
                    *(uint32_t*)&Dl[i1] = lo;
                }
            }
        }
    }
}

// QKV fused: z=0 -> Q (mode 1, 2-term), z=1 -> K (mode 2, 2-term),
//            z=2 -> V (mode 3, 1-term)
__global__ __launch_bounds__(256, 2) void gemm_qkv(
    const __half* __restrict__ A,
    const __half* __restrict__ WhB, const __half* __restrict__ WlB,
    const float* __restrict__ b0, const float* __restrict__ b1, const float* __restrict__ b2,
    __half* __restrict__ Q16,
    __half* __restrict__ K16h, __half* __restrict__ K16l,
    __half* __restrict__ V16)
{
    extern __shared__ __half smg[];
    const int z = blockIdx.z;
    const size_t WSZ = (size_t)D_MODEL * D_MODEL;
    const float* bias = (z == 0) ? b0 : (z == 1) ? b1 : b2;
    __half* Dh = (z == 0) ? Q16 : (z == 1) ? K16h : V16;
    __half* Dl = (z == 1) ? K16l : (__half*)0;
    int nterms = (z == 2) ? 1 : 2;
    gemm_body(A, WhB + z * WSZ, WlB + z * WSZ, bias,
              (float*)0, Dh, Dl, z + 1, nterms, smg);
}

__global__ __launch_bounds__(256, 2) void gemm_out(
    const __half* __restrict__ A,
    const __half* __restrict__ Wh, const __half* __restrict__ Wl,
    const float* __restrict__ bias, float* __restrict__ C)
{
    extern __shared__ __half smg[];
    gemm_body(A, Wh, Wl, bias, C, (__half*)0, (__half*)0, 0, 1, smg);
}

// ============================================================================
// Tensor-core flash attention (all fp16):
// S = Q @ (Kh + Kl)  (2 terms), softmax in exp2 domain, O += P @ V (1 term).
// Q fragments from gmem; KV cp.async double-buffered; occupancy 2.
// ============================================================================
#define ATS     72
#define A_ARR   (64 * ATS)
#define A_STAGE (3 * A_ARR)               // Kh, Kl, V (all fp16)
#define ATT_SMEM (2 * A_STAGE * 2)        // 55296 bytes

__device__ __forceinline__ void att_prefetch(
    __half* st,
    const __half* __restrict__ Kh, const __half* __restrict__ Kl,
    const __half* __restrict__ V16,
    size_t gbase, int kv0, int tid)
{
#pragma unroll
    for (int p = 0; p < 2; p++) {
        int idx = tid + p * 256;
        int r   = idx >> 3;
        int cq  = (idx & 7) * 8;
        int so  = r * ATS + cq;
        size_t gk = gbase + (size_t)(kv0 + r) * D_MODEL + cq;
        CP_ASYNC16(s_u32(st + so),             Kh  + gk);
        CP_ASYNC16(s_u32(st + A_ARR + so),     Kl  + gk);
        CP_ASYNC16(s_u32(st + 2 * A_ARR + so), V16 + gk);
    }
}

__global__ __launch_bounds__(256, 2) void attention_mma(
    const __half* __restrict__ Q16,
    const __half* __restrict__ K16h, const __half* __restrict__ K16l,
    const __half* __restrict__ V16,
    __half* __restrict__ O16)
{
    extern __shared__ __half sKV[];

    const int bh = blockIdx.y;
    const int b  = bh >> 4;
    const int h  = bh & 15;
    const int q0 = blockIdx.x * 128;
    const int tid  = threadIdx.x;
    const int lane = tid & 31;
    const int wrp  = tid >> 5;
    const int g    = lane >> 2;
    const int t    = lane & 3;

    const size_t gbase = (size_t)b * SEQ * D_MODEL + (size_t)h * DKH;

    att_prefetch(sKV, K16h, K16l, V16, gbase, 0, tid);
    CP_COMMIT;

    // ---- Q fragments directly from gmem (A-frag layout, single fp16) ----
    uint32_t qf[4][4];
    {
        const int r0 = q0 + 16 * wrp + g;
        size_t ro0 = gbase + (size_t)r0 * D_MODEL;
        size_t ro8 = ro0 + (size_t)8 * D_MODEL;
#pragma unroll
        for (int kc = 0; kc < 4; kc++) {
            int cw = kc * 16 + 2 * t;
            qf[kc][0] = *(const uint32_t*)&Q16[ro0 + cw];
            qf[kc][1] = *(const uint32_t*)&Q16[ro8 + cw];
            qf[kc][2] = *(const uint32_t*)&Q16[ro0 + cw + 8];
            qf[kc][3] = *(const uint32_t*)&Q16[ro8 + cw + 8];
        }
    }

    float m[2] = {-INFINITY, -INFINITY};
    float l[2] = {0.0f, 0.0f};
    float o[8][4];
#pragma unroll
    for (int j = 0; j < 8; j++)
#pragma unroll
        for (int e = 0; e < 4; e++) o[j][e] = 0.0f;

    const int brow  = ((lane >> 4) << 3) + (lane & 7);
    const int bko   = ((lane >> 3) & 1) * 8;
    const int vrow  = (lane & 7) + ((lane >> 3) & 1) * 8;
    const int vcol  = ((lane >> 4) << 3);

    const int NT = SEQ / 64;
    for (int it = 0; it < NT; it++) {
        __syncthreads();
        if (it + 1 < NT) {
            att_prefetch(sKV + ((it + 1) & 1) * A_STAGE, K16h, K16l, V16,
                         gbase, (it + 1) * 64, tid);
            CP_COMMIT;
            CP_WAIT1;
        } else {
            CP_WAIT0;
        }
        __syncthreads();

        __half* st  = sKV + (it & 1) * A_STAGE;
        __half* sKh = st;
        __half* sKl = st + A_ARR;
        __half* sV  = st + 2 * A_ARR;

        // ---- S = Q @ K^T (2-term fp16, term-major) ----
        float s[8][4];
#pragma unroll
        for (int j = 0; j < 8; j++)
#pragma unroll
            for (int e = 0; e < 4; e++) s[j][e] = 0.0f;

#pragma unroll
        for (int kc = 0; kc < 4; kc++) {
            uint32_t kb[8][2];
#pragma unroll
            for (int jj = 0; jj < 4; jj++) {
                uint32_t a = s_u32(&sKh[(16 * jj + brow) * ATS + kc * 16 + bko]);
                LDSM4(kb[2*jj][0], kb[2*jj][1], kb[2*jj+1][0], kb[2*jj+1][1], a);
            }
#pragma unroll
            for (int j = 0; j < 8; j++) MMA_FP16(s[j], qf[kc], kb[j]);
#pragma unroll
            for (int jj = 0; jj < 4; jj++) {
                uint32_t a = s_u32(&sKl[(16 * jj + brow) * ATS + kc * 16 + bko]);
                LDSM4(kb[2*jj][0], kb[2*jj][1], kb[2*jj+1][0], kb[2*jj+1][1], a);
            }
#pragma unroll
            for (int j = 0; j < 8; j++) MMA_FP16(s[j], qf[kc], kb[j]);
        }

        // ---- online softmax (exp2 domain, tree max, deferred l) ----
        float alpha[2];
#pragma unroll
        for (int e = 0; e < 2; e++) {
            float a0 = fmaxf(s[0][2*e], s[0][2*e+1]);
            float a1 = fmaxf(s[1][2*e], s[1][2*e+1]);
            float a2 = fmaxf(s[2][2*e], s[2][2*e+1]);
            float a3 = fmaxf(s[3][2*e], s[3][2*e+1]);
            float a4 = fmaxf(s[4][2*e], s[4][2*e+1]);
            float a5 = fmaxf(s[5][2*e], s[5][2*e+1]);
            float a6 = fmaxf(s[6][2*e], s[6][2*e+1]);
            float a7 = fmaxf(s[7][2*e], s[7][2*e+1]);
            a0 = fmaxf(a0, a1); a2 = fmaxf(a2, a3);
            a4 = fmaxf(a4, a5); a6 = fmaxf(a6, a7);
            float mloc = fmaxf(fmaxf(a0, a2), fmaxf(a4, a6));
            mloc = fmaxf(mloc, __shfl_xor_sync(0xffffffffu, mloc, 1));
            mloc = fmaxf(mloc, __shfl_xor_sync(0xffffffffu, mloc, 2));
            float mnew = fmaxf(m[e], mloc);
            alpha[e] = ex2f(m[e] - mnew);
            float ls0 = 0.0f, ls1 = 0.0f, ls2 = 0.0f, ls3 = 0.0f;
#pragma unroll
            for (int j = 0; j < 8; j += 2) {
                float p0 = ex2f(s[j][2*e]     - mnew);
                float p1 = ex2f(s[j][2*e+1]   - mnew);
                float p2 = ex2f(s[j+1][2*e]   - mnew);
                float p3 = ex2f(s[j+1][2*e+1] - mnew);
                s[j][2*e]     = p0; s[j][2*e+1]   = p1;
                s[j+1][2*e]   = p2; s[j+1][2*e+1] = p3;
                ls0 += p0; ls1 += p1; ls2 += p2; ls3 += p3;
            }
            l[e] = l[e] * alpha[e] + ((ls0 + ls1) + (ls2 + ls3));
            m[e] = mnew;
        }
#pragma unroll
        for (int j = 0; j < 8; j++) {
            o[j][0] *= alpha[0]; o[j][1] *= alpha[0];
            o[j][2] *= alpha[1]; o[j][3] *= alpha[1];
        }

        // ---- P fragments: single fp16 (A-frag layout) ----
        uint32_t pa[4][4];
#pragma unroll
        for (int kc = 0; kc < 4; kc++) {
            pa[kc][0] = f2h2(s[2*kc][0],   s[2*kc][1]);
            pa[kc][1] = f2h2(s[2*kc][2],   s[2*kc][3]);
            pa[kc][2] = f2h2(s[2*kc+1][0], s[2*kc+1][1]);
            pa[kc][3] = f2h2(s[2*kc+1][2], s[2*kc+1][3]);
        }

        // ---- O += P @ V (single fp16 term) ----
#pragma unroll
        for (int kc = 0; kc < 4; kc++) {
            uint32_t vb[8][2];
#pragma unroll
            for (int jj = 0; jj < 4; jj++) {
                uint32_t a = s_u32(&sV[(kc * 16 + vrow) * ATS + 16 * jj + vcol]);
                LDSM4T(vb[2*jj][0], vb[2*jj][1], vb[2*jj+1][0], vb[2*jj+1][1], a);
            }
#pragma unroll
            for (int j = 0; j < 8; j++) MMA_FP16(o[j], pa[kc], vb[j]);
        }
    }

    // ---- epilogue: quad-reduce l, normalize, write single fp16 O ----
    l[0] += __shfl_xor_sync(0xffffffffu, l[0], 1);
    l[0] += __shfl_xor_sync(0xffffffffu, l[0], 2);
    l[1] += __shfl_xor_sync(0xffffffffu, l[1], 1);
    l[1] += __shfl_xor_sync(0xffffffffu, l[1], 2);

    const int r0 = q0 + 16 * wrp + g;
    const float inv0 = 1.0f / l[0];
    const float inv1 = 1.0f / l[1];
#pragma unroll
    for (int j = 0; j < 8; j++) {
        int col = h * DKH + 8 * j + 2 * t;
        size_t i0 = (size_t)b * SEQ * D_MODEL + (size_t)r0 * D_MODEL + col;
        size_t i1 = i0 + (size_t)8 * D_MODEL;
        *(uint32_t*)&O16[i0] = f2h2(o[j][0] * inv0, o[j][1] * inv0);
        *(uint32_t*)&O16[i1] = f2h2(o[j][2] * inv1, o[j][3] * inv1);
    }
}

// ============================================================================
// Launch
// ============================================================================
extern "C" void kernel_launch(void* const* d_in, const int* in_sizes, int n_in,
                              void* d_out, int out_size)
{
    (void)in_sizes; (void)n_in; (void)out_size;
    const float* x  = (const float*)d_in[0];
    const float* wq = (const float*)d_in[1];
    const float* bq = (const float*)d_in[2];
    const float* wk = (const float*)d_in[3];
    const float* bk = (const float*)d_in[4];
    const float* wv = (const float*)d_in[5];
    const float* bv = (const float*)d_in[6];
    const float* wo = (const float*)d_in[7];
    const float* bo = (const float*)d_in[8];
    float* out = (float*)d_out;

    __half *X16, *O16, *Q16, *K16h, *K16l, *V16, *W16h, *W16l;
    cudaGetSymbolAddress((void**)&X16,  g_X16);
    cudaGetSymbolAddress((void**)&O16,  g_O16);
    cudaGetSymbolAddress((void**)&Q16,  g_Q16);
    cudaGetSymbolAddress((void**)&K16h, g_K16h);
    cudaGetSymbolAddress((void**)&K16l, g_K16l);
    cudaGetSymbolAddress((void**)&V16,  g_V16);
    cudaGetSymbolAddress((void**)&W16h, g_W16h);
    cudaGetSymbolAddress((void**)&W16l, g_W16l);

    cudaFuncSetAttribute(attention_mma,
                         cudaFuncAttributeMaxDynamicSharedMemorySize, ATT_SMEM);
    cudaFuncSetAttribute(gemm_qkv,
                         cudaFuncAttributeMaxDynamicSharedMemorySize, GEMM_SMEM);
    cudaFuncSetAttribute(gemm_out,
                         cudaFuncAttributeMaxDynamicSharedMemorySize, GEMM_SMEM);

    const size_t WSZ = (size_t)D_MODEL * D_MODEL;

    int n4x = (MROWS * D_MODEL) / 4;
    int n4w = (int)(WSZ / 4);
    convert_h4<<<(n4x + 255) / 256, 256>>>((const float4*)x, (uint2*)X16, n4x);
    dim3 wgrid((n4w + 255) / 256, 4);
    convert_weights4<<<wgrid, 256>>>((const float4*)wq, (const float4*)wk,
                                     (const float4*)wv, (const float4*)wo,
                                     (uint2*)W16h, (uint2*)W16l, n4w);

    // fused QKV projections
    dim3 qkvgrid(D_MODEL / 128, MROWS / 128, 3);
    gemm_qkv<<<qkvgrid, 256, GEMM_SMEM>>>(X16, W16h, W16l, bq, bk, bv,
                                          Q16, K16h, K16l, V16);

    // tensor-core flash attention
    dim3 agrid(SEQ / 128, BATCH * NUM_HEADS);
    attention_mma<<<agrid, 256, ATT_SMEM>>>(Q16, K16h, K16l, V16, O16);

    // output projection (1-term)
    dim3 ogrid(D_MODEL / 128, MROWS / 128);
    gemm_out<<<ogrid, 256, GEMM_SMEM>>>(O16, W16h + 3 * WSZ, W16l + 3 * WSZ,
                                        bo, out);
}

// round 14
// speedup vs baseline: 8.0907x; 1.2667x over previous
#include <cuda_runtime.h>
#include <cuda_fp16.h>
#include <math.h>
#include <stdint.h>

#define D_MODEL   1024
#define NUM_HEADS 16
#define DKH       64
#define BATCH     2
#define SEQ       2048
#define MROWS     (BATCH * SEQ)   // 4096

// Q pre-scale: 1/sqrt(dk) * log2(e)  (softmax runs in exp2 domain)
#define QSCALE (0.125f * 1.44269504f)

// ---------------- scratch (device globals; no allocation allowed) ----------
__device__ __half g_X16[MROWS * D_MODEL];
__device__ __half g_O16[MROWS * D_MODEL];
__device__ __half g_Q16[MROWS * D_MODEL];
__device__ __half g_K16[MROWS * D_MODEL];
__device__ __half g_V16[MROWS * D_MODEL];
__device__ __half g_W16[4 * D_MODEL * D_MODEL];

// ---------------- helpers ---------------------------------------------------
__device__ __forceinline__ uint32_t s_u32(const void* p) {
    return (uint32_t)__cvta_generic_to_shared(p);
}

#define LDSM4(r0, r1, r2, r3, a)                                              \
    asm volatile("ldmatrix.sync.aligned.m8n8.x4.shared.b16 {%0,%1,%2,%3},[%4];"\
        : "=r"(r0), "=r"(r1), "=r"(r2), "=r"(r3) : "r"(a))

#define LDSM4T(r0, r1, r2, r3, a)                                             \
    asm volatile("ldmatrix.sync.aligned.m8n8.x4.trans.shared.b16 {%0,%1,%2,%3},[%4];"\
        : "=r"(r0), "=r"(r1), "=r"(r2), "=r"(r3) : "r"(a))

#define MMA_FP16(c, a, b)                                                     \
    asm("mma.sync.aligned.m16n8k16.row.col.f32.f16.f16.f32 "                  \
        "{%0,%1,%2,%3}, {%4,%5,%6,%7}, {%8,%9}, {%0,%1,%2,%3};"               \
        : "+f"((c)[0]), "+f"((c)[1]), "+f"((c)[2]), "+f"((c)[3])              \
        : "r"((a)[0]), "r"((a)[1]), "r"((a)[2]), "r"((a)[3]),                 \
          "r"((b)[0]), "r"((b)[1]))

#define CP_ASYNC16(dst, src)                                                  \
    asm volatile("cp.async.cg.shared.global [%0], [%1], 16;"                  \
        :: "r"(dst), "l"(src))
#define CP_COMMIT   asm volatile("cp.async.commit_group;")
#define CP_WAIT1    asm volatile("cp.async.wait_group 1;")
#define CP_WAIT0    asm volatile("cp.async.wait_group 0;")

__device__ __forceinline__ float ex2f(float x) {
    float r;
    asm("ex2.approx.f32 %0, %1;" : "=f"(r) : "f"(x));
    return r;
}

__device__ __forceinline__ uint32_t f2h2(float a, float b) {
    __half2 h = __floats2half2_rn(a, b);
    return *reinterpret_cast<uint32_t*>(&h);
}

// ============================================================================
// converters
// ============================================================================
__global__ void convert_h4(const float4* __restrict__ src,
                           uint2* __restrict__ dst, int n4)
{
    int i = blockIdx.x * blockDim.x + threadIdx.x;
    if (i >= n4) return;
    float4 v = src[i];
    uint2 d;
    d.x = f2h2(v.x, v.y);
    d.y = f2h2(v.z, v.w);
    dst[i] = d;
}

__global__ void convert_weights4(const float4* __restrict__ w0,
                                 const float4* __restrict__ w1,
                                 const float4* __restrict__ w2,
                                 const float4* __restrict__ w3,
                                 uint2* __restrict__ W, int n4)
{
    int i = blockIdx.x * blockDim.x + threadIdx.x;
    if (i >= n4) return;
    int z = blockIdx.y;
    const float4* src = (z == 0) ? w0 : (z == 1) ? w1 : (z == 2) ? w2 : w3;
    float4 v = src[i];
    uint2 d;
    d.x = f2h2(v.x, v.y);
    d.y = f2h2(v.z, v.w);
    W[(size_t)z * n4 + i] = d;
}

// ============================================================================
// fp16 GEMM: C = A @ W^T + bias (single fp16 W). 128x128 tile, BK=32,
// 8 warps, cp.async double buffer, fp32 accum.
// mode 0: fp32 out (O-proj)
// mode 1: RoPE(acc+bias)*QSCALE -> fp16 (Q)
// mode 2: RoPE(acc+bias)        -> fp16 (K)
// mode 3: (acc+bias)            -> fp16 (V)
// ============================================================================
#define GSTR    40                 // smem row stride (halves): 32 data + 8 pad
#define G_ARR   (128 * GSTR)
#define G_STAGE (2 * G_ARR)
#define GEMM_SMEM (2 * G_STAGE * 2)   // 40960 bytes

__device__ __forceinline__ void gemm_prefetch(
    __half* st, const __half* __restrict__ A, const __half* __restrict__ W,
    int rowBase, int colBase, int kt, int tid)
{
#pragma unroll
    for (int p = 0; p < 2; p++) {
        int id = tid + p * 256;
        int r  = id >> 2;
        int q  = (id & 3) * 8;
        int so = r * GSTR + q;
        CP_ASYNC16(s_u32(st + so),
                   A + (size_t)(rowBase + r) * D_MODEL + kt + q);
        CP_ASYNC16(s_u32(st + G_ARR + so),
                   W + (size_t)(colBase + r) * D_MODEL + kt + q);
    }
}

__device__ __forceinline__ void gemm_body(
    const __half* __restrict__ A, const __half* __restrict__ W,
    const float* __restrict__ bias, float* __restrict__ C,
    __half* __restrict__ D, int mode, __half* sm)
{
    const int tid  = threadIdx.x;
    const int lane = tid & 31;
    const int wrp  = tid >> 5;
    const int g    = lane >> 2;
    const int t    = lane & 3;
    const int wm   = (wrp & 1) * 64;
    const int wn   = (wrp >> 1) * 32;
    const int rowBase = blockIdx.y * 128;
    const int colBase = blockIdx.x * 128;

    const int arow = (lane & 15);
    const int akoA = ((lane >> 4) << 3);
    const int brow = ((lane >> 4) << 3) + (lane & 7);
    const int bkoB = ((lane >> 3) & 1) * 8;

    float c[4][4][4];
#pragma unroll
    for (int i = 0; i < 4; i++)
#pragma unroll
        for (int j = 0; j < 4; j++)
#pragma unroll
            for (int e = 0; e < 4; e++) c[i][j][e] = 0.0f;

    gemm_prefetch(sm, A, W, rowBase, colBase, 0, tid);
    CP_COMMIT;

    const int NK = D_MODEL / 32;
    for (int it = 0; it < NK; it++) {
        __syncthreads();
        if (it + 1 < NK) {
            gemm_prefetch(sm + ((it + 1) & 1) * G_STAGE, A, W,
                          rowBase, colBase, (it + 1) * 32, tid);
            CP_COMMIT;
            CP_WAIT1;
        } else {
            CP_WAIT0;
        }
        __syncthreads();

        __half* st = sm + (it & 1) * G_STAGE;
        __half* sA = st;
        __half* sW = st + G_ARR;

#pragma unroll
        for (int kk = 0; kk < 2; kk++) {
            uint32_t ar[4][4], bb[4][2];
#pragma unroll
            for (int i = 0; i < 4; i++) {
                uint32_t a = s_u32(&sA[(wm + 16 * i + arow) * GSTR + kk * 16 + akoA]);
                LDSM4(ar[i][0], ar[i][1], ar[i][2], ar[i][3], a);
            }
#pragma unroll
            for (int jj = 0; jj < 2; jj++) {
                uint32_t a = s_u32(&sW[(wn + 16 * jj + brow) * GSTR + kk * 16 + bkoB]);
                LDSM4(bb[2*jj][0], bb[2*jj][1], bb[2*jj+1][0], bb[2*jj+1][1], a);
            }
#pragma unroll
            for (int i = 0; i < 4; i++)
#pragma unroll
                for (int j = 0; j < 4; j++) MMA_FP16(c[i][j], ar[i], bb[j]);
        }
    }

    // ---- fused epilogue ----
#pragma unroll
    for (int i = 0; i < 4; i++) {
        int row = rowBase + wm + i * 16 + g;
        int s0  = row & (SEQ - 1);
        int s1  = (row + 8) & (SEQ - 1);
#pragma unroll
        for (int j = 0; j < 4; j++) {
            int col = colBase + wn + j * 8 + 2 * t;
            float b0 = bias[col], b1 = bias[col + 1];
            float x0 = c[i][j][0] + b0, x1 = c[i][j][1] + b1;
            float y0 = c[i][j][2] + b0, y1 = c[i][j][3] + b1;
            size_t i0 = (size_t)row * D_MODEL + col;
            size_t i1 = i0 + (size_t)8 * D_MODEL;
            if (mode == 0) {
                *reinterpret_cast<float2*>(&C[i0]) = make_float2(x0, x1);
                *reinterpret_cast<float2*>(&C[i1]) = make_float2(y0, y1);
            } else if (mode == 3) {
                *(uint32_t*)&D[i0] = f2h2(x0, x1);
                *(uint32_t*)&D[i1] = f2h2(y0, y1);
            } else {
                int p = (col & 63) >> 1;
                float freq = powf(10000.0f, -(float)p * (1.0f / 32.0f));
                float sn0, cs0, sn1, cs1;
                sincosf((float)s0 * freq, &sn0, &cs0);
                sincosf((float)s1 * freq, &sn1, &cs1);
                float r0a = x0 * cs0 - x1 * sn0;
                float r0b = x1 * cs0 + x0 * sn0;
                float r1a = y0 * cs1 - y1 * sn1;
                float r1b = y1 * cs1 + y0 * sn1;
                if (mode == 1) {
                    r0a *= QSCALE; r0b *= QSCALE;
                    r1a *= QSCALE; r1b *= QSCALE;
                }
                *(uint32_t*)&D[i0] = f2h2(r0a, r0b);
                *(uint32_t*)&D[i1] = f2h2(r1a, r1b);
            }
        }
    }
}

// QKV fused: z=0 -> Q (mode 1), z=1 -> K (mode 2), z=2 -> V (mode 3)
__global__ __launch_bounds__(256, 2) void gemm_qkv(
    const __half* __restrict__ A, const __half* __restrict__ WB,
    const float* __restrict__ b0, const float* __restrict__ b1, const float* __restrict__ b2,
    __half* __restrict__ Q16, __half* __restrict__ K16, __half* __restrict__ V16)
{
    extern __shared__ __half smg[];
    const int z = blockIdx.z;
    const size_t WSZ = (size_t)D_MODEL * D_MODEL;
    const float* bias = (z == 0) ? b0 : (z == 1) ? b1 : b2;
    __half* D = (z == 0) ? Q16 : (z == 1) ? K16 : V16;
    gemm_body(A, WB + z * WSZ, bias, (float*)0, D, z + 1, smg);
}

__global__ __launch_bounds__(256, 2) void gemm_out(
    const __half* __restrict__ A, const __half* __restrict__ W,
    const float* __restrict__ bias, float* __restrict__ C)
{
    extern __shared__ __half smg[];
    gemm_body(A, W, bias, C, (__half*)0, 0, smg);
}

// ============================================================================
// Tensor-core flash attention (all single fp16):
// S = Q @ K^T, softmax in exp2 domain, O += P @ V. occupancy 2.
// ============================================================================
#define ATS     72
#define A_ARR   (64 * ATS)
#define A_STAGE (2 * A_ARR)               // K, V
#define ATT_SMEM (2 * A_STAGE * 2)        // 36864 bytes

__device__ __forceinline__ void att_prefetch(
    __half* st, const __half* __restrict__ K16, const __half* __restrict__ V16,
    size_t gbase, int kv0, int tid)
{
    int r  = tid >> 2;                 // 0..63 (two rows per 8 threads? no: 256/4)
    int cq = (tid & 3) * 16;           // 0,16,32,48
#pragma unroll
    for (int p = 0; p < 1; p++) { }
    // 64 rows x 64 halves = 64x128B; 256 threads x 16B covers K; same for V.
    {
        int so = r * ATS + cq;
        size_t gk = gbase + (size_t)(kv0 + r) * D_MODEL + cq;
        CP_ASYNC16(s_u32(st + so),          K16 + gk);
        CP_ASYNC16(s_u32(st + so + 8),      K16 + gk + 8);
        CP_ASYNC16(s_u32(st + A_ARR + so),     V16 + gk);
        CP_ASYNC16(s_u32(st + A_ARR + so + 8), V16 + gk + 8);
    }
}

__global__ __launch_bounds__(256, 2) void attention_mma(
    const __half* __restrict__ Q16, const __half* __restrict__ K16,
    const __half* __restrict__ V16, __half* __restrict__ O16)
{
    extern __shared__ __half sKV[];

    const int bh = blockIdx.y;
    const int b  = bh >> 4;
    const int h  = bh & 15;
    const int q0 = blockIdx.x * 128;
    const int tid  = threadIdx.x;
    const int lane = tid & 31;
    const int wrp  = tid >> 5;
    const int g    = lane >> 2;
    const int t    = lane & 3;

    const size_t gbase = (size_t)b * SEQ * D_MODEL + (size_t)h * DKH;

    att_prefetch(sKV, K16, V16, gbase, 0, tid);
    CP_COMMIT;

    // ---- Q fragments directly from gmem (A-frag layout) ----
    uint32_t qf[4][4];
    {
        const int r0 = q0 + 16 * wrp + g;
        size_t ro0 = gbase + (size_t)r0 * D_MODEL;
        size_t ro8 = ro0 + (size_t)8 * D_MODEL;
#pragma unroll
        for (int kc = 0; kc < 4; kc++) {
            int cw = kc * 16 + 2 * t;
            qf[kc][0] = *(const uint32_t*)&Q16[ro0 + cw];
            qf[kc][1] = *(const uint32_t*)&Q16[ro8 + cw];
            qf[kc][2] = *(const uint32_t*)&Q16[ro0 + cw + 8];
            qf[kc][3] = *(const uint32_t*)&Q16[ro8 + cw + 8];
        }
    }

    float m[2] = {-INFINITY, -INFINITY};
    float l[2] = {0.0f, 0.0f};
    float o[8][4];
#pragma unroll
    for (int j = 0; j < 8; j++)
#pragma unroll
        for (int e = 0; e < 4; e++) o[j][e] = 0.0f;

    const int brow  = ((lane >> 4) << 3) + (lane & 7);
    const int bko   = ((lane >> 3) & 1) * 8;
    const int vrow  = (lane & 7) + ((lane >> 3) & 1) * 8;
    const int vcol  = ((lane >> 4) << 3);

    const int NT = SEQ / 64;
    for (int it = 0; it < NT; it++) {
        __syncthreads();
        if (it + 1 < NT) {
            att_prefetch(sKV + ((it + 1) & 1) * A_STAGE, K16, V16,
                         gbase, (it + 1) * 64, tid);
            CP_COMMIT;
            CP_WAIT1;
        } else {
            CP_WAIT0;
        }
        __syncthreads();

        __half* st = sKV + (it & 1) * A_STAGE;
        __half* sK = st;
        __half* sV = st + A_ARR;

        // ---- S = Q @ K^T (single fp16 term) ----
        float s[8][4];
#pragma unroll
        for (int j = 0; j < 8; j++)
#pragma unroll
            for (int e = 0; e < 4; e++) s[j][e] = 0.0f;

#pragma unroll
        for (int kc = 0; kc < 4; kc++) {
            uint32_t kb[8][2];
#pragma unroll
            for (int jj = 0; jj < 4; jj++) {
                uint32_t a = s_u32(&sK[(16 * jj + brow) * ATS + kc * 16 + bko]);
                LDSM4(kb[2*jj][0], kb[2*jj][1], kb[2*jj+1][0], kb[2*jj+1][1], a);
            }
#pragma unroll
            for (int j = 0; j < 8; j++) MMA_FP16(s[j], qf[kc], kb[j]);
        }

        // ---- online softmax (exp2 domain, tree max, deferred l) ----
        float alpha[2];
#pragma unroll
        for (int e = 0; e < 2; e++) {
            float a0 = fmaxf(s[0][2*e], s[0][2*e+1]);
            float a1 = fmaxf(s[1][2*e], s[1][2*e+1]);
            float a2 = fmaxf(s[2][2*e], s[2][2*e+1]);
            float a3 = fmaxf(s[3][2*e], s[3][2*e+1]);
            float a4 = fmaxf(s[4][2*e], s[4][2*e+1]);
            float a5 = fmaxf(s[5][2*e], s[5][2*e+1]);
            float a6 = fmaxf(s[6][2*e], s[6][2*e+1]);
            float a7 = fmaxf(s[7][2*e], s[7][2*e+1]);
            a0 = fmaxf(a0, a1); a2 = fmaxf(a2, a3);
            a4 = fmaxf(a4, a5); a6 = fmaxf(a6, a7);
            float mloc = fmaxf(fmaxf(a0, a2), fmaxf(a4, a6));
            mloc = fmaxf(mloc, __shfl_xor_sync(0xffffffffu, mloc, 1));
            mloc = fmaxf(mloc, __shfl_xor_sync(0xffffffffu, mloc, 2));
            float mnew = fmaxf(m[e], mloc);
            alpha[e] = ex2f(m[e] - mnew);
            float ls0 = 0.0f, ls1 = 0.0f, ls2 = 0.0f, ls3 = 0.0f;
#pragma unroll
            for (int j = 0; j < 8; j += 2) {
                float p0 = ex2f(s[j][2*e]     - mnew);
                float p1 = ex2f(s[j][2*e+1]   - mnew);
                float p2 = ex2f(s[j+1][2*e]   - mnew);
                float p3 = ex2f(s[j+1][2*e+1] - mnew);
                s[j][2*e]     = p0; s[j][2*e+1]   = p1;
                s[j+1][2*e]   = p2; s[j+1][2*e+1] = p3;
                ls0 += p0; ls1 += p1; ls2 += p2; ls3 += p3;
            }
            l[e] = l[e] * alpha[e] + ((ls0 + ls1) + (ls2 + ls3));
            m[e] = mnew;
        }
#pragma unroll
        for (int j = 0; j < 8; j++) {
            o[j][0] *= alpha[0]; o[j][1] *= alpha[0];
            o[j][2] *= alpha[1]; o[j][3] *= alpha[1];
        }

        // ---- P fragments: fp16 (A-frag layout) ----
        uint32_t pa[4][4];
#pragma unroll
        for (int kc = 0; kc < 4; kc++) {
            pa[kc][0] = f2h2(s[2*kc][0],   s[2*kc][1]);
            pa[kc][1] = f2h2(s[2*kc][2],   s[2*kc][3]);
            pa[kc][2] = f2h2(s[2*kc+1][0], s[2*kc+1][1]);
            pa[kc][3] = f2h2(s[2*kc+1][2], s[2*kc+1][3]);
        }

        // ---- O += P @ V ----
#pragma unroll
        for (int kc = 0; kc < 4; kc++) {
            uint32_t vb[8][2];
#pragma unroll
            for (int jj = 0; jj < 4; jj++) {
                uint32_t a = s_u32(&sV[(kc * 16 + vrow) * ATS + 16 * jj + vcol]);
                LDSM4T(vb[2*jj][0], vb[2*jj][1], vb[2*jj+1][0], vb[2*jj+1][1], a);
            }
#pragma unroll
            for (int j = 0; j < 8; j++) MMA_FP16(o[j], pa[kc], vb[j]);
        }
    }

    // ---- epilogue: quad-reduce l, normalize, write fp16 O ----
    l[0] += __shfl_xor_sync(0xffffffffu, l[0], 1);
    l[0] += __shfl_xor_sync(0xffffffffu, l[0], 2);
    l[1] += __shfl_xor_sync(0xffffffffu, l[1], 1);
    l[1] += __shfl_xor_sync(0xffffffffu, l[1], 2);

    const int r0 = q0 + 16 * wrp + g;
    const float inv0 = 1.0f / l[0];
    const float inv1 = 1.0f / l[1];
#pragma unroll
    for (int j = 0; j < 8; j++) {
        int col = h * DKH + 8 * j + 2 * t;
        size_t i0 = (size_t)b * SEQ * D_MODEL + (size_t)r0 * D_MODEL + col;
        size_t i1 = i0 + (size_t)8 * D_MODEL;
        *(uint32_t*)&O16[i0] = f2h2(o[j][0] * inv0, o[j][1] * inv0);
        *(uint32_t*)&O16[i1] = f2h2(o[j][2] * inv1, o[j][3] * inv1);
    }
}

// ============================================================================
// Launch
// ============================================================================
extern "C" void kernel_launch(void* const* d_in, const int* in_sizes, int n_in,
                              void* d_out, int out_size)
{
    (void)in_sizes; (void)n_in; (void)out_size;
    const float* x  = (const float*)d_in[0];
    const float* wq = (const float*)d_in[1];
    const float* bq = (const float*)d_in[2];
    const float* wk = (const float*)d_in[3];
    const float* bk = (const float*)d_in[4];
    const float* wv = (const float*)d_in[5];
    const float* bv = (const float*)d_in[6];
    const float* wo = (const float*)d_in[7];
    const float* bo = (const float*)d_in[8];
    float* out = (float*)d_out;

    __half *X16, *O16, *Q16, *K16, *V16, *W16;
    cudaGetSymbolAddress((void**)&X16, g_X16);
    cudaGetSymbolAddress((void**)&O16, g_O16);
    cudaGetSymbolAddress((void**)&Q16, g_Q16);
    cudaGetSymbolAddress((void**)&K16, g_K16);
    cudaGetSymbolAddress((void**)&V16, g_V16);
    cudaGetSymbolAddress((void**)&W16, g_W16);

    cudaFuncSetAttribute(attention_mma,
                         cudaFuncAttributeMaxDynamicSharedMemorySize, ATT_SMEM);
    cudaFuncSetAttribute(gemm_qkv,
                         cudaFuncAttributeMaxDynamicSharedMemorySize, GEMM_SMEM);
    cudaFuncSetAttribute(gemm_out,
                         cudaFuncAttributeMaxDynamicSharedMemorySize, GEMM_SMEM);

    const size_t WSZ = (size_t)D_MODEL * D_MODEL;

    int n4x = (MROWS * D_MODEL) / 4;
    int n4w = (int)(WSZ / 4);
    convert_h4<<<(n4x + 255) / 256, 256>>>((const float4*)x, (uint2*)X16, n4x);
    dim3 wgrid((n4w + 255) / 256, 4);
    convert_weights4<<<wgrid, 256>>>((const float4*)wq, (const float4*)wk,
                                     (const float4*)wv, (const float4*)wo,
                                     (uint2*)W16, n4w);

    // fused QKV projections
    dim3 qkvgrid(D_MODEL / 128, MROWS / 128, 3);
    gemm_qkv<<<qkvgrid, 256, GEMM_SMEM>>>(X16, W16, bq, bk, bv, Q16, K16, V16);

    // tensor-core flash attention
    dim3 agrid(SEQ / 128, BATCH * NUM_HEADS);
    attention_mma<<<agrid, 256, ATT_SMEM>>>(Q16, K16, V16, O16);

    // output projection
    dim3 ogrid(D_MODEL / 128, MROWS / 128);
    gemm_out<<<ogrid, 256, GEMM_SMEM>>>(O16, W16 + 3 * WSZ, bo, out);
}

// round 15
// speedup vs baseline: 8.6663x; 1.0711x over previous
#include <cuda_runtime.h>
#include <cuda_fp16.h>
#include <math.h>
#include <stdint.h>

#define D_MODEL   1024
#define NUM_HEADS 16
#define DKH       64
#define BATCH     2
#define SEQ       2048
#define MROWS     (BATCH * SEQ)   // 4096

// Q pre-scale: 1/sqrt(dk) * log2(e)  (softmax runs in exp2 domain)
#define QSCALE (0.125f * 1.44269504f)

// ---------------- scratch (device globals; no allocation allowed) ----------
__device__ __half g_X16[MROWS * D_MODEL];
__device__ __half g_O16[MROWS * D_MODEL];
__device__ __half g_Q16[MROWS * D_MODEL];
__device__ __half g_K16[MROWS * D_MODEL];
__device__ __half g_V16[MROWS * D_MODEL];
__device__ __half g_W16[4 * D_MODEL * D_MODEL];

// ---------------- helpers ---------------------------------------------------
__device__ __forceinline__ uint32_t s_u32(const void* p) {
    return (uint32_t)__cvta_generic_to_shared(p);
}

#define LDSM4(r0, r1, r2, r3, a)                                              \
    asm volatile("ldmatrix.sync.aligned.m8n8.x4.shared.b16 {%0,%1,%2,%3},[%4];"\
        : "=r"(r0), "=r"(r1), "=r"(r2), "=r"(r3) : "r"(a))

#define LDSM4T(r0, r1, r2, r3, a)                                             \
    asm volatile("ldmatrix.sync.aligned.m8n8.x4.trans.shared.b16 {%0,%1,%2,%3},[%4];"\
        : "=r"(r0), "=r"(r1), "=r"(r2), "=r"(r3) : "r"(a))

#define MMA_FP16(c, a, b)                                                     \
    asm("mma.sync.aligned.m16n8k16.row.col.f32.f16.f16.f32 "                  \
        "{%0,%1,%2,%3}, {%4,%5,%6,%7}, {%8,%9}, {%0,%1,%2,%3};"               \
        : "+f"((c)[0]), "+f"((c)[1]), "+f"((c)[2]), "+f"((c)[3])              \
        : "r"((a)[0]), "r"((a)[1]), "r"((a)[2]), "r"((a)[3]),                 \
          "r"((b)[0]), "r"((b)[1]))

#define CP_ASYNC16(dst, src)                                                  \
    asm volatile("cp.async.cg.shared.global [%0], [%1], 16;"                  \
        :: "r"(dst), "l"(src))
#define CP_COMMIT   asm volatile("cp.async.commit_group;")
#define CP_WAIT0    asm volatile("cp.async.wait_group 0;")

__device__ __forceinline__ float ex2f(float x) {
    float r;
    asm("ex2.approx.f32 %0, %1;" : "=f"(r) : "f"(x));
    return r;
}

// packed fp16 exp2: d.lo = 2^a.lo, d.hi = 2^a.hi
__device__ __forceinline__ uint32_t h2ex2(uint32_t a) {
    uint32_t d;
    asm("ex2.approx.f16x2 %0, %1;" : "=r"(d) : "r"(a));
    return d;
}

__device__ __forceinline__ uint32_t hadd2(uint32_t a, uint32_t b) {
    uint32_t d;
    asm("add.f16x2 %0, %1, %2;" : "=r"(d) : "r"(a), "r"(b));
    return d;
}

__device__ __forceinline__ uint32_t f2h2(float a, float b) {
    __half2 h = __floats2half2_rn(a, b);
    return *reinterpret_cast<uint32_t*>(&h);
}

// ============================================================================
// converters
// ============================================================================
__global__ void convert_h4(const float4* __restrict__ src,
                           uint2* __restrict__ dst, int n4)
{
    int i = blockIdx.x * blockDim.x + threadIdx.x;
    if (i >= n4) return;
    float4 v = src[i];
    uint2 d;
    d.x = f2h2(v.x, v.y);
    d.y = f2h2(v.z, v.w);
    dst[i] = d;
}

__global__ void convert_weights4(const float4* __restrict__ w0,
                                 const float4* __restrict__ w1,
                                 const float4* __restrict__ w2,
                                 const float4* __restrict__ w3,
                                 uint2* __restrict__ W, int n4)
{
    int i = blockIdx.x * blockDim.x + threadIdx.x;
    if (i >= n4) return;
    int z = blockIdx.y;
    const float4* src = (z == 0) ? w0 : (z == 1) ? w1 : (z == 2) ? w2 : w3;
    float4 v = src[i];
    uint2 d;
    d.x = f2h2(v.x, v.y);
    d.y = f2h2(v.z, v.w);
    W[(size_t)z * n4 + i] = d;
}

// ============================================================================
// fp16 GEMM: C = A @ W^T + bias. 128x128 tile, BK=32, 8 warps,
// cp.async double buffer (single barrier per iter), fp32 accum.
// mode 0: fp32 out (O-proj)
// mode 1: RoPE(acc+bias)*QSCALE -> fp16 (Q)
// mode 2: RoPE(acc+bias)        -> fp16 (K)
// mode 3: (acc+bias)            -> fp16 (V)
// ============================================================================
#define GSTR    40                 // smem row stride (halves): 32 data + 8 pad
#define G_ARR   (128 * GSTR)
#define G_STAGE (2 * G_ARR)
#define GEMM_SMEM (2 * G_STAGE * 2)   // 40960 bytes

__device__ __forceinline__ void gemm_prefetch(
    __half* st, const __half* __restrict__ A, const __half* __restrict__ W,
    int rowBase, int colBase, int kt, int tid)
{
#pragma unroll
    for (int p = 0; p < 2; p++) {
        int id = tid + p * 256;
        int r  = id >> 2;
        int q  = (id & 3) * 8;
        int so = r * GSTR + q;
        CP_ASYNC16(s_u32(st + so),
                   A + (size_t)(rowBase + r) * D_MODEL + kt + q);
        CP_ASYNC16(s_u32(st + G_ARR + so),
                   W + (size_t)(colBase + r) * D_MODEL + kt + q);
    }
}

__device__ __forceinline__ void gemm_body(
    const __half* __restrict__ A, const __half* __restrict__ W,
    const float* __restrict__ bias, float* __restrict__ C,
    __half* __restrict__ D, int mode, __half* sm)
{
    const int tid  = threadIdx.x;
    const int lane = tid & 31;
    const int wrp  = tid >> 5;
    const int g    = lane >> 2;
    const int t    = lane & 3;
    const int wm   = (wrp & 1) * 64;
    const int wn   = (wrp >> 1) * 32;
    const int rowBase = blockIdx.y * 128;
    const int colBase = blockIdx.x * 128;

    const int arow = (lane & 15);
    const int akoA = ((lane >> 4) << 3);
    const int brow = ((lane >> 4) << 3) + (lane & 7);
    const int bkoB = ((lane >> 3) & 1) * 8;

    float c[4][4][4];
#pragma unroll
    for (int i = 0; i < 4; i++)
#pragma unroll
        for (int j = 0; j < 4; j++)
#pragma unroll
            for (int e = 0; e < 4; e++) c[i][j][e] = 0.0f;

    gemm_prefetch(sm, A, W, rowBase, colBase, 0, tid);
    CP_COMMIT;

    const int NK = D_MODEL / 32;
    for (int it = 0; it < NK; it++) {
        CP_WAIT0;          // stage it landed (this thread's view)
        __syncthreads();   // visible to all; everyone done reading other stage
        if (it + 1 < NK) {
            gemm_prefetch(sm + ((it + 1) & 1) * G_STAGE, A, W,
                          rowBase, colBase, (it + 1) * 32, tid);
            CP_COMMIT;
        }

        __half* st = sm + (it & 1) * G_STAGE;
        __half* sA = st;
        __half* sW = st + G_ARR;

#pragma unroll
        for (int kk = 0; kk < 2; kk++) {
            uint32_t ar[4][4], bb[4][2];
#pragma unroll
            for (int i = 0; i < 4; i++) {
                uint32_t a = s_u32(&sA[(wm + 16 * i + arow) * GSTR + kk * 16 + akoA]);
                LDSM4(ar[i][0], ar[i][1], ar[i][2], ar[i][3], a);
            }
#pragma unroll
            for (int jj = 0; jj < 2; jj++) {
                uint32_t a = s_u32(&sW[(wn + 16 * jj + brow) * GSTR + kk * 16 + bkoB]);
                LDSM4(bb[2*jj][0], bb[2*jj][1], bb[2*jj+1][0], bb[2*jj+1][1], a);
            }
#pragma unroll
            for (int i = 0; i < 4; i++)
#pragma unroll
                for (int j = 0; j < 4; j++) MMA_FP16(c[i][j], ar[i], bb[j]);
        }
    }

    // ---- fused epilogue ----
#pragma unroll
    for (int i = 0; i < 4; i++) {
        int row = rowBase + wm + i * 16 + g;
        int s0  = row & (SEQ - 1);
        int s1  = (row + 8) & (SEQ - 1);
#pragma unroll
        for (int j = 0; j < 4; j++) {
            int col = colBase + wn + j * 8 + 2 * t;
            float b0 = bias[col], b1 = bias[col + 1];
            float x0 = c[i][j][0] + b0, x1 = c[i][j][1] + b1;
            float y0 = c[i][j][2] + b0, y1 = c[i][j][3] + b1;
            size_t i0 = (size_t)row * D_MODEL + col;
            size_t i1 = i0 + (size_t)8 * D_MODEL;
            if (mode == 0) {
                *reinterpret_cast<float2*>(&C[i0]) = make_float2(x0, x1);
                *reinterpret_cast<float2*>(&C[i1]) = make_float2(y0, y1);
            } else if (mode == 3) {
                *(uint32_t*)&D[i0] = f2h2(x0, x1);
                *(uint32_t*)&D[i1] = f2h2(y0, y1);
            } else {
                int p = (col & 63) >> 1;
                float freq = powf(10000.0f, -(float)p * (1.0f / 32.0f));
                float sn0, cs0, sn1, cs1;
                sincosf((float)s0 * freq, &sn0, &cs0);
                sincosf((float)s1 * freq, &sn1, &cs1);
                float r0a = x0 * cs0 - x1 * sn0;
                float r0b = x1 * cs0 + x0 * sn0;
                float r1a = y0 * cs1 - y1 * sn1;
                float r1b = y1 * cs1 + y0 * sn1;
                if (mode == 1) {
                    r0a *= QSCALE; r0b *= QSCALE;
                    r1a *= QSCALE; r1b *= QSCALE;
                }
                *(uint32_t*)&D[i0] = f2h2(r0a, r0b);
                *(uint32_t*)&D[i1] = f2h2(r1a, r1b);
            }
        }
    }
}

__global__ __launch_bounds__(256, 2) void gemm_qkv(
    const __half* __restrict__ A, const __half* __restrict__ WB,
    const float* __restrict__ b0, const float* __restrict__ b1, const float* __restrict__ b2,
    __half* __restrict__ Q16, __half* __restrict__ K16, __half* __restrict__ V16)
{
    extern __shared__ __half smg[];
    const int z = blockIdx.z;
    const size_t WSZ = (size_t)D_MODEL * D_MODEL;
    const float* bias = (z == 0) ? b0 : (z == 1) ? b1 : b2;
    __half* D = (z == 0) ? Q16 : (z == 1) ? K16 : V16;
    gemm_body(A, WB + z * WSZ, bias, (float*)0, D, z + 1, smg);
}

__global__ __launch_bounds__(256, 2) void gemm_out(
    const __half* __restrict__ A, const __half* __restrict__ W,
    const float* __restrict__ bias, float* __restrict__ C)
{
    extern __shared__ __half smg[];
    gemm_body(A, W, bias, C, (__half*)0, 0, smg);
}

// ============================================================================
// Tensor-core flash attention (all fp16):
// S = Q @ K^T, softmax via ex2.approx.f16x2 (P born as fp16 A-fragments),
// l-sum via HADD2 tree, O += P @ V. Single barrier per tile. occupancy 2.
// ============================================================================
#define ATS     72
#define A_ARR   (64 * ATS)
#define A_STAGE (2 * A_ARR)               // K, V
#define ATT_SMEM (2 * A_STAGE * 2)        // 36864 bytes

__device__ __forceinline__ void att_prefetch(
    __half* st, const __half* __restrict__ K16, const __half* __restrict__ V16,
    size_t gbase, int kv0, int tid)
{
    int r  = tid >> 2;                 // 0..63
    int cq = (tid & 3) * 16;           // 0,16,32,48
    int so = r * ATS + cq;
    size_t gk = gbase + (size_t)(kv0 + r) * D_MODEL + cq;
    CP_ASYNC16(s_u32(st + so),             K16 + gk);
    CP_ASYNC16(s_u32(st + so + 8),         K16 + gk + 8);
    CP_ASYNC16(s_u32(st + A_ARR + so),     V16 + gk);
    CP_ASYNC16(s_u32(st + A_ARR + so + 8), V16 + gk + 8);
}

__global__ __launch_bounds__(256, 2) void attention_mma(
    const __half* __restrict__ Q16, const __half* __restrict__ K16,
    const __half* __restrict__ V16, __half* __restrict__ O16)
{
    extern __shared__ __half sKV[];

    const int bh = blockIdx.y;
    const int b  = bh >> 4;
    const int h  = bh & 15;
    const int q0 = blockIdx.x * 128;
    const int tid  = threadIdx.x;
    const int lane = tid & 31;
    const int wrp  = tid >> 5;
    const int g    = lane >> 2;
    const int t    = lane & 3;

    const size_t gbase = (size_t)b * SEQ * D_MODEL + (size_t)h * DKH;

    att_prefetch(sKV, K16, V16, gbase, 0, tid);
    CP_COMMIT;

    // ---- Q fragments directly from gmem (A-frag layout) ----
    uint32_t qf[4][4];
    {
        const int r0 = q0 + 16 * wrp + g;
        size_t ro0 = gbase + (size_t)r0 * D_MODEL;
        size_t ro8 = ro0 + (size_t)8 * D_MODEL;
#pragma unroll
        for (int kc = 0; kc < 4; kc++) {
            int cw = kc * 16 + 2 * t;
            qf[kc][0] = *(const uint32_t*)&Q16[ro0 + cw];
            qf[kc][1] = *(const uint32_t*)&Q16[ro8 + cw];
            qf[kc][2] = *(const uint32_t*)&Q16[ro0 + cw + 8];
            qf[kc][3] = *(const uint32_t*)&Q16[ro8 + cw + 8];
        }
    }

    float m[2] = {-INFINITY, -INFINITY};
    float l[2] = {0.0f, 0.0f};
    float o[8][4];
#pragma unroll
    for (int j = 0; j < 8; j++)
#pragma unroll
        for (int e = 0; e < 4; e++) o[j][e] = 0.0f;

    const int brow  = ((lane >> 4) << 3) + (lane & 7);
    const int bko   = ((lane >> 3) & 1) * 8;
    const int vrow  = (lane & 7) + ((lane >> 3) & 1) * 8;
    const int vcol  = ((lane >> 4) << 3);

    const int NT = SEQ / 64;
    for (int it = 0; it < NT; it++) {
        CP_WAIT0;
        __syncthreads();
        if (it + 1 < NT) {
            att_prefetch(sKV + ((it + 1) & 1) * A_STAGE, K16, V16,
                         gbase, (it + 1) * 64, tid);
            CP_COMMIT;
        }

        __half* st = sKV + (it & 1) * A_STAGE;
        __half* sK = st;
        __half* sV = st + A_ARR;

        // ---- S = Q @ K^T ----
        float s[8][4];
#pragma unroll
        for (int j = 0; j < 8; j++)
#pragma unroll
            for (int e = 0; e < 4; e++) s[j][e] = 0.0f;

#pragma unroll
        for (int kc = 0; kc < 4; kc++) {
            uint32_t kb[8][2];
#pragma unroll
            for (int jj = 0; jj < 4; jj++) {
                uint32_t a = s_u32(&sK[(16 * jj + brow) * ATS + kc * 16 + bko]);
                LDSM4(kb[2*jj][0], kb[2*jj][1], kb[2*jj+1][0], kb[2*jj+1][1], a);
            }
#pragma unroll
            for (int j = 0; j < 8; j++) MMA_FP16(s[j], qf[kc], kb[j]);
        }

        // ---- online softmax: tree max, then P = ex2.f16x2 directly ----
        float alpha[2];
#pragma unroll
        for (int e = 0; e < 2; e++) {
            float a0 = fmaxf(s[0][2*e], s[0][2*e+1]);
            float a1 = fmaxf(s[1][2*e], s[1][2*e+1]);
            float a2 = fmaxf(s[2][2*e], s[2][2*e+1]);
            float a3 = fmaxf(s[3][2*e], s[3][2*e+1]);
            float a4 = fmaxf(s[4][2*e], s[4][2*e+1]);
            float a5 = fmaxf(s[5][2*e], s[5][2*e+1]);
            float a6 = fmaxf(s[6][2*e], s[6][2*e+1]);
            float a7 = fmaxf(s[7][2*e], s[7][2*e+1]);
            a0 = fmaxf(a0, a1); a2 = fmaxf(a2, a3);
            a4 = fmaxf(a4, a5); a6 = fmaxf(a6, a7);
            float mloc = fmaxf(fmaxf(a0, a2), fmaxf(a4, a6));
            mloc = fmaxf(mloc, __shfl_xor_sync(0xffffffffu, mloc, 1));
            mloc = fmaxf(mloc, __shfl_xor_sync(0xffffffffu, mloc, 2));
            float mnew = fmaxf(m[e], mloc);
            alpha[e] = ex2f(m[e] - mnew);
            m[e] = mnew;
        }

        // P fragments born as fp16x2 (A-frag pair layout)
        uint32_t ph[8][2];
#pragma unroll
        for (int j = 0; j < 8; j++) {
            ph[j][0] = h2ex2(f2h2(s[j][0] - m[0], s[j][1] - m[0]));
            ph[j][1] = h2ex2(f2h2(s[j][2] - m[1], s[j][3] - m[1]));
        }

        // l sums via HADD2 tree (lane-parallel column pairs)
#pragma unroll
        for (int e = 0; e < 2; e++) {
            uint32_t t01 = hadd2(ph[0][e], ph[1][e]);
            uint32_t t23 = hadd2(ph[2][e], ph[3][e]);
            uint32_t t45 = hadd2(ph[4][e], ph[5][e]);
            uint32_t t67 = hadd2(ph[6][e], ph[7][e]);
            uint32_t t03 = hadd2(t01, t23);
            uint32_t t47 = hadd2(t45, t67);
            uint32_t tt  = hadd2(t03, t47);
            __half2 hh = *reinterpret_cast<__half2*>(&tt);
            float2 ff = __half22float2(hh);
            l[e] = l[e] * alpha[e] + (ff.x + ff.y);
        }
#pragma unroll
        for (int j = 0; j < 8; j++) {
            o[j][0] *= alpha[0]; o[j][1] *= alpha[0];
            o[j][2] *= alpha[1]; o[j][3] *= alpha[1];
        }

        // ---- O += P @ V ----
#pragma unroll
        for (int kc = 0; kc < 4; kc++) {
            uint32_t pa[4] = {ph[2*kc][0], ph[2*kc][1], ph[2*kc+1][0], ph[2*kc+1][1]};
            uint32_t vb[8][2];
#pragma unroll
            for (int jj = 0; jj < 4; jj++) {
                uint32_t a = s_u32(&sV[(kc * 16 + vrow) * ATS + 16 * jj + vcol]);
                LDSM4T(vb[2*jj][0], vb[2*jj][1], vb[2*jj+1][0], vb[2*jj+1][1], a);
            }
#pragma unroll
            for (int j = 0; j < 8; j++) MMA_FP16(o[j], pa, vb[j]);
        }
    }

    // ---- epilogue: quad-reduce l, normalize, write fp16 O ----
    l[0] += __shfl_xor_sync(0xffffffffu, l[0], 1);
    l[0] += __shfl_xor_sync(0xffffffffu, l[0], 2);
    l[1] += __shfl_xor_sync(0xffffffffu, l[1], 1);
    l[1] += __shfl_xor_sync(0xffffffffu, l[1], 2);

    const int r0 = q0 + 16 * wrp + g;
    const float inv0 = 1.0f / l[0];
    const float inv1 = 1.0f / l[1];
#pragma unroll
    for (int j = 0; j < 8; j++) {
        int col = h * DKH + 8 * j + 2 * t;
        size_t i0 = (size_t)b * SEQ * D_MODEL + (size_t)r0 * D_MODEL + col;
        size_t i1 = i0 + (size_t)8 * D_MODEL;
        *(uint32_t*)&O16[i0] = f2h2(o[j][0] * inv0, o[j][1] * inv0);
        *(uint32_t*)&O16[i1] = f2h2(o[j][2] * inv1, o[j][3] * inv1);
    }
}

// ============================================================================
// Launch
// ============================================================================
extern "C" void kernel_launch(void* const* d_in, const int* in_sizes, int n_in,
                              void* d_out, int out_size)
{
    (void)in_sizes; (void)n_in; (void)out_size;
    const float* x  = (const float*)d_in[0];
    const float* wq = (const float*)d_in[1];
    const float* bq = (const float*)d_in[2];
    const float* wk = (const float*)d_in[3];
    const float* bk = (const float*)d_in[4];
    const float* wv = (const float*)d_in[5];
    const float* bv = (const float*)d_in[6];
    const float* wo = (const float*)d_in[7];
    const float* bo = (const float*)d_in[8];
    float* out = (float*)d_out;

    __half *X16, *O16, *Q16, *K16, *V16, *W16;
    cudaGetSymbolAddress((void**)&X16, g_X16);
    cudaGetSymbolAddress((void**)&O16, g_O16);
    cudaGetSymbolAddress((void**)&Q16, g_Q16);
    cudaGetSymbolAddress((void**)&K16, g_K16);
    cudaGetSymbolAddress((void**)&V16, g_V16);
    cudaGetSymbolAddress((void**)&W16, g_W16);

    cudaFuncSetAttribute(attention_mma,
                         cudaFuncAttributeMaxDynamicSharedMemorySize, ATT_SMEM);
    cudaFuncSetAttribute(gemm_qkv,
                         cudaFuncAttributeMaxDynamicSharedMemorySize, GEMM_SMEM);
    cudaFuncSetAttribute(gemm_out,
                         cudaFuncAttributeMaxDynamicSharedMemorySize, GEMM_SMEM);

    const size_t WSZ = (size_t)D_MODEL * D_MODEL;

    int n4x = (MROWS * D_MODEL) / 4;
    int n4w = (int)(WSZ / 4);
    convert_h4<<<(n4x + 255) / 256, 256>>>((const float4*)x, (uint2*)X16, n4x);
    dim3 wgrid((n4w + 255) / 256, 4);
    convert_weights4<<<wgrid, 256>>>((const float4*)wq, (const float4*)wk,
                                     (const float4*)wv, (const float4*)wo,
                                     (uint2*)W16, n4w);

    // fused QKV projections
    dim3 qkvgrid(D_MODEL / 128, MROWS / 128, 3);
    gemm_qkv<<<qkvgrid, 256, GEMM_SMEM>>>(X16, W16, bq, bk, bv, Q16, K16, V16);

    // tensor-core flash attention
    dim3 agrid(SEQ / 128, BATCH * NUM_HEADS);
    attention_mma<<<agrid, 256, ATT_SMEM>>>(Q16, K16, V16, O16);

    // output projection
    dim3 ogrid(D_MODEL / 128, MROWS / 128);
    gemm_out<<<ogrid, 256, GEMM_SMEM>>>(O16, W16 + 3 * WSZ, bo, out);
}

// round 16
// speedup vs baseline: 9.0703x; 1.0466x over previous
#include <cuda_runtime.h>
#include <cuda_fp16.h>
#include <math.h>
#include <stdint.h>

#define D_MODEL   1024
#define NUM_HEADS 16
#define DKH       64
#define BATCH     2
#define SEQ       2048
#define MROWS     (BATCH * SEQ)   // 4096

// Q pre-scale: 1/sqrt(dk) * log2(e)  (softmax runs in exp2 domain)
#define QSCALE (0.125f * 1.44269504f)

// ---------------- scratch (device globals; no allocation allowed) ----------
__device__ __half g_X16[MROWS * D_MODEL];
__device__ __half g_O16[MROWS * D_MODEL];
__device__ __half g_Q16[MROWS * D_MODEL];
__device__ __half g_K16[MROWS * D_MODEL];
__device__ __half g_V16[MROWS * D_MODEL];
__device__ __half g_W16[4 * D_MODEL * D_MODEL];

// ---------------- helpers ---------------------------------------------------
__device__ __forceinline__ uint32_t s_u32(const void* p) {
    return (uint32_t)__cvta_generic_to_shared(p);
}

#define LDSM4(r0, r1, r2, r3, a)                                              \
    asm volatile("ldmatrix.sync.aligned.m8n8.x4.shared.b16 {%0,%1,%2,%3},[%4];"\
        : "=r"(r0), "=r"(r1), "=r"(r2), "=r"(r3) : "r"(a))

#define LDSM4T(r0, r1, r2, r3, a)                                             \
    asm volatile("ldmatrix.sync.aligned.m8n8.x4.trans.shared.b16 {%0,%1,%2,%3},[%4];"\
        : "=r"(r0), "=r"(r1), "=r"(r2), "=r"(r3) : "r"(a))

#define MMA_FP16(c, a, b)                                                     \
    asm("mma.sync.aligned.m16n8k16.row.col.f32.f16.f16.f32 "                  \
        "{%0,%1,%2,%3}, {%4,%5,%6,%7}, {%8,%9}, {%0,%1,%2,%3};"               \
        : "+f"((c)[0]), "+f"((c)[1]), "+f"((c)[2]), "+f"((c)[3])              \
        : "r"((a)[0]), "r"((a)[1]), "r"((a)[2]), "r"((a)[3]),                 \
          "r"((b)[0]), "r"((b)[1]))

#define CP_ASYNC16(dst, src)                                                  \
    asm volatile("cp.async.cg.shared.global [%0], [%1], 16;"                  \
        :: "r"(dst), "l"(src))
#define CP_COMMIT   asm volatile("cp.async.commit_group;")
#define CP_WAIT0    asm volatile("cp.async.wait_group 0;")

__device__ __forceinline__ float ex2f(float x) {
    float r;
    asm("ex2.approx.f32 %0, %1;" : "=f"(r) : "f"(x));
    return r;
}

// packed fp16 exp2
__device__ __forceinline__ uint32_t h2ex2(uint32_t a) {
    uint32_t d;
    asm("ex2.approx.f16x2 %0, %1;" : "=r"(d) : "r"(a));
    return d;
}

__device__ __forceinline__ uint32_t hadd2(uint32_t a, uint32_t b) {
    uint32_t d;
    asm("add.f16x2 %0, %1, %2;" : "=r"(d) : "r"(a), "r"(b));
    return d;
}

__device__ __forceinline__ uint32_t f2h2(float a, float b) {
    __half2 h = __floats2half2_rn(a, b);
    return *reinterpret_cast<uint32_t*>(&h);
}

// ============================================================================
// converters
// ============================================================================
__global__ void convert_h4(const float4* __restrict__ src,
                           uint2* __restrict__ dst, int n4)
{
    int i = blockIdx.x * blockDim.x + threadIdx.x;
    if (i >= n4) return;
    float4 v = src[i];
    uint2 d;
    d.x = f2h2(v.x, v.y);
    d.y = f2h2(v.z, v.w);
    dst[i] = d;
}

__global__ void convert_weights4(const float4* __restrict__ w0,
                                 const float4* __restrict__ w1,
                                 const float4* __restrict__ w2,
                                 const float4* __restrict__ w3,
                                 uint2* __restrict__ W, int n4)
{
    int i = blockIdx.x * blockDim.x + threadIdx.x;
    if (i >= n4) return;
    int z = blockIdx.y;
    const float4* src = (z == 0) ? w0 : (z == 1) ? w1 : (z == 2) ? w2 : w3;
    float4 v = src[i];
    uint2 d;
    d.x = f2h2(v.x, v.y);
    d.y = f2h2(v.z, v.w);
    W[(size_t)z * n4 + i] = d;
}

// ============================================================================
// fp16 GEMM: C = A @ W^T + bias. 128x128 tile, BK=64, 8 warps,
// cp.async double buffer (single barrier per iter), fp32 accum.
// mode 0: fp32 out (O-proj)
// mode 1: RoPE(acc+bias)*QSCALE -> fp16 (Q)
// mode 2: RoPE(acc+bias)        -> fp16 (K)
// mode 3: (acc+bias)            -> fp16 (V)
// ============================================================================
#define GSTR    72                 // smem row stride (halves): 64 data + 8 pad
#define G_ARR   (128 * GSTR)
#define G_STAGE (2 * G_ARR)
#define GEMM_SMEM (2 * G_STAGE * 2)   // 73728 bytes

__device__ __forceinline__ void gemm_prefetch(
    __half* st, const __half* __restrict__ A, const __half* __restrict__ W,
    int rowBase, int colBase, int kt, int tid)
{
#pragma unroll
    for (int p = 0; p < 4; p++) {
        int id = tid + p * 256;        // 0..1023
        int r  = id >> 3;              // 0..127
        int q  = (id & 7) * 8;         // 0..56 halves
        int so = r * GSTR + q;
        CP_ASYNC16(s_u32(st + so),
                   A + (size_t)(rowBase + r) * D_MODEL + kt + q);
        CP_ASYNC16(s_u32(st + G_ARR + so),
                   W + (size_t)(colBase + r) * D_MODEL + kt + q);
    }
}

__device__ __forceinline__ void gemm_body(
    const __half* __restrict__ A, const __half* __restrict__ W,
    const float* __restrict__ bias, float* __restrict__ C,
    __half* __restrict__ D, int mode, __half* sm)
{
    const int tid  = threadIdx.x;
    const int lane = tid & 31;
    const int wrp  = tid >> 5;
    const int g    = lane >> 2;
    const int t    = lane & 3;
    const int wm   = (wrp & 1) * 64;
    const int wn   = (wrp >> 1) * 32;
    const int rowBase = blockIdx.y * 128;
    const int colBase = blockIdx.x * 128;

    const int arow = (lane & 15);
    const int akoA = ((lane >> 4) << 3);
    const int brow = ((lane >> 4) << 3) + (lane & 7);
    const int bkoB = ((lane >> 3) & 1) * 8;

    float c[4][4][4];
#pragma unroll
    for (int i = 0; i < 4; i++)
#pragma unroll
        for (int j = 0; j < 4; j++)
#pragma unroll
            for (int e = 0; e < 4; e++) c[i][j][e] = 0.0f;

    gemm_prefetch(sm, A, W, rowBase, colBase, 0, tid);
    CP_COMMIT;

    const int NK = D_MODEL / 64;   // 16
    for (int it = 0; it < NK; it++) {
        CP_WAIT0;
        __syncthreads();
        if (it + 1 < NK) {
            gemm_prefetch(sm + ((it + 1) & 1) * G_STAGE, A, W,
                          rowBase, colBase, (it + 1) * 64, tid);
            CP_COMMIT;
        }

        __half* st = sm + (it & 1) * G_STAGE;
        __half* sA = st;
        __half* sW = st + G_ARR;

#pragma unroll
        for (int kk = 0; kk < 4; kk++) {
            uint32_t ar[4][4], bb[4][2];
#pragma unroll
            for (int i = 0; i < 4; i++) {
                uint32_t a = s_u32(&sA[(wm + 16 * i + arow) * GSTR + kk * 16 + akoA]);
                LDSM4(ar[i][0], ar[i][1], ar[i][2], ar[i][3], a);
            }
#pragma unroll
            for (int jj = 0; jj < 2; jj++) {
                uint32_t a = s_u32(&sW[(wn + 16 * jj + brow) * GSTR + kk * 16 + bkoB]);
                LDSM4(bb[2*jj][0], bb[2*jj][1], bb[2*jj+1][0], bb[2*jj+1][1], a);
            }
#pragma unroll
            for (int i = 0; i < 4; i++)
#pragma unroll
                for (int j = 0; j < 4; j++) MMA_FP16(c[i][j], ar[i], bb[j]);
        }
    }

    // ---- fused epilogue ----
#pragma unroll
    for (int i = 0; i < 4; i++) {
        int row = rowBase + wm + i * 16 + g;
        int s0  = row & (SEQ - 1);
        int s1  = (row + 8) & (SEQ - 1);
#pragma unroll
        for (int j = 0; j < 4; j++) {
            int col = colBase + wn + j * 8 + 2 * t;
            float b0 = bias[col], b1 = bias[col + 1];
            float x0 = c[i][j][0] + b0, x1 = c[i][j][1] + b1;
            float y0 = c[i][j][2] + b0, y1 = c[i][j][3] + b1;
            size_t i0 = (size_t)row * D_MODEL + col;
            size_t i1 = i0 + (size_t)8 * D_MODEL;
            if (mode == 0) {
                *reinterpret_cast<float2*>(&C[i0]) = make_float2(x0, x1);
                *reinterpret_cast<float2*>(&C[i1]) = make_float2(y0, y1);
            } else if (mode == 3) {
                *(uint32_t*)&D[i0] = f2h2(x0, x1);
                *(uint32_t*)&D[i1] = f2h2(y0, y1);
            } else {
                int p = (col & 63) >> 1;
                float freq = powf(10000.0f, -(float)p * (1.0f / 32.0f));
                float sn0, cs0, sn1, cs1;
                sincosf((float)s0 * freq, &sn0, &cs0);
                sincosf((float)s1 * freq, &sn1, &cs1);
                float r0a = x0 * cs0 - x1 * sn0;
                float r0b = x1 * cs0 + x0 * sn0;
                float r1a = y0 * cs1 - y1 * sn1;
                float r1b = y1 * cs1 + y0 * sn1;
                if (mode == 1) {
                    r0a *= QSCALE; r0b *= QSCALE;
                    r1a *= QSCALE; r1b *= QSCALE;
                }
                *(uint32_t*)&D[i0] = f2h2(r0a, r0b);
                *(uint32_t*)&D[i1] = f2h2(r1a, r1b);
            }
        }
    }
}

__global__ __launch_bounds__(256, 2) void gemm_qkv(
    const __half* __restrict__ A, const __half* __restrict__ WB,
    const float* __restrict__ b0, const float* __restrict__ b1, const float* __restrict__ b2,
    __half* __restrict__ Q16, __half* __restrict__ K16, __half* __restrict__ V16)
{
    extern __shared__ __half smg[];
    const int z = blockIdx.z;
    const size_t WSZ = (size_t)D_MODEL * D_MODEL;
    const float* bias = (z == 0) ? b0 : (z == 1) ? b1 : b2;
    __half* D = (z == 0) ? Q16 : (z == 1) ? K16 : V16;
    gemm_body(A, WB + z * WSZ, bias, (float*)0, D, z + 1, smg);
}

__global__ __launch_bounds__(256, 2) void gemm_out(
    const __half* __restrict__ A, const __half* __restrict__ W,
    const float* __restrict__ bias, float* __restrict__ C)
{
    extern __shared__ __half smg[];
    gemm_body(A, W, bias, C, (__half*)0, 0, smg);
}

// ============================================================================
// Tensor-core flash attention (all fp16):
// S = Q @ K^T, softmax via ex2.approx.f16x2, conditional rescale (skip when
// the running max is unchanged across the whole warp), O += P @ V.
// Single barrier per tile. occupancy 2.
// ============================================================================
#define ATS     72
#define A_ARR   (64 * ATS)
#define A_STAGE (2 * A_ARR)               // K, V
#define ATT_SMEM (2 * A_STAGE * 2)        // 36864 bytes

__device__ __forceinline__ void att_prefetch(
    __half* st, const __half* __restrict__ K16, const __half* __restrict__ V16,
    size_t gbase, int kv0, int tid)
{
    int r  = tid >> 2;                 // 0..63
    int cq = (tid & 3) * 16;           // 0,16,32,48
    int so = r * ATS + cq;
    size_t gk = gbase + (size_t)(kv0 + r) * D_MODEL + cq;
    CP_ASYNC16(s_u32(st + so),             K16 + gk);
    CP_ASYNC16(s_u32(st + so + 8),         K16 + gk + 8);
    CP_ASYNC16(s_u32(st + A_ARR + so),     V16 + gk);
    CP_ASYNC16(s_u32(st + A_ARR + so + 8), V16 + gk + 8);
}

__global__ __launch_bounds__(256, 2) void attention_mma(
    const __half* __restrict__ Q16, const __half* __restrict__ K16,
    const __half* __restrict__ V16, __half* __restrict__ O16)
{
    extern __shared__ __half sKV[];

    const int bh = blockIdx.y;
    const int b  = bh >> 4;
    const int h  = bh & 15;
    const int q0 = blockIdx.x * 128;
    const int tid  = threadIdx.x;
    const int lane = tid & 31;
    const int wrp  = tid >> 5;
    const int g    = lane >> 2;
    const int t    = lane & 3;

    const size_t gbase = (size_t)b * SEQ * D_MODEL + (size_t)h * DKH;

    att_prefetch(sKV, K16, V16, gbase, 0, tid);
    CP_COMMIT;

    // ---- Q fragments directly from gmem (A-frag layout) ----
    uint32_t qf[4][4];
    {
        const int r0 = q0 + 16 * wrp + g;
        size_t ro0 = gbase + (size_t)r0 * D_MODEL;
        size_t ro8 = ro0 + (size_t)8 * D_MODEL;
#pragma unroll
        for (int kc = 0; kc < 4; kc++) {
            int cw = kc * 16 + 2 * t;
            qf[kc][0] = *(const uint32_t*)&Q16[ro0 + cw];
            qf[kc][1] = *(const uint32_t*)&Q16[ro8 + cw];
            qf[kc][2] = *(const uint32_t*)&Q16[ro0 + cw + 8];
            qf[kc][3] = *(const uint32_t*)&Q16[ro8 + cw + 8];
        }
    }

    float m[2] = {-INFINITY, -INFINITY};
    float l[2] = {0.0f, 0.0f};
    float o[8][4];
#pragma unroll
    for (int j = 0; j < 8; j++)
#pragma unroll
        for (int e = 0; e < 4; e++) o[j][e] = 0.0f;

    const int brow  = ((lane >> 4) << 3) + (lane & 7);
    const int bko   = ((lane >> 3) & 1) * 8;
    const int vrow  = (lane & 7) + ((lane >> 3) & 1) * 8;
    const int vcol  = ((lane >> 4) << 3);

    const int NT = SEQ / 64;
    for (int it = 0; it < NT; it++) {
        CP_WAIT0;
        __syncthreads();
        if (it + 1 < NT) {
            att_prefetch(sKV + ((it + 1) & 1) * A_STAGE, K16, V16,
                         gbase, (it + 1) * 64, tid);
            CP_COMMIT;
        }

        __half* st = sKV + (it & 1) * A_STAGE;
        __half* sK = st;
        __half* sV = st + A_ARR;

        // ---- S = Q @ K^T ----
        float s[8][4];
#pragma unroll
        for (int j = 0; j < 8; j++)
#pragma unroll
            for (int e = 0; e < 4; e++) s[j][e] = 0.0f;

#pragma unroll
        for (int kc = 0; kc < 4; kc++) {
            uint32_t kb[8][2];
#pragma unroll
            for (int jj = 0; jj < 4; jj++) {
                uint32_t a = s_u32(&sK[(16 * jj + brow) * ATS + kc * 16 + bko]);
                LDSM4(kb[2*jj][0], kb[2*jj][1], kb[2*jj+1][0], kb[2*jj+1][1], a);
            }
#pragma unroll
            for (int j = 0; j < 8; j++) MMA_FP16(s[j], qf[kc], kb[j]);
        }

        // ---- row max (tree + quad shuffles) ----
        float mn[2];
#pragma unroll
        for (int e = 0; e < 2; e++) {
            float a0 = fmaxf(s[0][2*e], s[0][2*e+1]);
            float a1 = fmaxf(s[1][2*e], s[1][2*e+1]);
            float a2 = fmaxf(s[2][2*e], s[2][2*e+1]);
            float a3 = fmaxf(s[3][2*e], s[3][2*e+1]);
            float a4 = fmaxf(s[4][2*e], s[4][2*e+1]);
            float a5 = fmaxf(s[5][2*e], s[5][2*e+1]);
            float a6 = fmaxf(s[6][2*e], s[6][2*e+1]);
            float a7 = fmaxf(s[7][2*e], s[7][2*e+1]);
            a0 = fmaxf(a0, a1); a2 = fmaxf(a2, a3);
            a4 = fmaxf(a4, a5); a6 = fmaxf(a6, a7);
            float mloc = fmaxf(fmaxf(a0, a2), fmaxf(a4, a6));
            mloc = fmaxf(mloc, __shfl_xor_sync(0xffffffffu, mloc, 1));
            mloc = fmaxf(mloc, __shfl_xor_sync(0xffffffffu, mloc, 2));
            mn[e] = fmaxf(m[e], mloc);
        }

        // ---- conditional rescale: skip when max unchanged warp-wide ----
        bool upd = (mn[0] > m[0]) || (mn[1] > m[1]);
        if (__any_sync(0xffffffffu, upd)) {
            float a0 = ex2f(m[0] - mn[0]);
            float a1 = ex2f(m[1] - mn[1]);
            m[0] = mn[0]; m[1] = mn[1];
            l[0] *= a0; l[1] *= a1;
#pragma unroll
            for (int j = 0; j < 8; j++) {
                o[j][0] *= a0; o[j][1] *= a0;
                o[j][2] *= a1; o[j][3] *= a1;
            }
        }

        // ---- P fragments born as fp16x2 ----
        uint32_t ph[8][2];
#pragma unroll
        for (int j = 0; j < 8; j++) {
            ph[j][0] = h2ex2(f2h2(s[j][0] - m[0], s[j][1] - m[0]));
            ph[j][1] = h2ex2(f2h2(s[j][2] - m[1], s[j][3] - m[1]));
        }

        // ---- l sums via HADD2 tree ----
#pragma unroll
        for (int e = 0; e < 2; e++) {
            uint32_t t01 = hadd2(ph[0][e], ph[1][e]);
            uint32_t t23 = hadd2(ph[2][e], ph[3][e]);
            uint32_t t45 = hadd2(ph[4][e], ph[5][e]);
            uint32_t t67 = hadd2(ph[6][e], ph[7][e]);
            uint32_t t03 = hadd2(t01, t23);
            uint32_t t47 = hadd2(t45, t67);
            uint32_t tt  = hadd2(t03, t47);
            __half2 hh = *reinterpret_cast<__half2*>(&tt);
            float2 ff = __half22float2(hh);
            l[e] += ff.x + ff.y;
        }

        // ---- O += P @ V ----
#pragma unroll
        for (int kc = 0; kc < 4; kc++) {
            uint32_t pa[4] = {ph[2*kc][0], ph[2*kc][1], ph[2*kc+1][0], ph[2*kc+1][1]};
            uint32_t vb[8][2];
#pragma unroll
            for (int jj = 0; jj < 4; jj++) {
                uint32_t a = s_u32(&sV[(kc * 16 + vrow) * ATS + 16 * jj + vcol]);
                LDSM4T(vb[2*jj][0], vb[2*jj][1], vb[2*jj+1][0], vb[2*jj+1][1], a);
            }
#pragma unroll
            for (int j = 0; j < 8; j++) MMA_FP16(o[j], pa, vb[j]);
        }
    }

    // ---- epilogue: quad-reduce l, normalize, write fp16 O ----
    l[0] += __shfl_xor_sync(0xffffffffu, l[0], 1);
    l[0] += __shfl_xor_sync(0xffffffffu, l[0], 2);
    l[1] += __shfl_xor_sync(0xffffffffu, l[1], 1);
    l[1] += __shfl_xor_sync(0xffffffffu, l[1], 2);

    const int r0 = q0 + 16 * wrp + g;
    const float inv0 = 1.0f / l[0];
    const float inv1 = 1.0f / l[1];
#pragma unroll
    for (int j = 0; j < 8; j++) {
        int col = h * DKH + 8 * j + 2 * t;
        size_t i0 = (size_t)b * SEQ * D_MODEL + (size_t)r0 * D_MODEL + col;
        size_t i1 = i0 + (size_t)8 * D_MODEL;
        *(uint32_t*)&O16[i0] = f2h2(o[j][0] * inv0, o[j][1] * inv0);
        *(uint32_t*)&O16[i1] = f2h2(o[j][2] * inv1, o[j][3] * inv1);
    }
}

// ============================================================================
// Launch
// ============================================================================
extern "C" void kernel_launch(void* const* d_in, const int* in_sizes, int n_in,
                              void* d_out, int out_size)
{
    (void)in_sizes; (void)n_in; (void)out_size;
    const float* x  = (const float*)d_in[0];
    const float* wq = (const float*)d_in[1];
    const float* bq = (const float*)d_in[2];
    const float* wk = (const float*)d_in[3];
    const float* bk = (const float*)d_in[4];
    const float* wv = (const float*)d_in[5];
    const float* bv = (const float*)d_in[6];
    const float* wo = (const float*)d_in[7];
    const float* bo = (const float*)d_in[8];
    float* out = (float*)d_out;

    __half *X16, *O16, *Q16, *K16, *V16, *W16;
    cudaGetSymbolAddress((void**)&X16, g_X16);
    cudaGetSymbolAddress((void**)&O16, g_O16);
    cudaGetSymbolAddress((void**)&Q16, g_Q16);
    cudaGetSymbolAddress((void**)&K16, g_K16);
    cudaGetSymbolAddress((void**)&V16, g_V16);
    cudaGetSymbolAddress((void**)&W16, g_W16);

    cudaFuncSetAttribute(attention_mma,
                         cudaFuncAttributeMaxDynamicSharedMemorySize, ATT_SMEM);
    cudaFuncSetAttribute(gemm_qkv,
                         cudaFuncAttributeMaxDynamicSharedMemorySize, GEMM_SMEM);
    cudaFuncSetAttribute(gemm_out,
                         cudaFuncAttributeMaxDynamicSharedMemorySize, GEMM_SMEM);

    const size_t WSZ = (size_t)D_MODEL * D_MODEL;

    int n4x = (MROWS * D_MODEL) / 4;
    int n4w = (int)(WSZ / 4);
    convert_h4<<<(n4x + 255) / 256, 256>>>((const float4*)x, (uint2*)X16, n4x);
    dim3 wgrid((n4w + 255) / 256, 4);
    convert_weights4<<<wgrid, 256>>>((const float4*)wq, (const float4*)wk,
                                     (const float4*)wv, (const float4*)wo,
                                     (uint2*)W16, n4w);

    // fused QKV projections
    dim3 qkvgrid(D_MODEL / 128, MROWS / 128, 3);
    gemm_qkv<<<qkvgrid, 256, GEMM_SMEM>>>(X16, W16, bq, bk, bv, Q16, K16, V16);

    // tensor-core flash attention
    dim3 agrid(SEQ / 128, BATCH * NUM_HEADS);
    attention_mma<<<agrid, 256, ATT_SMEM>>>(Q16, K16, V16, O16);

    // output projection
    dim3 ogrid(D_MODEL / 128, MROWS / 128);
    gemm_out<<<ogrid, 256, GEMM_SMEM>>>(O16, W16 + 3 * WSZ, bo, out);
}